// round 7
// baseline (speedup 1.0000x reference)
#include <cuda_runtime.h>
#include <math.h>

#define T_ 128
#define N_ 256
#define L_ 256
#define H_ 256
#define COND_ 64
#define ROWS_ (T_ * N_)   // 32768
#define OUTW_ 770         // 1 + 1 + H + L + L

typedef unsigned long long u64;
typedef unsigned u32;

// ---------------- scratch (single __device__ symbol, no allocations) -------
#define XIN_OFF 0L
#define XA_OFF  (XIN_OFF + (long)ROWS_ * 320)
#define XB_OFF  (XA_OFF  + (long)ROWS_ * 256)
#define GI_OFF  (XB_OFF  + (long)ROWS_ * 256)
#define KB_OFF  (GI_OFF  + (long)ROWS_ * 768)
#define WB_OFF  (KB_OFF  + (long)ROWS_ * 256)
#define CC_OFF  (WB_OFF  + (long)ROWS_ * 256)
#define SCRATCH_FLOATS (CC_OFF + (long)ROWS_)

__device__ float g_scratch[SCRATCH_FLOATS];
__device__ unsigned g_bar2[16 * 32];   // per-nt barriers: arrive [g*32], epoch [(8+g)*32]

// ---------------- packed fp32x2 helpers (GRU) --------------------------------
#define FMA2(d, a, b) \
    asm("fma.rn.f32x2 %0, %1, %2, %0;" : "+l"(d) : "l"(a), "l"(b))
#define UNPACK2(lo, hi, v) \
    asm("mov.b64 {%0, %1}, %2;" : "=f"(lo), "=f"(hi) : "l"(v))

// ---------------- tf32 helpers ------------------------------------------------
__device__ __forceinline__ u32 cvt_tf32(float x) {
    u32 r;
    asm("cvt.rna.tf32.f32 %0, %1;" : "=r"(r) : "f"(x));
    return r;
}
__device__ __forceinline__ void mma_tf32(float* d, const u32* a, const u32* b) {
    asm volatile(
        "mma.sync.aligned.m16n8k8.row.col.f32.tf32.tf32.f32 "
        "{%0,%1,%2,%3}, {%4,%5,%6,%7}, {%8,%9}, {%0,%1,%2,%3};"
        : "+f"(d[0]), "+f"(d[1]), "+f"(d[2]), "+f"(d[3])
        : "r"(a[0]), "r"(a[1]), "r"(a[2]), "r"(a[3]), "r"(b[0]), "r"(b[1]));
}

// ---------------------------------------------------------------------------
__global__ __launch_bounds__(256) void t0_kernel(
    const float* __restrict__ p0, const float* __restrict__ M,
    const float* __restrict__ C, float* __restrict__ XIN, float* __restrict__ CC)
{
    int n = blockIdx.x;
    int tid = threadIdx.x;
    float v = p0[(long)n * L_ + tid];
    int any = __syncthreads_or(v != 0.f);
    if (!any) {
        XIN[(long)n * 320 + 64 + tid] = M[(long)n * L_ * H_ + tid];
        if (tid == 0) CC[n] = C[(long)n * L_];
        return;
    }
    __shared__ float red[256];
    __shared__ float ps[256];
    ps[tid] = v;
    __syncthreads();
    float acc = 0.f;
    const float* Mn = M + (long)n * L_ * H_;
    for (int l = 0; l < L_; l++)
        acc = fmaf(ps[l], Mn[(long)l * H_ + tid], acc);
    XIN[(long)n * 320 + 64 + tid] = acc;
    red[tid] = ps[tid] * C[(long)n * L_ + tid];
    __syncthreads();
    for (int s = 128; s > 0; s >>= 1) {
        if (tid < s) red[tid] += red[tid + s];
        __syncthreads();
    }
    if (tid == 0) CC[n] = red[0];
}

// ---------------------------------------------------------------------------
__global__ __launch_bounds__(256) void gather_kernel(
    const float* __restrict__ cond, const float* __restrict__ M,
    const float* __restrict__ C, const int* __restrict__ actions,
    float* __restrict__ XIN, float* __restrict__ CC)
{
    int r = threadIdx.x >> 5, lane = threadIdx.x & 31;
    long idx = (long)blockIdx.x * 8 + r;    // t*N + n
    int t = (int)(idx / N_), n = (int)(idx % N_);
    float4* dst = (float4*)(XIN + idx * 320);
    const float4* csrc = (const float4*)(cond + idx * COND_);
    if (lane < 16) dst[lane] = csrc[lane];
    if (t > 0) {
        int a = actions[idx - N_];
        const float4* msrc = (const float4*)(M + ((long)n * L_ + a) * H_);
#pragma unroll
        for (int i = 0; i < 2; i++) dst[16 + lane + i * 32] = msrc[lane + i * 32];
        if (lane == 0) CC[idx] = C[(long)n * L_ + a];
    }
}

// ---------------------------------------------------------------------------
// tf32 tensor-core GEMM with 3xTF32 split (fp32-class accuracy).
// Tile 128x128, BK=16, 8 warps (2m x 4n), each warp 64x32 via m16n8k8.
// Frag-ready smem: one LDS.128 per A-frag, one LDS.64 per B-frag.
// smem floats per buf: A 2 parts x 2048, B 2 parts x 2048 => 8192; x2 buf.
#define GEMM_SMEM (16384 * 4)

template <bool TRANSB, bool RELU>
__global__ __launch_bounds__(256) void gemm_tf32(
    const float* __restrict__ A, const float* __restrict__ B,
    const float* __restrict__ bias, float* __restrict__ C,
    int Mdim, int Ndim, int K, int lda, int ldb, int ldc,
    long batchA, long batchB, long batchC)
{
    extern __shared__ float sm[];
    long bz = blockIdx.z;
    A += bz * batchA; B += bz * batchB; C += bz * batchC;
    int m0 = blockIdx.x * 128, n0 = blockIdx.y * 128;
    int tid = threadIdx.x;
    int wid = tid >> 5, lane = tid & 31;
    int warp_m = wid >> 2, warp_n = wid & 3;
    int gid = lane >> 2, tg = lane & 3;

    // staging coordinates (2 float4 per thread per operand)
    int sa_m[2], sa_q[2];
    int sb_x[2], sb_y[2];
#pragma unroll
    for (int i = 0; i < 2; i++) {
        int idx = tid + i * 256;      // 0..511
        sa_m[i] = idx >> 2; sa_q[i] = idx & 3;
        if (TRANSB) { sb_x[i] = idx >> 2; sb_y[i] = idx & 3; }   // (n, q)
        else        { sb_x[i] = idx >> 5; sb_y[i] = idx & 31; }  // (k, p)
    }

    float acc[4][4][4];
#pragma unroll
    for (int i = 0; i < 4; i++)
#pragma unroll
        for (int j = 0; j < 4; j++)
#pragma unroll
            for (int v = 0; v < 4; v++) acc[i][j][v] = 0.f;

    // stage one K-tile into buffer `buf`
    auto stage = [&](int buf, int k0) {
        float* AF = sm + buf * 8192;          // 2 parts x 2048
        float* BF = sm + buf * 8192 + 4096;   // 2 parts x 2048
#pragma unroll
        for (int i = 0; i < 2; i++) {
            int m = sa_m[i], q = sa_q[i];
            float4 v4 = *(const float4*)&A[(long)(m0 + m) * lda + k0 + q * 4];
            int mi = m >> 4, r = m & 15;
            int g = r & 7, hi8 = r >> 3;
            int ks = q >> 1, khi = q & 1;
            int vv = hi8 + 2 * khi;
            int base = (mi * 2 + ks) * 128 + g * 16 + vv;
            float xs[4] = {v4.x, v4.y, v4.z, v4.w};
#pragma unroll
            for (int e = 0; e < 4; e++) {
                u32 hi = cvt_tf32(xs[e]);
                u32 lo = cvt_tf32(xs[e] - __uint_as_float(hi));
                AF[base + e * 4] = __uint_as_float(hi);
                AF[2048 + base + e * 4] = __uint_as_float(lo);
            }
        }
#pragma unroll
        for (int i = 0; i < 2; i++) {
            float4 v4;
            int base[4];
            if (TRANSB) {
                int n = sb_x[i], q = sb_y[i];
                v4 = *(const float4*)&B[(long)(n0 + n) * ldb + k0 + q * 4];
                int ni = n >> 3, g = n & 7;
                int ks = q >> 1, vv = q & 1;
                int b0 = (ni * 2 + ks) * 64 + g * 8 + vv;
#pragma unroll
                for (int e = 0; e < 4; e++) base[e] = b0 + e * 2;
            } else {
                int k = sb_x[i], p = sb_y[i];
                v4 = *(const float4*)&B[(long)(k0 + k) * ldb + n0 + p * 4];
                int ks = k >> 3, tgk = k & 3, vv = (k >> 2) & 1;
                int ni = p >> 1, gb = (p & 1) * 4;
                int b0 = (ni * 2 + ks) * 64 + gb * 8 + tgk * 2 + vv;
#pragma unroll
                for (int e = 0; e < 4; e++) base[e] = b0 + e * 8;
            }
            float xs[4] = {v4.x, v4.y, v4.z, v4.w};
#pragma unroll
            for (int e = 0; e < 4; e++) {
                u32 hi = cvt_tf32(xs[e]);
                u32 lo = cvt_tf32(xs[e] - __uint_as_float(hi));
                BF[base[e]] = __uint_as_float(hi);
                BF[2048 + base[e]] = __uint_as_float(lo);
            }
        }
    };

    stage(0, 0);
    __syncthreads();

    int nk = K / 16;
    for (int kt = 0; kt < nk; kt++) {
        int buf = kt & 1;
        const float* AF = sm + buf * 8192;
        const float* BF = sm + buf * 8192 + 4096;
#pragma unroll
        for (int ks = 0; ks < 2; ks++) {
            uint4 ahi[4], alo[4];
            uint2 bhi[4], blo[4];
#pragma unroll
            for (int i = 0; i < 4; i++) {
                int mi = warp_m * 4 + i;
                int off = (mi * 2 + ks) * 128 + lane * 4;
                ahi[i] = *(const uint4*)&AF[off];
                alo[i] = *(const uint4*)&AF[2048 + off];
            }
#pragma unroll
            for (int j = 0; j < 4; j++) {
                int ni = warp_n * 4 + j;
                int off = (ni * 2 + ks) * 64 + lane * 2;
                bhi[j] = *(const uint2*)&BF[off];
                blo[j] = *(const uint2*)&BF[2048 + off];
            }
#pragma unroll
            for (int i = 0; i < 4; i++)
#pragma unroll
                for (int j = 0; j < 4; j++) {
                    mma_tf32(acc[i][j], (const u32*)&ahi[i], (const u32*)&bhi[j]);
                    mma_tf32(acc[i][j], (const u32*)&ahi[i], (const u32*)&blo[j]);
                    mma_tf32(acc[i][j], (const u32*)&alo[i], (const u32*)&bhi[j]);
                }
        }
        if (kt + 1 < nk) {
            stage(buf ^ 1, (kt + 1) * 16);
        }
        __syncthreads();
    }

    // epilogue
#pragma unroll
    for (int i = 0; i < 4; i++) {
        int mbase = m0 + warp_m * 64 + i * 16;
#pragma unroll
        for (int j = 0; j < 4; j++) {
            int nbase = n0 + warp_n * 32 + j * 8;
            int col = nbase + tg * 2;
            float b0 = 0.f, b1 = 0.f;
            if (bias) { b0 = bias[col]; b1 = bias[col + 1]; }
            float v0 = acc[i][j][0] + b0, v1 = acc[i][j][1] + b1;
            float v2 = acc[i][j][2] + b0, v3 = acc[i][j][3] + b1;
            if (RELU) {
                v0 = fmaxf(v0, 0.f); v1 = fmaxf(v1, 0.f);
                v2 = fmaxf(v2, 0.f); v3 = fmaxf(v3, 0.f);
            }
            *(float2*)&C[(long)(mbase + gid) * ldc + col] = make_float2(v0, v1);
            *(float2*)&C[(long)(mbase + gid + 8) * ldc + col] = make_float2(v2, v3);
        }
    }
}

// ---------------------------------------------------------------------------
// persistent GRU (R5 version: k-split x2, per-nt group barrier) + __expf
#define GRU_BLOCKS 128
#define HSTR 260

__device__ __forceinline__ float sigmf(float x) { return 1.f / (1.f + __expf(-x)); }
__device__ __forceinline__ float tanhfast(float x) { return 2.f / (1.f + __expf(-2.f * x)) - 1.f; }

__global__ __launch_bounds__(256) void gru_persistent(
    const float* __restrict__ GI, const float* __restrict__ h0,
    const float* __restrict__ W_hh, const float* __restrict__ b_hh,
    float* __restrict__ HD)
{
    extern __shared__ float smem[];
    float4* w4 = (float4*)smem;                       // [64 chunks][48 rows]
    float* hs = smem + 4 * 64 * 48;                   // [32][HSTR]
    u64* redm = (u64*)(hs + 32 * HSTR);               // [128][12]

    int tid = threadIdx.x;
    int jt = blockIdx.x & 15, nt = blockIdx.x >> 4;
    int j0 = jt * 16, n0 = nt * 32;
    int kg = tid >> 7;
    int lt = tid & 127;
    int jj = lt & 15, nn8 = lt >> 4;
    int j = j0 + jj;

    unsigned* arr = &g_bar2[nt * 32];
    unsigned* ep  = &g_bar2[(8 + nt) * 32];

    for (int e = tid; e < 48 * 64; e += 256) {
        int c = e & 63, r = e >> 6;
        int g = r >> 4, jr = r & 15;
        w4[c * 48 + r] = *(const float4*)&W_hh[(long)(g * 256 + j0 + jr) * 256 + c * 4];
    }
    float bhr = b_hh[j], bhz = b_hh[256 + j], bhn = b_hh[512 + j];

    float gi_r[4], gi_z[4], gi_n[4];
    if (kg == 0) {
#pragma unroll
        for (int i = 0; i < 4; i++) {
            const float* g = GI + ((long)(n0 + nn8 + 8 * i)) * 768;
            gi_r[i] = g[j]; gi_z[i] = g[256 + j]; gi_n[i] = g[512 + j];
        }
    }
    int cbase = kg * 32;

    for (int t = 0; t < T_; t++) {
        const float* hin = (t == 0) ? h0 : (HD + (long)(t - 1) * N_ * H_);
        float* hout = HD + (long)t * N_ * H_;

        {
            int n = tid >> 3, f = tid & 7;
            const float4* src = (const float4*)(hin + (long)(n0 + n) * H_);
            float4* dst = (float4*)(hs + n * HSTR);
#pragma unroll
            for (int i = 0; i < 8; i++) dst[f + 8 * i] = src[f + 8 * i];
        }
        __syncthreads();

        u64 acc[4][3];
#pragma unroll
        for (int i = 0; i < 4; i++)
#pragma unroll
            for (int g = 0; g < 3; g++) acc[i][g] = 0ull;

#pragma unroll 8
        for (int c = cbase; c < cbase + 32; c++) {
            const ulonglong2* wrow = (const ulonglong2*)(w4 + c * 48);
            ulonglong2 w0 = wrow[jj];
            ulonglong2 w1 = wrow[16 + jj];
            ulonglong2 w2 = wrow[32 + jj];
#pragma unroll
            for (int i = 0; i < 4; i++) {
                ulonglong2 hv = *(const ulonglong2*)(hs + (nn8 + 8 * i) * HSTR + c * 4);
                FMA2(acc[i][0], hv.x, w0.x); FMA2(acc[i][0], hv.y, w0.y);
                FMA2(acc[i][1], hv.x, w1.x); FMA2(acc[i][1], hv.y, w1.y);
                FMA2(acc[i][2], hv.x, w2.x); FMA2(acc[i][2], hv.y, w2.y);
            }
        }

        if (kg == 1) {
#pragma unroll
            for (int i = 0; i < 4; i++)
#pragma unroll
                for (int g = 0; g < 3; g++) redm[lt * 12 + i * 3 + g] = acc[i][g];
        }
        __syncthreads();

        if (kg == 0) {
#pragma unroll
            for (int i = 0; i < 4; i++) {
                float lo, hi, s[3];
#pragma unroll
                for (int g = 0; g < 3; g++) {
                    UNPACK2(lo, hi, acc[i][g]);
                    s[g] = lo + hi;
                    UNPACK2(lo, hi, redm[lt * 12 + i * 3 + g]);
                    s[g] += lo + hi;
                }
                int nl = nn8 + 8 * i;
                float rg = sigmf(gi_r[i] + s[0] + bhr);
                float z  = sigmf(gi_z[i] + s[1] + bhz);
                float nv = tanhfast(gi_n[i] + rg * (s[2] + bhn));
                float hp = hs[nl * HSTR + j];
                float hn = (1.f - z) * nv + z * hp;
                hout[(long)(n0 + nl) * H_ + j] = hn;
            }
        }

        if (t < T_ - 1) {
            __syncthreads();
            if (tid == 0) {
                unsigned prev;
                asm volatile("atom.release.gpu.global.add.u32 %0, [%1], %2;"
                             : "=r"(prev) : "l"(arr), "r"(1u) : "memory");
                if (prev == (unsigned)((t + 1) * 16 - 1)) {
                    asm volatile("st.release.gpu.global.u32 [%0], %1;"
                                 :: "l"(ep), "r"((unsigned)(t + 1)) : "memory");
                }
            }
            if (kg == 0) {
#pragma unroll
                for (int i = 0; i < 4; i++) {
                    const float* g = GI + ((long)(t + 1) * N_ + n0 + nn8 + 8 * i) * 768;
                    gi_r[i] = g[j]; gi_z[i] = g[256 + j]; gi_n[i] = g[512 + j];
                }
            }
            if (tid == 0) {
                unsigned e;
                do {
                    asm volatile("ld.acquire.gpu.global.u32 %0, [%1];"
                                 : "=r"(e) : "l"(ep) : "memory");
                } while (e < (unsigned)(t + 1));
            }
            __syncthreads();
        }
    }
}

// ---------------------------------------------------------------------------
__global__ __launch_bounds__(256) void epilogue_kernel(
    const float* __restrict__ WB, const float* __restrict__ CC,
    const int* __restrict__ actions, const float* __restrict__ Wc,
    const float* __restrict__ bc, const float* __restrict__ HD,
    float* __restrict__ out)
{
    int wid = threadIdx.x >> 5, lane = threadIdx.x & 31;
    long idx = (long)blockIdx.x * 8 + wid;   // t*N + n
    int t = (int)(idx / N_), n = (int)(idx % N_);
    float cc = CC[idx];
    long base = idx * OUTW_;

    const float4* hrow = (const float4*)(HD + idx * 256);
    const float4* wc = (const float4*)Wc;
    float4 h0v = hrow[lane * 2], h1v = hrow[lane * 2 + 1];
    float4 c0 = wc[lane * 2], c1 = wc[lane * 2 + 1];
    float2* hdst = (float2*)(out + base + 2 + lane * 8);
    hdst[0] = make_float2(h0v.x, h0v.y);
    hdst[1] = make_float2(h0v.z, h0v.w);
    hdst[2] = make_float2(h1v.x, h1v.y);
    hdst[3] = make_float2(h1v.z, h1v.w);
    float d = h0v.x * c0.x + h0v.y * c0.y + h0v.z * c0.z + h0v.w * c0.w
            + h1v.x * c1.x + h1v.y * c1.y + h1v.z * c1.z + h1v.w * c1.w;
#pragma unroll
    for (int o = 16; o; o >>= 1) d += __shfl_xor_sync(~0u, d, o);

    const float4* wrow = (const float4*)(WB + ((long)n * T_ + t) * L_);
    float4 w0 = wrow[lane * 2], w1 = wrow[lane * 2 + 1];
    float wv[8] = {w0.x * cc, w0.y * cc, w0.z * cc, w0.w * cc,
                   w1.x * cc, w1.y * cc, w1.z * cc, w1.w * cc};
    float mx = wv[0];
#pragma unroll
    for (int i = 1; i < 8; i++) mx = fmaxf(mx, wv[i]);
#pragma unroll
    for (int o = 16; o; o >>= 1) mx = fmaxf(mx, __shfl_xor_sync(~0u, mx, o));
    float e[8], s = 0.f;
#pragma unroll
    for (int i = 0; i < 8; i++) { e[i] = expf(wv[i] - mx); s += e[i]; }
#pragma unroll
    for (int o = 16; o; o >>= 1) s += __shfl_xor_sync(~0u, s, o);
    float inv = 1.f / s;

    int a = actions[idx];
    float2* pdst = (float2*)(out + base + 258 + lane * 8);
    float2* odst = (float2*)(out + base + 514 + lane * 8);
#pragma unroll
    for (int i = 0; i < 4; i++) {
        pdst[i] = make_float2(e[2 * i] * inv, e[2 * i + 1] * inv);
        int l0 = lane * 8 + 2 * i;
        odst[i] = make_float2(l0 == a ? 1.f : 0.f, l0 + 1 == a ? 1.f : 0.f);
    }
    if (lane == 0) {
        out[base + 0] = (float)a;
        out[base + 1] = d + bc[0];
    }
}

// ---------------------------------------------------------------------------
extern "C" void kernel_launch(void* const* d_in, const int* in_sizes, int n_in,
                              void* d_out, int out_size)
{
    const float* cond = (const float*)d_in[0];
    const float* M    = (const float*)d_in[1];
    const float* Km   = (const float*)d_in[2];
    const float* Cm   = (const float*)d_in[3];
    const float* h0   = (const float*)d_in[4];
    const float* p0   = (const float*)d_in[5];
    const float* W0   = (const float*)d_in[6];
    const float* b0   = (const float*)d_in[7];
    const float* W1   = (const float*)d_in[8];
    const float* b1   = (const float*)d_in[9];
    const float* W2   = (const float*)d_in[10];
    const float* b2   = (const float*)d_in[11];
    const float* W_ih = (const float*)d_in[12];
    const float* W_hh = (const float*)d_in[13];
    const float* b_ih = (const float*)d_in[14];
    const float* b_hh = (const float*)d_in[15];
    const float* Wa   = (const float*)d_in[16];
    const float* ba   = (const float*)d_in[17];
    const float* Wc   = (const float*)d_in[18];
    const float* bc   = (const float*)d_in[19];
    const int* actions = (const int*)d_in[20];
    float* out = (float*)d_out;

    float* base = nullptr;
    cudaGetSymbolAddress((void**)&base, g_scratch);
    float* XIN = base + XIN_OFF;
    float* XA  = base + XA_OFF;
    float* XB  = base + XB_OFF;
    float* GI  = base + GI_OFF;
    float* KB  = base + KB_OFF;
    float* WB  = base + WB_OFF;
    float* CC  = base + CC_OFF;
    float* HD  = base + XIN_OFF;   // reuse XIN region after phase A

    void* bar_addr = nullptr;
    cudaGetSymbolAddress(&bar_addr, g_bar2);

    const int GRU_SMEM = 4 * 64 * 48 * 4 + 32 * HSTR * 4 + 128 * 12 * 8; // 94720
    cudaFuncSetAttribute(gru_persistent,
                         cudaFuncAttributeMaxDynamicSharedMemorySize, GRU_SMEM);
    cudaFuncSetAttribute(gemm_tf32<false, true>,
                         cudaFuncAttributeMaxDynamicSharedMemorySize, GEMM_SMEM);
    cudaFuncSetAttribute(gemm_tf32<false, false>,
                         cudaFuncAttributeMaxDynamicSharedMemorySize, GEMM_SMEM);
    cudaFuncSetAttribute(gemm_tf32<true, false>,
                         cudaFuncAttributeMaxDynamicSharedMemorySize, GEMM_SMEM);

    // phase A: inputs -> gi (fully parallel over T*N)
    t0_kernel<<<N_, 256>>>(p0, M, Cm, XIN, CC);
    gather_kernel<<<ROWS_ / 8, 256>>>(cond, M, Cm, actions, XIN, CC);
    gemm_tf32<false, true><<<dim3(ROWS_ / 128, 2, 1), 256, GEMM_SMEM>>>(
        XIN, W0, b0, XA, ROWS_, 256, 320, 320, 256, 256, 0, 0, 0);
    gemm_tf32<false, true><<<dim3(ROWS_ / 128, 2, 1), 256, GEMM_SMEM>>>(
        XA, W1, b1, XB, ROWS_, 256, 256, 256, 256, 256, 0, 0, 0);
    gemm_tf32<false, true><<<dim3(ROWS_ / 128, 2, 1), 256, GEMM_SMEM>>>(
        XB, W2, b2, XA, ROWS_, 256, 256, 256, 256, 256, 0, 0, 0);
    gemm_tf32<true, false><<<dim3(ROWS_ / 128, 6, 1), 256, GEMM_SMEM>>>(
        XA, W_ih, b_ih, GI, ROWS_, 768, 256, 256, 256, 768, 0, 0, 0);

    // phase B: persistent GRU (per-nt 16-block barriers)
    cudaMemsetAsync(bar_addr, 0, 16 * 32 * sizeof(unsigned));
    gru_persistent<<<GRU_BLOCKS, 256, GRU_SMEM>>>(GI, h0, W_hh, b_hh, HD);

    // phase C: actor head
    gemm_tf32<false, false><<<dim3(ROWS_ / 128, 2, 1), 256, GEMM_SMEM>>>(
        HD, Wa, ba, KB, ROWS_, 256, 256, 256, 256, 256, 0, 0, 0);
    gemm_tf32<true, false><<<dim3(1, 2, N_), 256, GEMM_SMEM>>>(
        KB, Km, nullptr, WB, T_, 256, 256, N_ * 256, 256, 256,
        256L, (long)L_ * H_, (long)T_ * L_);
    epilogue_kernel<<<ROWS_ / 8, 256>>>(WB, CC, actions, Wc, bc, HD, out);
}

// round 8
// speedup vs baseline: 1.7137x; 1.7137x over previous
#include <cuda_runtime.h>
#include <cuda_bf16.h>
#include <math.h>

#define T_ 128
#define N_ 256
#define L_ 256
#define H_ 256
#define COND_ 64
#define ROWS_ (T_ * N_)   // 32768
#define OUTW_ 770

typedef unsigned long long u64;
typedef unsigned u32;

// ---------------- scratch ----------------------------------------------------
#define XIN_OFF 0L
#define XA_OFF  (XIN_OFF + (long)ROWS_ * 320)
#define XB_OFF  (XA_OFF  + (long)ROWS_ * 256)
#define GI_OFF  (XB_OFF  + (long)ROWS_ * 256)
#define KB_OFF  (GI_OFF  + (long)ROWS_ * 768)
#define WB_OFF  (KB_OFF  + (long)ROWS_ * 256)
#define CC_OFF  (WB_OFF  + (long)ROWS_ * 256)
#define WT_OFF  (CC_OFF + (long)ROWS_)
#define WT_FLOATS 475136L
#define SCRATCH_FLOATS (WT_OFF + WT_FLOATS)

__device__ float g_scratch[SCRATCH_FLOATS];
__device__ unsigned g_bar2[16 * 32];

// bf16 weight-buffer offsets (bf16 element units inside WT)
#define W0H 0
#define W0L 81920
#define W1H 163840
#define W1L 229376
#define W2H 294912
#define W2L 360448
#define WIHH 425984
#define WIHL 622592
#define WAH 819200
#define WAL 884736

// ---------------- packed fp32x2 helpers --------------------------------------
#define FMA2(d, a, b) \
    asm("fma.rn.f32x2 %0, %1, %2, %0;" : "+l"(d) : "l"(a), "l"(b))
#define DUP2(d, x) \
    asm("mov.b64 %0, {%1, %1};" : "=l"(d) : "f"(x))
#define UNPACK2(lo, hi, v) \
    asm("mov.b64 {%0, %1}, %2;" : "=f"(lo), "=f"(hi) : "l"(v))

// ---------------- bf16 helpers ------------------------------------------------
__device__ __forceinline__ void cvt_split(float x0, float x1, u32& h, u32& l) {
    u32 hh;
    asm("cvt.rn.bf16x2.f32 %0, %1, %2;" : "=r"(hh) : "f"(x1), "f"(x0));
    float r0 = x0 - __uint_as_float(hh << 16);
    float r1 = x1 - __uint_as_float(hh & 0xFFFF0000u);
    u32 ll;
    asm("cvt.rn.bf16x2.f32 %0, %1, %2;" : "=r"(ll) : "f"(r1), "f"(r0));
    h = hh; l = ll;
}
__device__ __forceinline__ void ldsm_x4(u32& r0, u32& r1, u32& r2, u32& r3, u32 a) {
    asm volatile("ldmatrix.sync.aligned.m8n8.x4.shared.b16 {%0,%1,%2,%3}, [%4];"
                 : "=r"(r0), "=r"(r1), "=r"(r2), "=r"(r3) : "r"(a));
}
__device__ __forceinline__ void ldsm_x2(u32& r0, u32& r1, u32 a) {
    asm volatile("ldmatrix.sync.aligned.m8n8.x2.shared.b16 {%0,%1}, [%2];"
                 : "=r"(r0), "=r"(r1) : "r"(a));
}
__device__ __forceinline__ void mma_bf16(float* d, const u32* a, const u32* b) {
    asm volatile(
        "mma.sync.aligned.m16n8k16.row.col.f32.bf16.bf16.f32 "
        "{%0,%1,%2,%3}, {%4,%5,%6,%7}, {%8,%9}, {%0,%1,%2,%3};"
        : "+f"(d[0]), "+f"(d[1]), "+f"(d[2]), "+f"(d[3])
        : "r"(a[0]), "r"(a[1]), "r"(a[2]), "r"(a[3]), "r"(b[0]), "r"(b[1]));
}

// ---------------------------------------------------------------------------
// one-off weight conversion: src fp32 -> [n][k] bf16 hi/lo (optional transpose)
__global__ __launch_bounds__(256) void convert_w(
    const float* __restrict__ src, __nv_bfloat16* __restrict__ hi,
    __nv_bfloat16* __restrict__ lo, int K, int Nn, int transpose)
{
    int e = blockIdx.x * 256 + threadIdx.x;
    if (e >= K * Nn) return;
    int n = e / K, k = e % K;
    float v = transpose ? src[(long)k * Nn + n] : src[e];
    __nv_bfloat16 h = __float2bfloat16(v);
    float r = v - __bfloat162float(h);
    hi[e] = h;
    lo[e] = __float2bfloat16(r);
}

// ---------------------------------------------------------------------------
__global__ __launch_bounds__(256) void t0_kernel(
    const float* __restrict__ p0, const float* __restrict__ M,
    const float* __restrict__ C, float* __restrict__ XIN, float* __restrict__ CC)
{
    int n = blockIdx.x;
    int tid = threadIdx.x;
    float v = p0[(long)n * L_ + tid];
    int any = __syncthreads_or(v != 0.f);
    if (!any) {
        XIN[(long)n * 320 + 64 + tid] = M[(long)n * L_ * H_ + tid];
        if (tid == 0) CC[n] = C[(long)n * L_];
        return;
    }
    __shared__ float red[256];
    __shared__ float ps[256];
    ps[tid] = v;
    __syncthreads();
    float acc = 0.f;
    const float* Mn = M + (long)n * L_ * H_;
    for (int l = 0; l < L_; l++)
        acc = fmaf(ps[l], Mn[(long)l * H_ + tid], acc);
    XIN[(long)n * 320 + 64 + tid] = acc;
    red[tid] = ps[tid] * C[(long)n * L_ + tid];
    __syncthreads();
    for (int s = 128; s > 0; s >>= 1) {
        if (tid < s) red[tid] += red[tid + s];
        __syncthreads();
    }
    if (tid == 0) CC[n] = red[0];
}

// ---------------------------------------------------------------------------
__global__ __launch_bounds__(256) void gather_kernel(
    const float* __restrict__ cond, const float* __restrict__ M,
    const float* __restrict__ C, const int* __restrict__ actions,
    float* __restrict__ XIN, float* __restrict__ CC)
{
    int r = threadIdx.x >> 5, lane = threadIdx.x & 31;
    long idx = (long)blockIdx.x * 8 + r;
    int t = (int)(idx / N_), n = (int)(idx % N_);
    float4* dst = (float4*)(XIN + idx * 320);
    const float4* csrc = (const float4*)(cond + idx * COND_);
    if (lane < 16) dst[lane] = csrc[lane];
    if (t > 0) {
        int a = actions[idx - N_];
        const float4* msrc = (const float4*)(M + ((long)n * L_ + a) * H_);
#pragma unroll
        for (int i = 0; i < 2; i++) dst[16 + lane + i * 32] = msrc[lane + i * 32];
        if (lane == 0) CC[idx] = C[(long)n * L_ + a];
    }
}

// ---------------------------------------------------------------------------
// bf16x3 tensor-core GEMM. C = act(A(fp32) @ B^T + bias), B pre-split hi/lo
// [n][k] bf16. Tile 128x128, BK=32. 8 warps (2m x 4n), warp tile 64x32.
// XOR-swizzled smem: row stride 64B, chunk phys = c ^ ((row>>1)&3).
#define BGEMM_SMEM 32768

template <bool RELU>
__global__ __launch_bounds__(256) void gemm_bf16(
    const float* __restrict__ A, const __nv_bfloat16* __restrict__ Bh,
    const __nv_bfloat16* __restrict__ Bl, const float* __restrict__ bias,
    float* __restrict__ C, int Mdim, int Ndim, int K, int lda, int ldc)
{
    extern __shared__ char smx[];
    u32 sb32 = (u32)__cvta_generic_to_shared(smx);

    int m0 = blockIdx.x * 128, n0 = blockIdx.y * 128;
    int tid = threadIdx.x;
    int wid = tid >> 5, lane = tid & 31;
    int warp_m = wid & 1, warp_n = wid >> 1;
    int gid = lane >> 2, tg = lane & 3;

    // staging coords
    int am[4], aq[4], bn_[2], bc_[2];
#pragma unroll
    for (int j = 0; j < 4; j++) {
        int idx = tid + j * 256;
        am[j] = idx >> 3; aq[j] = idx & 7;
    }
#pragma unroll
    for (int j = 0; j < 2; j++) {
        int idx = tid + j * 256;
        bn_[j] = idx >> 2; bc_[j] = idx & 3;
    }

    // frag-load invariants
    int rowa = warp_m * 64 + (lane & 15);
    int rsa = (rowa >> 1) & 3;
    int ha = lane >> 4;               // 0/1 -> k-half
    int rowb = warp_n * 32 + (lane & 7);
    int rsb = (rowb >> 1) & 3;
    int hb = (lane >> 3) & 1;

    float acc[4][4][4];
#pragma unroll
    for (int i = 0; i < 4; i++)
#pragma unroll
        for (int j = 0; j < 4; j++)
#pragma unroll
            for (int v = 0; v < 4; v++) acc[i][j][v] = 0.f;

    auto store_a = [&](int m, int q, float4 v) {
        u32 h01, l01, h23, l23;
        cvt_split(v.x, v.y, h01, l01);
        cvt_split(v.z, v.w, h23, l23);
        char* p = smx + m * 64 + (((q >> 1) ^ ((m >> 1) & 3)) * 16) + (q & 1) * 8;
        *(uint2*)p = make_uint2(h01, h23);
        *(uint2*)(p + 8192) = make_uint2(l01, l23);
    };
    auto store_b = [&](int n, int c, uint4 h, uint4 l) {
        char* p = smx + 16384 + n * 64 + ((c ^ ((n >> 1) & 3)) * 16);
        *(uint4*)p = h;
        *(uint4*)(p + 8192) = l;
    };

    // prologue: stage k-tile 0
#pragma unroll
    for (int j = 0; j < 4; j++) {
        float4 v = *(const float4*)&A[(long)(m0 + am[j]) * lda + aq[j] * 4];
        store_a(am[j], aq[j], v);
    }
#pragma unroll
    for (int j = 0; j < 2; j++) {
        long off = (long)(n0 + bn_[j]) * K + bc_[j] * 8;
        uint4 h = *(const uint4*)(Bh + off);
        uint4 l = *(const uint4*)(Bl + off);
        store_b(bn_[j], bc_[j], h, l);
    }
    __syncthreads();

    int nk = K / 32;
    for (int kt = 0; kt < nk; kt++) {
        float4 ra[4];
        uint4 rbh[2], rbl[2];
        bool nxt = (kt + 1 < nk);
        if (nxt) {
            int k0 = (kt + 1) * 32;
#pragma unroll
            for (int j = 0; j < 4; j++)
                ra[j] = *(const float4*)&A[(long)(m0 + am[j]) * lda + k0 + aq[j] * 4];
#pragma unroll
            for (int j = 0; j < 2; j++) {
                long off = (long)(n0 + bn_[j]) * K + k0 + bc_[j] * 8;
                rbh[j] = *(const uint4*)(Bh + off);
                rbl[j] = *(const uint4*)(Bl + off);
            }
        }

#pragma unroll
        for (int ks = 0; ks < 2; ks++) {
            u32 bh[4][2], bl[4][2];
#pragma unroll
            for (int ni = 0; ni < 4; ni++) {
                int cb = (ks * 2 + hb) ^ rsb;
                u32 addr = sb32 + 16384 + (rowb + ni * 8) * 64 + cb * 16;
                ldsm_x2(bh[ni][0], bh[ni][1], addr);
                ldsm_x2(bl[ni][0], bl[ni][1], addr + 8192);
            }
#pragma unroll
            for (int mi = 0; mi < 4; mi++) {
                int ca = (ks * 2 + ha) ^ rsa;
                u32 addr = sb32 + (rowa + mi * 16) * 64 + ca * 16;
                u32 ah[4], al[4];
                ldsm_x4(ah[0], ah[1], ah[2], ah[3], addr);
                ldsm_x4(al[0], al[1], al[2], al[3], addr + 8192);
#pragma unroll
                for (int ni = 0; ni < 4; ni++) {
                    mma_bf16(acc[mi][ni], ah, bh[ni]);
                    mma_bf16(acc[mi][ni], ah, bl[ni]);
                    mma_bf16(acc[mi][ni], al, bh[ni]);
                }
            }
        }
        __syncthreads();
        if (nxt) {
#pragma unroll
            for (int j = 0; j < 4; j++) store_a(am[j], aq[j], ra[j]);
#pragma unroll
            for (int j = 0; j < 2; j++) store_b(bn_[j], bc_[j], rbh[j], rbl[j]);
        }
        __syncthreads();
    }

    // epilogue
#pragma unroll
    for (int mi = 0; mi < 4; mi++) {
        int mbase = m0 + warp_m * 64 + mi * 16;
#pragma unroll
        for (int ni = 0; ni < 4; ni++) {
            int col = n0 + warp_n * 32 + ni * 8 + tg * 2;
            float b0 = 0.f, b1 = 0.f;
            if (bias) { b0 = bias[col]; b1 = bias[col + 1]; }
            float v0 = acc[mi][ni][0] + b0, v1 = acc[mi][ni][1] + b1;
            float v2 = acc[mi][ni][2] + b0, v3 = acc[mi][ni][3] + b1;
            if (RELU) {
                v0 = fmaxf(v0, 0.f); v1 = fmaxf(v1, 0.f);
                v2 = fmaxf(v2, 0.f); v3 = fmaxf(v3, 0.f);
            }
            *(float2*)&C[(long)(mbase + gid) * ldc + col] = make_float2(v0, v1);
            *(float2*)&C[(long)(mbase + gid + 8) * ldc + col] = make_float2(v2, v3);
        }
    }
}

// ---------------------------------------------------------------------------
// fp32 GEMM (R5): 128x64 tile, 8x4/thread, f32x2, reg-prefetch. For Km batch.
template <bool TRANSB, bool RELU>
__global__ __launch_bounds__(256, 2) void gemm_kernel(
    const float* __restrict__ A, const float* __restrict__ B,
    const float* __restrict__ bias, float* __restrict__ C,
    int M, int N, int K, int lda, int ldb, int ldc,
    long batchA, long batchB, long batchC)
{
    constexpr int BM = 128, BN = 64, BK = 16;
    __shared__ float As[2][BK][BM + 4];
    __shared__ float Bs[2][BK][BN + 4];

    long bz = blockIdx.z;
    A += bz * batchA; B += bz * batchB; C += bz * batchC;
    int m0 = blockIdx.x * BM, n0 = blockIdx.y * BN;
    int tid = threadIdx.x;
    int tx = tid & 15, ty = tid >> 4;

    int am[2], ac[2];
#pragma unroll
    for (int i = 0; i < 2; i++) {
        int idx = tid + i * 256;
        am[i] = idx & 127; ac[i] = idx >> 7;
    }
    int bk = tid >> 4, bn4 = tid & 15;
    int bn = tid & 63, bc2 = tid >> 6;

    u64 acc[4][4];
#pragma unroll
    for (int p = 0; p < 4; p++)
#pragma unroll
        for (int c = 0; c < 4; c++) acc[p][c] = 0ull;

    {
#pragma unroll
        for (int i = 0; i < 2; i++) {
            float4 v = *(const float4*)&A[(long)(m0 + am[i]) * lda + ac[i] * 4];
            As[0][ac[i] * 4 + 0][am[i]] = v.x;
            As[0][ac[i] * 4 + 1][am[i]] = v.y;
            As[0][ac[i] * 4 + 2][am[i]] = v.z;
            As[0][ac[i] * 4 + 3][am[i]] = v.w;
        }
        if (!TRANSB) {
            float4 b = *(const float4*)&B[(long)bk * ldb + n0 + bn4 * 4];
            *(float4*)&Bs[0][bk][bn4 * 4] = b;
        } else {
            float4 b = *(const float4*)&B[(long)(n0 + bn) * ldb + bc2 * 4];
            Bs[0][bc2 * 4 + 0][bn] = b.x;
            Bs[0][bc2 * 4 + 1][bn] = b.y;
            Bs[0][bc2 * 4 + 2][bn] = b.z;
            Bs[0][bc2 * 4 + 3][bn] = b.w;
        }
    }
    __syncthreads();

    int nk = K / BK;
    float4 ra[2], rb;
    for (int it = 0; it < nk; it++) {
        int buf = it & 1;
        bool has_next = (it + 1 < nk);
        if (has_next) {
            int k0 = (it + 1) * BK;
#pragma unroll
            for (int i = 0; i < 2; i++)
                ra[i] = *(const float4*)&A[(long)(m0 + am[i]) * lda + k0 + ac[i] * 4];
            if (!TRANSB)
                rb = *(const float4*)&B[(long)(k0 + bk) * ldb + n0 + bn4 * 4];
            else
                rb = *(const float4*)&B[(long)(n0 + bn) * ldb + k0 + bc2 * 4];
        }
        ulonglong2 a01c = *(const ulonglong2*)&As[buf][0][ty * 8];
        ulonglong2 a23c = *(const ulonglong2*)&As[buf][0][ty * 8 + 4];
        float4 bfc = *(const float4*)&Bs[buf][0][tx * 4];
#pragma unroll
        for (int k = 0; k < BK; k++) {
            ulonglong2 a01n, a23n; float4 bfn;
            if (k < BK - 1) {
                a01n = *(const ulonglong2*)&As[buf][k + 1][ty * 8];
                a23n = *(const ulonglong2*)&As[buf][k + 1][ty * 8 + 4];
                bfn = *(const float4*)&Bs[buf][k + 1][tx * 4];
            }
            u64 bd0, bd1, bd2, bd3;
            DUP2(bd0, bfc.x); DUP2(bd1, bfc.y); DUP2(bd2, bfc.z); DUP2(bd3, bfc.w);
            FMA2(acc[0][0], a01c.x, bd0); FMA2(acc[0][1], a01c.x, bd1);
            FMA2(acc[0][2], a01c.x, bd2); FMA2(acc[0][3], a01c.x, bd3);
            FMA2(acc[1][0], a01c.y, bd0); FMA2(acc[1][1], a01c.y, bd1);
            FMA2(acc[1][2], a01c.y, bd2); FMA2(acc[1][3], a01c.y, bd3);
            FMA2(acc[2][0], a23c.x, bd0); FMA2(acc[2][1], a23c.x, bd1);
            FMA2(acc[2][2], a23c.x, bd2); FMA2(acc[2][3], a23c.x, bd3);
            FMA2(acc[3][0], a23c.y, bd0); FMA2(acc[3][1], a23c.y, bd1);
            FMA2(acc[3][2], a23c.y, bd2); FMA2(acc[3][3], a23c.y, bd3);
            if (k < BK - 1) { a01c = a01n; a23c = a23n; bfc = bfn; }
        }
        if (has_next) {
            int nb = buf ^ 1;
#pragma unroll
            for (int i = 0; i < 2; i++) {
                As[nb][ac[i] * 4 + 0][am[i]] = ra[i].x;
                As[nb][ac[i] * 4 + 1][am[i]] = ra[i].y;
                As[nb][ac[i] * 4 + 2][am[i]] = ra[i].z;
                As[nb][ac[i] * 4 + 3][am[i]] = ra[i].w;
            }
            if (!TRANSB) {
                *(float4*)&Bs[nb][bk][bn4 * 4] = rb;
            } else {
                Bs[nb][bc2 * 4 + 0][bn] = rb.x;
                Bs[nb][bc2 * 4 + 1][bn] = rb.y;
                Bs[nb][bc2 * 4 + 2][bn] = rb.z;
                Bs[nb][bc2 * 4 + 3][bn] = rb.w;
            }
        }
        __syncthreads();
    }

    float4 bv = make_float4(0.f, 0.f, 0.f, 0.f);
    if (bias) bv = *(const float4*)&bias[n0 + tx * 4];
#pragma unroll
    for (int p = 0; p < 4; p++) {
        float r0[4], r1[4];
#pragma unroll
        for (int c = 0; c < 4; c++) UNPACK2(r0[c], r1[c], acc[p][c]);
        r0[0] += bv.x; r0[1] += bv.y; r0[2] += bv.z; r0[3] += bv.w;
        r1[0] += bv.x; r1[1] += bv.y; r1[2] += bv.z; r1[3] += bv.w;
        if (RELU) {
#pragma unroll
            for (int c = 0; c < 4; c++) {
                r0[c] = fmaxf(r0[c], 0.f);
                r1[c] = fmaxf(r1[c], 0.f);
            }
        }
        int m = m0 + ty * 8 + 2 * p;
        *(float4*)&C[(long)m * ldc + n0 + tx * 4] = *(float4*)r0;
        *(float4*)&C[(long)(m + 1) * ldc + n0 + tx * 4] = *(float4*)r1;
    }
}

// ---------------------------------------------------------------------------
// persistent GRU (R5 best: k-split x2, per-nt group barrier, fast exp)
#define GRU_BLOCKS 128
#define HSTR 260

__device__ __forceinline__ float sigmf(float x) { return 1.f / (1.f + __expf(-x)); }
__device__ __forceinline__ float tanhfast(float x) { return 2.f / (1.f + __expf(-2.f * x)) - 1.f; }

__global__ __launch_bounds__(256) void gru_persistent(
    const float* __restrict__ GI, const float* __restrict__ h0,
    const float* __restrict__ W_hh, const float* __restrict__ b_hh,
    float* __restrict__ HD)
{
    extern __shared__ float smem[];
    float4* w4 = (float4*)smem;
    float* hs = smem + 4 * 64 * 48;
    u64* redm = (u64*)(hs + 32 * HSTR);

    int tid = threadIdx.x;
    int jt = blockIdx.x & 15, nt = blockIdx.x >> 4;
    int j0 = jt * 16, n0 = nt * 32;
    int kg = tid >> 7;
    int lt = tid & 127;
    int jj = lt & 15, nn8 = lt >> 4;
    int j = j0 + jj;

    unsigned* arr = &g_bar2[nt * 32];
    unsigned* ep  = &g_bar2[(8 + nt) * 32];

    for (int e = tid; e < 48 * 64; e += 256) {
        int c = e & 63, r = e >> 6;
        int g = r >> 4, jr = r & 15;
        w4[c * 48 + r] = *(const float4*)&W_hh[(long)(g * 256 + j0 + jr) * 256 + c * 4];
    }
    float bhr = b_hh[j], bhz = b_hh[256 + j], bhn = b_hh[512 + j];

    float gi_r[4], gi_z[4], gi_n[4];
    if (kg == 0) {
#pragma unroll
        for (int i = 0; i < 4; i++) {
            const float* g = GI + ((long)(n0 + nn8 + 8 * i)) * 768;
            gi_r[i] = g[j]; gi_z[i] = g[256 + j]; gi_n[i] = g[512 + j];
        }
    }
    int cbase = kg * 32;

    for (int t = 0; t < T_; t++) {
        const float* hin = (t == 0) ? h0 : (HD + (long)(t - 1) * N_ * H_);
        float* hout = HD + (long)t * N_ * H_;

        {
            int n = tid >> 3, f = tid & 7;
            const float4* src = (const float4*)(hin + (long)(n0 + n) * H_);
            float4* dst = (float4*)(hs + n * HSTR);
#pragma unroll
            for (int i = 0; i < 8; i++) dst[f + 8 * i] = src[f + 8 * i];
        }
        __syncthreads();

        u64 acc[4][3];
#pragma unroll
        for (int i = 0; i < 4; i++)
#pragma unroll
            for (int g = 0; g < 3; g++) acc[i][g] = 0ull;

#pragma unroll 8
        for (int c = cbase; c < cbase + 32; c++) {
            const ulonglong2* wrow = (const ulonglong2*)(w4 + c * 48);
            ulonglong2 w0 = wrow[jj];
            ulonglong2 w1 = wrow[16 + jj];
            ulonglong2 w2 = wrow[32 + jj];
#pragma unroll
            for (int i = 0; i < 4; i++) {
                ulonglong2 hv = *(const ulonglong2*)(hs + (nn8 + 8 * i) * HSTR + c * 4);
                FMA2(acc[i][0], hv.x, w0.x); FMA2(acc[i][0], hv.y, w0.y);
                FMA2(acc[i][1], hv.x, w1.x); FMA2(acc[i][1], hv.y, w1.y);
                FMA2(acc[i][2], hv.x, w2.x); FMA2(acc[i][2], hv.y, w2.y);
            }
        }

        if (kg == 1) {
#pragma unroll
            for (int i = 0; i < 4; i++)
#pragma unroll
                for (int g = 0; g < 3; g++) redm[lt * 12 + i * 3 + g] = acc[i][g];
        }
        __syncthreads();

        if (kg == 0) {
#pragma unroll
            for (int i = 0; i < 4; i++) {
                float lo, hi, s[3];
#pragma unroll
                for (int g = 0; g < 3; g++) {
                    UNPACK2(lo, hi, acc[i][g]);
                    s[g] = lo + hi;
                    UNPACK2(lo, hi, redm[lt * 12 + i * 3 + g]);
                    s[g] += lo + hi;
                }
                int nl = nn8 + 8 * i;
                float rg = sigmf(gi_r[i] + s[0] + bhr);
                float z  = sigmf(gi_z[i] + s[1] + bhz);
                float nv = tanhfast(gi_n[i] + rg * (s[2] + bhn));
                float hp = hs[nl * HSTR + j];
                float hn = (1.f - z) * nv + z * hp;
                hout[(long)(n0 + nl) * H_ + j] = hn;
            }
        }

        if (t < T_ - 1) {
            __syncthreads();
            if (tid == 0) {
                unsigned prev;
                asm volatile("atom.release.gpu.global.add.u32 %0, [%1], %2;"
                             : "=r"(prev) : "l"(arr), "r"(1u) : "memory");
                if (prev == (unsigned)((t + 1) * 16 - 1)) {
                    asm volatile("st.release.gpu.global.u32 [%0], %1;"
                                 :: "l"(ep), "r"((unsigned)(t + 1)) : "memory");
                }
            }
            if (kg == 0) {
#pragma unroll
                for (int i = 0; i < 4; i++) {
                    const float* g = GI + ((long)(t + 1) * N_ + n0 + nn8 + 8 * i) * 768;
                    gi_r[i] = g[j]; gi_z[i] = g[256 + j]; gi_n[i] = g[512 + j];
                }
            }
            if (tid == 0) {
                unsigned e;
                do {
                    asm volatile("ld.acquire.gpu.global.u32 %0, [%1];"
                                 : "=r"(e) : "l"(ep) : "memory");
                } while (e < (unsigned)(t + 1));
            }
            __syncthreads();
        }
    }
}

// ---------------------------------------------------------------------------
__global__ __launch_bounds__(256) void epilogue_kernel(
    const float* __restrict__ WB, const float* __restrict__ CC,
    const int* __restrict__ actions, const float* __restrict__ Wc,
    const float* __restrict__ bc, const float* __restrict__ HD,
    float* __restrict__ out)
{
    int wid = threadIdx.x >> 5, lane = threadIdx.x & 31;
    long idx = (long)blockIdx.x * 8 + wid;
    int t = (int)(idx / N_), n = (int)(idx % N_);
    float cc = CC[idx];
    long base = idx * OUTW_;

    const float4* hrow = (const float4*)(HD + idx * 256);
    const float4* wc = (const float4*)Wc;
    float4 h0v = hrow[lane * 2], h1v = hrow[lane * 2 + 1];
    float4 c0 = wc[lane * 2], c1 = wc[lane * 2 + 1];
    float2* hdst = (float2*)(out + base + 2 + lane * 8);
    hdst[0] = make_float2(h0v.x, h0v.y);
    hdst[1] = make_float2(h0v.z, h0v.w);
    hdst[2] = make_float2(h1v.x, h1v.y);
    hdst[3] = make_float2(h1v.z, h1v.w);
    float d = h0v.x * c0.x + h0v.y * c0.y + h0v.z * c0.z + h0v.w * c0.w
            + h1v.x * c1.x + h1v.y * c1.y + h1v.z * c1.z + h1v.w * c1.w;
#pragma unroll
    for (int o = 16; o; o >>= 1) d += __shfl_xor_sync(~0u, d, o);

    const float4* wrow = (const float4*)(WB + ((long)n * T_ + t) * L_);
    float4 w0 = wrow[lane * 2], w1 = wrow[lane * 2 + 1];
    float wv[8] = {w0.x * cc, w0.y * cc, w0.z * cc, w0.w * cc,
                   w1.x * cc, w1.y * cc, w1.z * cc, w1.w * cc};
    float mx = wv[0];
#pragma unroll
    for (int i = 1; i < 8; i++) mx = fmaxf(mx, wv[i]);
#pragma unroll
    for (int o = 16; o; o >>= 1) mx = fmaxf(mx, __shfl_xor_sync(~0u, mx, o));
    float e[8], s = 0.f;
#pragma unroll
    for (int i = 0; i < 8; i++) { e[i] = expf(wv[i] - mx); s += e[i]; }
#pragma unroll
    for (int o = 16; o; o >>= 1) s += __shfl_xor_sync(~0u, s, o);
    float inv = 1.f / s;

    int a = actions[idx];
    float2* pdst = (float2*)(out + base + 258 + lane * 8);
    float2* odst = (float2*)(out + base + 514 + lane * 8);
#pragma unroll
    for (int i = 0; i < 4; i++) {
        pdst[i] = make_float2(e[2 * i] * inv, e[2 * i + 1] * inv);
        int l0 = lane * 8 + 2 * i;
        odst[i] = make_float2(l0 == a ? 1.f : 0.f, l0 + 1 == a ? 1.f : 0.f);
    }
    if (lane == 0) {
        out[base + 0] = (float)a;
        out[base + 1] = d + bc[0];
    }
}

// ---------------------------------------------------------------------------
extern "C" void kernel_launch(void* const* d_in, const int* in_sizes, int n_in,
                              void* d_out, int out_size)
{
    const float* cond = (const float*)d_in[0];
    const float* M    = (const float*)d_in[1];
    const float* Km   = (const float*)d_in[2];
    const float* Cm   = (const float*)d_in[3];
    const float* h0   = (const float*)d_in[4];
    const float* p0   = (const float*)d_in[5];
    const float* W0   = (const float*)d_in[6];
    const float* b0   = (const float*)d_in[7];
    const float* W1   = (const float*)d_in[8];
    const float* b1   = (const float*)d_in[9];
    const float* W2   = (const float*)d_in[10];
    const float* b2   = (const float*)d_in[11];
    const float* W_ih = (const float*)d_in[12];
    const float* W_hh = (const float*)d_in[13];
    const float* b_ih = (const float*)d_in[14];
    const float* b_hh = (const float*)d_in[15];
    const float* Wa   = (const float*)d_in[16];
    const float* ba   = (const float*)d_in[17];
    const float* Wc   = (const float*)d_in[18];
    const float* bc   = (const float*)d_in[19];
    const int* actions = (const int*)d_in[20];
    float* out = (float*)d_out;

    float* base = nullptr;
    cudaGetSymbolAddress((void**)&base, g_scratch);
    float* XIN = base + XIN_OFF;
    float* XA  = base + XA_OFF;
    float* XB  = base + XB_OFF;
    float* GI  = base + GI_OFF;
    float* KB  = base + KB_OFF;
    float* WB  = base + WB_OFF;
    float* CC  = base + CC_OFF;
    float* HD  = base + XIN_OFF;
    __nv_bfloat16* WT = (__nv_bfloat16*)(base + WT_OFF);

    void* bar_addr = nullptr;
    cudaGetSymbolAddress(&bar_addr, g_bar2);

    const int GRU_SMEM = 4 * 64 * 48 * 4 + 32 * HSTR * 4 + 128 * 12 * 8;
    cudaFuncSetAttribute(gru_persistent,
                         cudaFuncAttributeMaxDynamicSharedMemorySize, GRU_SMEM);

    // phase 0: weight conversion (tiny, once per launch)
    convert_w<<<320, 256>>>(W0, WT + W0H, WT + W0L, 320, 256, 1);
    convert_w<<<256, 256>>>(W1, WT + W1H, WT + W1L, 256, 256, 1);
    convert_w<<<256, 256>>>(W2, WT + W2H, WT + W2L, 256, 256, 1);
    convert_w<<<768, 256>>>(W_ih, WT + WIHH, WT + WIHL, 256, 768, 0);
    convert_w<<<256, 256>>>(Wa, WT + WAH, WT + WAL, 256, 256, 1);

    // phase A
    t0_kernel<<<N_, 256>>>(p0, M, Cm, XIN, CC);
    gather_kernel<<<ROWS_ / 8, 256>>>(cond, M, Cm, actions, XIN, CC);
    gemm_bf16<true><<<dim3(ROWS_ / 128, 2), 256, BGEMM_SMEM>>>(
        XIN, WT + W0H, WT + W0L, b0, XA, ROWS_, 256, 320, 320, 256);
    gemm_bf16<true><<<dim3(ROWS_ / 128, 2), 256, BGEMM_SMEM>>>(
        XA, WT + W1H, WT + W1L, b1, XB, ROWS_, 256, 256, 256, 256);
    gemm_bf16<true><<<dim3(ROWS_ / 128, 2), 256, BGEMM_SMEM>>>(
        XB, WT + W2H, WT + W2L, b2, XA, ROWS_, 256, 256, 256, 256);
    gemm_bf16<false><<<dim3(ROWS_ / 128, 6), 256, BGEMM_SMEM>>>(
        XA, WT + WIHH, WT + WIHL, b_ih, GI, ROWS_, 768, 256, 256, 768);

    // phase B
    cudaMemsetAsync(bar_addr, 0, 16 * 32 * sizeof(unsigned));
    gru_persistent<<<GRU_BLOCKS, 256, GRU_SMEM>>>(GI, h0, W_hh, b_hh, HD);

    // phase C
    gemm_bf16<false><<<dim3(ROWS_ / 128, 2), 256, BGEMM_SMEM>>>(
        HD, WT + WAH, WT + WAL, ba, KB, ROWS_, 256, 256, 256, 256);
    gemm_kernel<true, false><<<dim3(1, 4, N_), 256>>>(
        KB, Km, nullptr, WB, T_, 256, 256, N_ * 256, 256, 256,
        256L, (long)L_ * H_, (long)T_ * L_);
    epilogue_kernel<<<ROWS_ / 8, 256>>>(WB, CC, actions, Wc, bc, HD, out);
}

// round 9
// speedup vs baseline: 2.1481x; 1.2535x over previous
#include <cuda_runtime.h>
#include <cuda_bf16.h>
#include <math.h>

#define T_ 128
#define N_ 256
#define L_ 256
#define H_ 256
#define COND_ 64
#define ROWS_ (T_ * N_)   // 32768
#define OUTW_ 770

typedef unsigned long long u64;
typedef unsigned u32;

// ---------------- scratch ----------------------------------------------------
#define XIN_OFF 0L
#define XA_OFF  (XIN_OFF + (long)ROWS_ * 320)
#define XB_OFF  (XA_OFF  + (long)ROWS_ * 256)
#define GI_OFF  (XB_OFF  + (long)ROWS_ * 256)
#define KB_OFF  (GI_OFF  + (long)ROWS_ * 768)
#define WB_OFF  (KB_OFF  + (long)ROWS_ * 256)
#define CC_OFF  (WB_OFF  + (long)ROWS_ * 256)
#define WT_OFF  (CC_OFF + (long)ROWS_)
#define WT_FLOATS 475136L
#define HBH_OFF (WT_OFF + WT_FLOATS)
#define HBL_OFF (HBH_OFF + 4194304L)
#define HB0H_OFF (HBL_OFF + 4194304L)
#define HB0L_OFF (HB0H_OFF + 32768L)
#define SCRATCH_FLOATS (HB0L_OFF + 32768L)

__device__ float g_scratch[SCRATCH_FLOATS];
__device__ unsigned g_bar2[16 * 32];

// bf16 weight-buffer offsets (bf16 element units inside WT)
#define W0H 0
#define W0L 81920
#define W1H 163840
#define W1L 229376
#define W2H 294912
#define W2L 360448
#define WIHH 425984
#define WIHL 622592
#define WAH 819200
#define WAL 884736

// ---------------- packed fp32x2 helpers --------------------------------------
#define FMA2(d, a, b) \
    asm("fma.rn.f32x2 %0, %1, %2, %0;" : "+l"(d) : "l"(a), "l"(b))
#define DUP2(d, x) \
    asm("mov.b64 %0, {%1, %1};" : "=l"(d) : "f"(x))
#define UNPACK2(lo, hi, v) \
    asm("mov.b64 {%0, %1}, %2;" : "=f"(lo), "=f"(hi) : "l"(v))

// ---------------- bf16 helpers ------------------------------------------------
__device__ __forceinline__ void cvt_split(float x0, float x1, u32& h, u32& l) {
    u32 hh;
    asm("cvt.rn.bf16x2.f32 %0, %1, %2;" : "=r"(hh) : "f"(x1), "f"(x0));
    float r0 = x0 - __uint_as_float(hh << 16);
    float r1 = x1 - __uint_as_float(hh & 0xFFFF0000u);
    u32 ll;
    asm("cvt.rn.bf16x2.f32 %0, %1, %2;" : "=r"(ll) : "f"(r1), "f"(r0));
    h = hh; l = ll;
}
__device__ __forceinline__ void ldsm_x4(u32& r0, u32& r1, u32& r2, u32& r3, u32 a) {
    asm volatile("ldmatrix.sync.aligned.m8n8.x4.shared.b16 {%0,%1,%2,%3}, [%4];"
                 : "=r"(r0), "=r"(r1), "=r"(r2), "=r"(r3) : "r"(a));
}
__device__ __forceinline__ void ldsm_x2(u32& r0, u32& r1, u32 a) {
    asm volatile("ldmatrix.sync.aligned.m8n8.x2.shared.b16 {%0,%1}, [%2];"
                 : "=r"(r0), "=r"(r1) : "r"(a));
}
__device__ __forceinline__ void mma_bf16(float* d, const u32* a, const u32* b) {
    asm volatile(
        "mma.sync.aligned.m16n8k16.row.col.f32.bf16.bf16.f32 "
        "{%0,%1,%2,%3}, {%4,%5,%6,%7}, {%8,%9}, {%0,%1,%2,%3};"
        : "+f"(d[0]), "+f"(d[1]), "+f"(d[2]), "+f"(d[3])
        : "r"(a[0]), "r"(a[1]), "r"(a[2]), "r"(a[3]), "r"(b[0]), "r"(b[1]));
}

// ---------------------------------------------------------------------------
__global__ __launch_bounds__(256) void convert_w(
    const float* __restrict__ src, __nv_bfloat16* __restrict__ hi,
    __nv_bfloat16* __restrict__ lo, int K, int Nn, int transpose)
{
    int e = blockIdx.x * 256 + threadIdx.x;
    if (e >= K * Nn) return;
    int n = e / K, k = e % K;
    float v = transpose ? src[(long)k * Nn + n] : src[e];
    __nv_bfloat16 h = __float2bfloat16(v);
    float r = v - __bfloat162float(h);
    hi[e] = h;
    lo[e] = __float2bfloat16(r);
}

__global__ __launch_bounds__(256) void convert_h0(
    const float* __restrict__ h0, __nv_bfloat16* __restrict__ hi,
    __nv_bfloat16* __restrict__ lo)
{
    int e = blockIdx.x * 256 + threadIdx.x;
    float v = h0[e];
    __nv_bfloat16 h = __float2bfloat16(v);
    hi[e] = h;
    lo[e] = __float2bfloat16(v - __bfloat162float(h));
}

// ---------------------------------------------------------------------------
__global__ __launch_bounds__(256) void t0_kernel(
    const float* __restrict__ p0, const float* __restrict__ M,
    const float* __restrict__ C, float* __restrict__ XIN, float* __restrict__ CC)
{
    int n = blockIdx.x;
    int tid = threadIdx.x;
    float v = p0[(long)n * L_ + tid];
    int any = __syncthreads_or(v != 0.f);
    if (!any) {
        XIN[(long)n * 320 + 64 + tid] = M[(long)n * L_ * H_ + tid];
        if (tid == 0) CC[n] = C[(long)n * L_];
        return;
    }
    __shared__ float red[256];
    __shared__ float ps[256];
    ps[tid] = v;
    __syncthreads();
    float acc = 0.f;
    const float* Mn = M + (long)n * L_ * H_;
    for (int l = 0; l < L_; l++)
        acc = fmaf(ps[l], Mn[(long)l * H_ + tid], acc);
    XIN[(long)n * 320 + 64 + tid] = acc;
    red[tid] = ps[tid] * C[(long)n * L_ + tid];
    __syncthreads();
    for (int s = 128; s > 0; s >>= 1) {
        if (tid < s) red[tid] += red[tid + s];
        __syncthreads();
    }
    if (tid == 0) CC[n] = red[0];
}

// ---------------------------------------------------------------------------
__global__ __launch_bounds__(256) void gather_kernel(
    const float* __restrict__ cond, const float* __restrict__ M,
    const float* __restrict__ C, const int* __restrict__ actions,
    float* __restrict__ XIN, float* __restrict__ CC)
{
    int r = threadIdx.x >> 5, lane = threadIdx.x & 31;
    long idx = (long)blockIdx.x * 8 + r;
    int t = (int)(idx / N_), n = (int)(idx % N_);
    float4* dst = (float4*)(XIN + idx * 320);
    const float4* csrc = (const float4*)(cond + idx * COND_);
    if (lane < 16) dst[lane] = csrc[lane];
    if (t > 0) {
        int a = actions[idx - N_];
        const float4* msrc = (const float4*)(M + ((long)n * L_ + a) * H_);
#pragma unroll
        for (int i = 0; i < 2; i++) dst[16 + lane + i * 32] = msrc[lane + i * 32];
        if (lane == 0) CC[idx] = C[(long)n * L_ + a];
    }
}

// ---------------------------------------------------------------------------
// bf16x3 tensor-core GEMM (R8, proven). C = act(A(fp32) @ B^T + bias).
#define BGEMM_SMEM 32768

template <bool RELU>
__global__ __launch_bounds__(256) void gemm_bf16(
    const float* __restrict__ A, const __nv_bfloat16* __restrict__ Bh,
    const __nv_bfloat16* __restrict__ Bl, const float* __restrict__ bias,
    float* __restrict__ C, int Mdim, int Ndim, int K, int lda, int ldc)
{
    extern __shared__ char smx[];
    u32 sb32 = (u32)__cvta_generic_to_shared(smx);

    int m0 = blockIdx.x * 128, n0 = blockIdx.y * 128;
    int tid = threadIdx.x;
    int wid = tid >> 5, lane = tid & 31;
    int warp_m = wid & 1, warp_n = wid >> 1;
    int gid = lane >> 2, tg = lane & 3;

    int am[4], aq[4], bn_[2], bc_[2];
#pragma unroll
    for (int j = 0; j < 4; j++) {
        int idx = tid + j * 256;
        am[j] = idx >> 3; aq[j] = idx & 7;
    }
#pragma unroll
    for (int j = 0; j < 2; j++) {
        int idx = tid + j * 256;
        bn_[j] = idx >> 2; bc_[j] = idx & 3;
    }

    int rowa = warp_m * 64 + (lane & 15);
    int rsa = (rowa >> 1) & 3;
    int ha = lane >> 4;
    int rowb = warp_n * 32 + (lane & 7);
    int rsb = (rowb >> 1) & 3;
    int hb = (lane >> 3) & 1;

    float acc[4][4][4];
#pragma unroll
    for (int i = 0; i < 4; i++)
#pragma unroll
        for (int j = 0; j < 4; j++)
#pragma unroll
            for (int v = 0; v < 4; v++) acc[i][j][v] = 0.f;

    auto store_a = [&](int m, int q, float4 v) {
        u32 h01, l01, h23, l23;
        cvt_split(v.x, v.y, h01, l01);
        cvt_split(v.z, v.w, h23, l23);
        char* p = smx + m * 64 + (((q >> 1) ^ ((m >> 1) & 3)) * 16) + (q & 1) * 8;
        *(uint2*)p = make_uint2(h01, h23);
        *(uint2*)(p + 8192) = make_uint2(l01, l23);
    };
    auto store_b = [&](int n, int c, uint4 h, uint4 l) {
        char* p = smx + 16384 + n * 64 + ((c ^ ((n >> 1) & 3)) * 16);
        *(uint4*)p = h;
        *(uint4*)(p + 8192) = l;
    };

#pragma unroll
    for (int j = 0; j < 4; j++) {
        float4 v = *(const float4*)&A[(long)(m0 + am[j]) * lda + aq[j] * 4];
        store_a(am[j], aq[j], v);
    }
#pragma unroll
    for (int j = 0; j < 2; j++) {
        long off = (long)(n0 + bn_[j]) * K + bc_[j] * 8;
        uint4 h = *(const uint4*)(Bh + off);
        uint4 l = *(const uint4*)(Bl + off);
        store_b(bn_[j], bc_[j], h, l);
    }
    __syncthreads();

    int nk = K / 32;
    for (int kt = 0; kt < nk; kt++) {
        float4 ra[4];
        uint4 rbh[2], rbl[2];
        bool nxt = (kt + 1 < nk);
        if (nxt) {
            int k0 = (kt + 1) * 32;
#pragma unroll
            for (int j = 0; j < 4; j++)
                ra[j] = *(const float4*)&A[(long)(m0 + am[j]) * lda + k0 + aq[j] * 4];
#pragma unroll
            for (int j = 0; j < 2; j++) {
                long off = (long)(n0 + bn_[j]) * K + k0 + bc_[j] * 8;
                rbh[j] = *(const uint4*)(Bh + off);
                rbl[j] = *(const uint4*)(Bl + off);
            }
        }

#pragma unroll
        for (int ks = 0; ks < 2; ks++) {
            u32 bhf[4][2], blf[4][2];
#pragma unroll
            for (int ni = 0; ni < 4; ni++) {
                int cb = (ks * 2 + hb) ^ rsb;
                u32 addr = sb32 + 16384 + (rowb + ni * 8) * 64 + cb * 16;
                ldsm_x2(bhf[ni][0], bhf[ni][1], addr);
                ldsm_x2(blf[ni][0], blf[ni][1], addr + 8192);
            }
#pragma unroll
            for (int mi = 0; mi < 4; mi++) {
                int ca = (ks * 2 + ha) ^ rsa;
                u32 addr = sb32 + (rowa + mi * 16) * 64 + ca * 16;
                u32 ah[4], al[4];
                ldsm_x4(ah[0], ah[1], ah[2], ah[3], addr);
                ldsm_x4(al[0], al[1], al[2], al[3], addr + 8192);
#pragma unroll
                for (int ni = 0; ni < 4; ni++) {
                    mma_bf16(acc[mi][ni], ah, bhf[ni]);
                    mma_bf16(acc[mi][ni], ah, blf[ni]);
                    mma_bf16(acc[mi][ni], al, bhf[ni]);
                }
            }
        }
        __syncthreads();
        if (nxt) {
#pragma unroll
            for (int j = 0; j < 4; j++) store_a(am[j], aq[j], ra[j]);
#pragma unroll
            for (int j = 0; j < 2; j++) store_b(bn_[j], bc_[j], rbh[j], rbl[j]);
        }
        __syncthreads();
    }

#pragma unroll
    for (int mi = 0; mi < 4; mi++) {
        int mbase = m0 + warp_m * 64 + mi * 16;
#pragma unroll
        for (int ni = 0; ni < 4; ni++) {
            int col = n0 + warp_n * 32 + ni * 8 + tg * 2;
            float b0 = 0.f, b1 = 0.f;
            if (bias) { b0 = bias[col]; b1 = bias[col + 1]; }
            float v0 = acc[mi][ni][0] + b0, v1 = acc[mi][ni][1] + b1;
            float v2 = acc[mi][ni][2] + b0, v3 = acc[mi][ni][3] + b1;
            if (RELU) {
                v0 = fmaxf(v0, 0.f); v1 = fmaxf(v1, 0.f);
                v2 = fmaxf(v2, 0.f); v3 = fmaxf(v3, 0.f);
            }
            *(float2*)&C[(long)(mbase + gid) * ldc + col] = make_float2(v0, v1);
            *(float2*)&C[(long)(mbase + gid + 8) * ldc + col] = make_float2(v2, v3);
        }
    }
}

// ---------------------------------------------------------------------------
// fp32 GEMM (R5) for the batched Km GEMM.
template <bool TRANSB, bool RELU>
__global__ __launch_bounds__(256, 2) void gemm_kernel(
    const float* __restrict__ A, const float* __restrict__ B,
    const float* __restrict__ bias, float* __restrict__ C,
    int M, int N, int K, int lda, int ldb, int ldc,
    long batchA, long batchB, long batchC)
{
    constexpr int BM = 128, BN = 64, BK = 16;
    __shared__ float As[2][BK][BM + 4];
    __shared__ float Bs[2][BK][BN + 4];

    long bz = blockIdx.z;
    A += bz * batchA; B += bz * batchB; C += bz * batchC;
    int m0 = blockIdx.x * BM, n0 = blockIdx.y * BN;
    int tid = threadIdx.x;
    int tx = tid & 15, ty = tid >> 4;

    int am[2], ac[2];
#pragma unroll
    for (int i = 0; i < 2; i++) {
        int idx = tid + i * 256;
        am[i] = idx & 127; ac[i] = idx >> 7;
    }
    int bk = tid >> 4, bn4 = tid & 15;
    int bn = tid & 63, bc2 = tid >> 6;

    u64 acc[4][4];
#pragma unroll
    for (int p = 0; p < 4; p++)
#pragma unroll
        for (int c = 0; c < 4; c++) acc[p][c] = 0ull;

    {
#pragma unroll
        for (int i = 0; i < 2; i++) {
            float4 v = *(const float4*)&A[(long)(m0 + am[i]) * lda + ac[i] * 4];
            As[0][ac[i] * 4 + 0][am[i]] = v.x;
            As[0][ac[i] * 4 + 1][am[i]] = v.y;
            As[0][ac[i] * 4 + 2][am[i]] = v.z;
            As[0][ac[i] * 4 + 3][am[i]] = v.w;
        }
        if (!TRANSB) {
            float4 b = *(const float4*)&B[(long)bk * ldb + n0 + bn4 * 4];
            *(float4*)&Bs[0][bk][bn4 * 4] = b;
        } else {
            float4 b = *(const float4*)&B[(long)(n0 + bn) * ldb + bc2 * 4];
            Bs[0][bc2 * 4 + 0][bn] = b.x;
            Bs[0][bc2 * 4 + 1][bn] = b.y;
            Bs[0][bc2 * 4 + 2][bn] = b.z;
            Bs[0][bc2 * 4 + 3][bn] = b.w;
        }
    }
    __syncthreads();

    int nk = K / BK;
    float4 ra[2], rb;
    for (int it = 0; it < nk; it++) {
        int buf = it & 1;
        bool has_next = (it + 1 < nk);
        if (has_next) {
            int k0 = (it + 1) * BK;
#pragma unroll
            for (int i = 0; i < 2; i++)
                ra[i] = *(const float4*)&A[(long)(m0 + am[i]) * lda + k0 + ac[i] * 4];
            if (!TRANSB)
                rb = *(const float4*)&B[(long)(k0 + bk) * ldb + n0 + bn4 * 4];
            else
                rb = *(const float4*)&B[(long)(n0 + bn) * ldb + k0 + bc2 * 4];
        }
        ulonglong2 a01c = *(const ulonglong2*)&As[buf][0][ty * 8];
        ulonglong2 a23c = *(const ulonglong2*)&As[buf][0][ty * 8 + 4];
        float4 bfc = *(const float4*)&Bs[buf][0][tx * 4];
#pragma unroll
        for (int k = 0; k < BK; k++) {
            ulonglong2 a01n, a23n; float4 bfn;
            if (k < BK - 1) {
                a01n = *(const ulonglong2*)&As[buf][k + 1][ty * 8];
                a23n = *(const ulonglong2*)&As[buf][k + 1][ty * 8 + 4];
                bfn = *(const float4*)&Bs[buf][k + 1][tx * 4];
            }
            u64 bd0, bd1, bd2, bd3;
            DUP2(bd0, bfc.x); DUP2(bd1, bfc.y); DUP2(bd2, bfc.z); DUP2(bd3, bfc.w);
            FMA2(acc[0][0], a01c.x, bd0); FMA2(acc[0][1], a01c.x, bd1);
            FMA2(acc[0][2], a01c.x, bd2); FMA2(acc[0][3], a01c.x, bd3);
            FMA2(acc[1][0], a01c.y, bd0); FMA2(acc[1][1], a01c.y, bd1);
            FMA2(acc[1][2], a01c.y, bd2); FMA2(acc[1][3], a01c.y, bd3);
            FMA2(acc[2][0], a23c.x, bd0); FMA2(acc[2][1], a23c.x, bd1);
            FMA2(acc[2][2], a23c.x, bd2); FMA2(acc[2][3], a23c.x, bd3);
            FMA2(acc[3][0], a23c.y, bd0); FMA2(acc[3][1], a23c.y, bd1);
            FMA2(acc[3][2], a23c.y, bd2); FMA2(acc[3][3], a23c.y, bd3);
            if (k < BK - 1) { a01c = a01n; a23c = a23n; bfc = bfn; }
        }
        if (has_next) {
            int nb = buf ^ 1;
#pragma unroll
            for (int i = 0; i < 2; i++) {
                As[nb][ac[i] * 4 + 0][am[i]] = ra[i].x;
                As[nb][ac[i] * 4 + 1][am[i]] = ra[i].y;
                As[nb][ac[i] * 4 + 2][am[i]] = ra[i].z;
                As[nb][ac[i] * 4 + 3][am[i]] = ra[i].w;
            }
            if (!TRANSB) {
                *(float4*)&Bs[nb][bk][bn4 * 4] = rb;
            } else {
                Bs[nb][bc2 * 4 + 0][bn] = rb.x;
                Bs[nb][bc2 * 4 + 1][bn] = rb.y;
                Bs[nb][bc2 * 4 + 2][bn] = rb.z;
                Bs[nb][bc2 * 4 + 3][bn] = rb.w;
            }
        }
        __syncthreads();
    }

    float4 bv = make_float4(0.f, 0.f, 0.f, 0.f);
    if (bias) bv = *(const float4*)&bias[n0 + tx * 4];
#pragma unroll
    for (int p = 0; p < 4; p++) {
        float r0[4], r1[4];
#pragma unroll
        for (int c = 0; c < 4; c++) UNPACK2(r0[c], r1[c], acc[p][c]);
        r0[0] += bv.x; r0[1] += bv.y; r0[2] += bv.z; r0[3] += bv.w;
        r1[0] += bv.x; r1[1] += bv.y; r1[2] += bv.z; r1[3] += bv.w;
        if (RELU) {
#pragma unroll
            for (int c = 0; c < 4; c++) {
                r0[c] = fmaxf(r0[c], 0.f);
                r1[c] = fmaxf(r1[c], 0.f);
            }
        }
        int m = m0 + ty * 8 + 2 * p;
        *(float4*)&C[(long)m * ldc + n0 + tx * 4] = *(float4*)r0;
        *(float4*)&C[(long)(m + 1) * ldc + n0 + tx * 4] = *(float4*)r1;
    }
}

// ---------------------------------------------------------------------------
// persistent GRU with tensor-core gh (bf16x3). 128 blocks (16 jt x 8 nt).
// W_hh frags in registers (preloaded once); h exchanged pre-split bf16 hi/lo.
// smem: A_HI 16K | A_LO 16K | GH 8K | HOWN 2K  (A region reused for W staging)
#define GRU_SMEM2 43008

__device__ __forceinline__ float sigmf(float x) { return 1.f / (1.f + __expf(-x)); }
__device__ __forceinline__ float tanhfast(float x) { return 2.f / (1.f + __expf(-2.f * x)) - 1.f; }

__global__ __launch_bounds__(256) void gru_tc(
    const float* __restrict__ GI, const float* __restrict__ h0,
    const float* __restrict__ W_hh, const float* __restrict__ b_hh,
    const __nv_bfloat16* __restrict__ HB0H, const __nv_bfloat16* __restrict__ HB0L,
    __nv_bfloat16* __restrict__ HBH, __nv_bfloat16* __restrict__ HBL,
    float* __restrict__ HD)
{
    extern __shared__ char sm8[];
    u32 sb = (u32)__cvta_generic_to_shared(sm8);
    float* ghs = (float*)(sm8 + 32768);      // [32][64] fp32
    float* hown = (float*)(sm8 + 40960);     // [32][16] fp32

    int tid = threadIdx.x;
    int wid = tid >> 5, lane = tid & 31;
    int jt = blockIdx.x & 15, nt = blockIdx.x >> 4;
    int j0 = jt * 16, n0 = nt * 32;

    unsigned* arr = &g_bar2[nt * 32];
    unsigned* ep  = &g_bar2[(8 + nt) * 32];

    // ---- W_hh fragment preload (two-phase through A region) ----
    u32 bhf[16][2], blf[16][2];
    {
        // phase 1: hi plane
        for (int i = 0; i < 12; i++) {
            int e = tid + i * 256;          // 0..3071
            int r = e >> 6, q = e & 63;     // r: W row (gate*16+jr), q: float4 k-chunk
            float4 v = *(const float4*)&W_hh[(long)((r >> 4) * 256 + j0 + (r & 15)) * 256 + q * 4];
            u32 h01, l01, h23, l23;
            cvt_split(v.x, v.y, h01, l01);
            cvt_split(v.z, v.w, h23, l23);
            *(uint2*)(sm8 + r * 512 + (((q >> 1) ^ (r & 7)) * 16) + (q & 1) * 8) =
                make_uint2(h01, h23);
        }
        __syncthreads();
        if (wid < 6) {
            int rb = wid * 8 + (lane & 7);
            int hb2 = (lane >> 3) & 1;
#pragma unroll
            for (int s = 0; s < 16; s++) {
                u32 addr = sb + rb * 512 + (((s * 2 + hb2) ^ (rb & 7)) * 16);
                ldsm_x2(bhf[s][0], bhf[s][1], addr);
            }
        }
        __syncthreads();
        // phase 2: lo plane
        for (int i = 0; i < 12; i++) {
            int e = tid + i * 256;
            int r = e >> 6, q = e & 63;
            float4 v = *(const float4*)&W_hh[(long)((r >> 4) * 256 + j0 + (r & 15)) * 256 + q * 4];
            u32 h01, l01, h23, l23;
            cvt_split(v.x, v.y, h01, l01);
            cvt_split(v.z, v.w, h23, l23);
            *(uint2*)(sm8 + r * 512 + (((q >> 1) ^ (r & 7)) * 16) + (q & 1) * 8) =
                make_uint2(l01, l23);
        }
        __syncthreads();
        if (wid < 6) {
            int rb = wid * 8 + (lane & 7);
            int hb2 = (lane >> 3) & 1;
#pragma unroll
            for (int s = 0; s < 16; s++) {
                u32 addr = sb + rb * 512 + (((s * 2 + hb2) ^ (rb & 7)) * 16);
                ldsm_x2(blf[s][0], blf[s][1], addr);
            }
        }
        __syncthreads();
    }

    // tail-thread mapping: pairs p = tid, tid+256; n = p>>4, jj = p&15
    int jj = tid & 15, nb0 = tid >> 4;
    float bhr = b_hh[j0 + jj], bhz = b_hh[256 + j0 + jj], bhn = b_hh[512 + j0 + jj];
#pragma unroll
    for (int i = 0; i < 2; i++) {
        int n = nb0 + 16 * i;
        hown[n * 16 + jj] = h0[(long)(n0 + n) * H_ + j0 + jj];
    }
    float gr[2], gz[2], gn[2];
#pragma unroll
    for (int i = 0; i < 2; i++) {
        long base = ((long)(n0 + nb0 + 16 * i)) * 768 + j0 + jj;
        gr[i] = GI[base]; gz[i] = GI[base + 256]; gn[i] = GI[base + 512];
    }
    __syncthreads();

    for (int t = 0; t < T_; t++) {
        // ---- stage h(t-1) bf16 hi/lo into smem ----
        const __nv_bfloat16* srcH = t ? HBH + (long)(t - 1) * N_ * H_ : HB0H;
        const __nv_bfloat16* srcL = t ? HBL + (long)(t - 1) * N_ * H_ : HB0L;
#pragma unroll
        for (int i = 0; i < 4; i++) {
            int e = tid + i * 256;
            int r = e >> 5, c = e & 31;
            u32 soff = r * 512 + ((c ^ (r & 7)) * 16);
            *(uint4*)(sm8 + soff) = *(const uint4*)(srcH + (long)(n0 + r) * 256 + c * 8);
            *(uint4*)(sm8 + 16384 + soff) = *(const uint4*)(srcL + (long)(n0 + r) * 256 + c * 8);
        }
        __syncthreads();

        // ---- mma: gh[32n][48col] (warps 0-5, n-tile = wid) ----
        if (wid < 6) {
            float acc[2][4];
#pragma unroll
            for (int mt = 0; mt < 2; mt++)
#pragma unroll
                for (int v = 0; v < 4; v++) acc[mt][v] = 0.f;
            int rowa = lane & 15, ha2 = lane >> 4;
#pragma unroll
            for (int s = 0; s < 16; s++) {
#pragma unroll
                for (int mt = 0; mt < 2; mt++) {
                    int rr = rowa + mt * 16;
                    u32 addr = sb + rr * 512 + (((s * 2 + ha2) ^ (rr & 7)) * 16);
                    u32 ah[4], al[4];
                    ldsm_x4(ah[0], ah[1], ah[2], ah[3], addr);
                    ldsm_x4(al[0], al[1], al[2], al[3], addr + 16384);
                    mma_bf16(acc[mt], ah, bhf[s]);
                    mma_bf16(acc[mt], ah, blf[s]);
                    mma_bf16(acc[mt], al, bhf[s]);
                }
            }
            int gid = lane >> 2, tg = lane & 3;
#pragma unroll
            for (int mt = 0; mt < 2; mt++) {
                *(float2*)&ghs[(mt * 16 + gid) * 64 + wid * 8 + tg * 2] =
                    make_float2(acc[mt][0], acc[mt][1]);
                *(float2*)&ghs[(mt * 16 + gid + 8) * 64 + wid * 8 + tg * 2] =
                    make_float2(acc[mt][2], acc[mt][3]);
            }
        }
        __syncthreads();

        // ---- elementwise tail: 2 (n,j) pairs per thread ----
        float* hdst = HD + (long)t * N_ * H_;
        __nv_bfloat16* bhd = HBH + (long)t * N_ * H_;
        __nv_bfloat16* bld = HBL + (long)t * N_ * H_;
#pragma unroll
        for (int i = 0; i < 2; i++) {
            int n = nb0 + 16 * i;
            float ghr = ghs[n * 64 + jj];
            float ghz = ghs[n * 64 + 16 + jj];
            float ghn = ghs[n * 64 + 32 + jj];
            float rg = sigmf(gr[i] + ghr + bhr);
            float z  = sigmf(gz[i] + ghz + bhz);
            float nv = tanhfast(gn[i] + rg * (ghn + bhn));
            float hp = hown[n * 16 + jj];
            float hn = (1.f - z) * nv + z * hp;
            hown[n * 16 + jj] = hn;
            long gofs = (long)(n0 + n) * H_ + j0 + jj;
            hdst[gofs] = hn;
            __nv_bfloat16 hh = __float2bfloat16(hn);
            bhd[gofs] = hh;
            bld[gofs] = __float2bfloat16(hn - __bfloat162float(hh));
        }

        if (t < T_ - 1) {
            __syncthreads();
            if (tid == 0) {
                unsigned prev;
                asm volatile("atom.release.gpu.global.add.u32 %0, [%1], %2;"
                             : "=r"(prev) : "l"(arr), "r"(1u) : "memory");
                if (prev == (unsigned)((t + 1) * 16 - 1)) {
                    asm volatile("st.release.gpu.global.u32 [%0], %1;"
                                 :: "l"(ep), "r"((unsigned)(t + 1)) : "memory");
                }
            }
            // prefetch gi(t+1) while waiting
#pragma unroll
            for (int i = 0; i < 2; i++) {
                long base = ((long)(t + 1) * N_ + n0 + nb0 + 16 * i) * 768 + j0 + jj;
                gr[i] = GI[base]; gz[i] = GI[base + 256]; gn[i] = GI[base + 512];
            }
            if (tid == 0) {
                unsigned e;
                do {
                    asm volatile("ld.acquire.gpu.global.u32 %0, [%1];"
                                 : "=r"(e) : "l"(ep) : "memory");
                } while (e < (unsigned)(t + 1));
            }
            __syncthreads();
        }
    }
}

// ---------------------------------------------------------------------------
__global__ __launch_bounds__(256) void epilogue_kernel(
    const float* __restrict__ WB, const float* __restrict__ CC,
    const int* __restrict__ actions, const float* __restrict__ Wc,
    const float* __restrict__ bc, const float* __restrict__ HD,
    float* __restrict__ out)
{
    int wid = threadIdx.x >> 5, lane = threadIdx.x & 31;
    long idx = (long)blockIdx.x * 8 + wid;
    int t = (int)(idx / N_), n = (int)(idx % N_);
    float cc = CC[idx];
    long base = idx * OUTW_;

    const float4* hrow = (const float4*)(HD + idx * 256);
    const float4* wc = (const float4*)Wc;
    float4 h0v = hrow[lane * 2], h1v = hrow[lane * 2 + 1];
    float4 c0 = wc[lane * 2], c1 = wc[lane * 2 + 1];
    float2* hdst = (float2*)(out + base + 2 + lane * 8);
    hdst[0] = make_float2(h0v.x, h0v.y);
    hdst[1] = make_float2(h0v.z, h0v.w);
    hdst[2] = make_float2(h1v.x, h1v.y);
    hdst[3] = make_float2(h1v.z, h1v.w);
    float d = h0v.x * c0.x + h0v.y * c0.y + h0v.z * c0.z + h0v.w * c0.w
            + h1v.x * c1.x + h1v.y * c1.y + h1v.z * c1.z + h1v.w * c1.w;
#pragma unroll
    for (int o = 16; o; o >>= 1) d += __shfl_xor_sync(~0u, d, o);

    const float4* wrow = (const float4*)(WB + ((long)n * T_ + t) * L_);
    float4 w0 = wrow[lane * 2], w1 = wrow[lane * 2 + 1];
    float wv[8] = {w0.x * cc, w0.y * cc, w0.z * cc, w0.w * cc,
                   w1.x * cc, w1.y * cc, w1.z * cc, w1.w * cc};
    float mx = wv[0];
#pragma unroll
    for (int i = 1; i < 8; i++) mx = fmaxf(mx, wv[i]);
#pragma unroll
    for (int o = 16; o; o >>= 1) mx = fmaxf(mx, __shfl_xor_sync(~0u, mx, o));
    float e[8], s = 0.f;
#pragma unroll
    for (int i = 0; i < 8; i++) { e[i] = expf(wv[i] - mx); s += e[i]; }
#pragma unroll
    for (int o = 16; o; o >>= 1) s += __shfl_xor_sync(~0u, s, o);
    float inv = 1.f / s;

    int a = actions[idx];
    float2* pdst = (float2*)(out + base + 258 + lane * 8);
    float2* odst = (float2*)(out + base + 514 + lane * 8);
#pragma unroll
    for (int i = 0; i < 4; i++) {
        pdst[i] = make_float2(e[2 * i] * inv, e[2 * i + 1] * inv);
        int l0 = lane * 8 + 2 * i;
        odst[i] = make_float2(l0 == a ? 1.f : 0.f, l0 + 1 == a ? 1.f : 0.f);
    }
    if (lane == 0) {
        out[base + 0] = (float)a;
        out[base + 1] = d + bc[0];
    }
}

// ---------------------------------------------------------------------------
extern "C" void kernel_launch(void* const* d_in, const int* in_sizes, int n_in,
                              void* d_out, int out_size)
{
    const float* cond = (const float*)d_in[0];
    const float* M    = (const float*)d_in[1];
    const float* Km   = (const float*)d_in[2];
    const float* Cm   = (const float*)d_in[3];
    const float* h0   = (const float*)d_in[4];
    const float* p0   = (const float*)d_in[5];
    const float* W0   = (const float*)d_in[6];
    const float* b0   = (const float*)d_in[7];
    const float* W1   = (const float*)d_in[8];
    const float* b1   = (const float*)d_in[9];
    const float* W2   = (const float*)d_in[10];
    const float* b2   = (const float*)d_in[11];
    const float* W_ih = (const float*)d_in[12];
    const float* W_hh = (const float*)d_in[13];
    const float* b_ih = (const float*)d_in[14];
    const float* b_hh = (const float*)d_in[15];
    const float* Wa   = (const float*)d_in[16];
    const float* ba   = (const float*)d_in[17];
    const float* Wc   = (const float*)d_in[18];
    const float* bc   = (const float*)d_in[19];
    const int* actions = (const int*)d_in[20];
    float* out = (float*)d_out;

    float* base = nullptr;
    cudaGetSymbolAddress((void**)&base, g_scratch);
    float* XIN = base + XIN_OFF;
    float* XA  = base + XA_OFF;
    float* XB  = base + XB_OFF;
    float* GI  = base + GI_OFF;
    float* KB  = base + KB_OFF;
    float* WB  = base + WB_OFF;
    float* CC  = base + CC_OFF;
    float* HD  = base + XIN_OFF;
    __nv_bfloat16* WT = (__nv_bfloat16*)(base + WT_OFF);
    __nv_bfloat16* HBH = (__nv_bfloat16*)(base + HBH_OFF);
    __nv_bfloat16* HBL = (__nv_bfloat16*)(base + HBL_OFF);
    __nv_bfloat16* HB0H = (__nv_bfloat16*)(base + HB0H_OFF);
    __nv_bfloat16* HB0L = (__nv_bfloat16*)(base + HB0L_OFF);

    void* bar_addr = nullptr;
    cudaGetSymbolAddress(&bar_addr, g_bar2);

    cudaFuncSetAttribute(gru_tc,
                         cudaFuncAttributeMaxDynamicSharedMemorySize, GRU_SMEM2);

    // phase 0: weight + h0 conversion
    convert_w<<<320, 256>>>(W0, WT + W0H, WT + W0L, 320, 256, 1);
    convert_w<<<256, 256>>>(W1, WT + W1H, WT + W1L, 256, 256, 1);
    convert_w<<<256, 256>>>(W2, WT + W2H, WT + W2L, 256, 256, 1);
    convert_w<<<768, 256>>>(W_ih, WT + WIHH, WT + WIHL, 256, 768, 0);
    convert_w<<<256, 256>>>(Wa, WT + WAH, WT + WAL, 256, 256, 1);
    convert_h0<<<256, 256>>>(h0, HB0H, HB0L);

    // phase A
    t0_kernel<<<N_, 256>>>(p0, M, Cm, XIN, CC);
    gather_kernel<<<ROWS_ / 8, 256>>>(cond, M, Cm, actions, XIN, CC);
    gemm_bf16<true><<<dim3(ROWS_ / 128, 2), 256, BGEMM_SMEM>>>(
        XIN, WT + W0H, WT + W0L, b0, XA, ROWS_, 256, 320, 320, 256);
    gemm_bf16<true><<<dim3(ROWS_ / 128, 2), 256, BGEMM_SMEM>>>(
        XA, WT + W1H, WT + W1L, b1, XB, ROWS_, 256, 256, 256, 256);
    gemm_bf16<true><<<dim3(ROWS_ / 128, 2), 256, BGEMM_SMEM>>>(
        XB, WT + W2H, WT + W2L, b2, XA, ROWS_, 256, 256, 256, 256);
    gemm_bf16<false><<<dim3(ROWS_ / 128, 6), 256, BGEMM_SMEM>>>(
        XA, WT + WIHH, WT + WIHL, b_ih, GI, ROWS_, 768, 256, 256, 768);

    // phase B: persistent tensor-core GRU
    cudaMemsetAsync(bar_addr, 0, 16 * 32 * sizeof(unsigned));
    gru_tc<<<128, 256, GRU_SMEM2>>>(GI, h0, W_hh, b_hh, HB0H, HB0L, HBH, HBL, HD);

    // phase C
    gemm_bf16<false><<<dim3(ROWS_ / 128, 2), 256, BGEMM_SMEM>>>(
        HD, WT + WAH, WT + WAL, ba, KB, ROWS_, 256, 256, 256, 256);
    gemm_kernel<true, false><<<dim3(1, 4, N_), 256>>>(
        KB, Km, nullptr, WB, T_, 256, 256, N_ * 256, 256, 256,
        256L, (long)L_ * H_, (long)T_ * L_);
    epilogue_kernel<<<ROWS_ / 8, 256>>>(WB, CC, actions, Wc, bc, HD, out);
}

// round 10
// speedup vs baseline: 2.4221x; 1.1276x over previous
#include <cuda_runtime.h>
#include <cuda_bf16.h>
#include <math.h>

#define T_ 128
#define N_ 256
#define L_ 256
#define H_ 256
#define COND_ 64
#define ROWS_ (T_ * N_)   // 32768
#define OUTW_ 770

typedef unsigned long long u64;
typedef unsigned u32;

// ---------------- scratch (float units) --------------------------------------
#define XIN_OFF 0L
#define XA_OFF  (XIN_OFF + (long)ROWS_ * 320)
#define XB_OFF  (XA_OFF  + (long)ROWS_ * 256)
#define GI_OFF  (XB_OFF  + (long)ROWS_ * 256)
#define KB_OFF  (GI_OFF  + (long)ROWS_ * 768)
#define WB_OFF  (KB_OFF  + (long)ROWS_ * 256)
#define CC_OFF  (WB_OFF  + (long)ROWS_ * 256)
#define WT_OFF  (CC_OFF + (long)ROWS_)
#define WT_FLOATS 475136L
#define HBH_OFF (WT_OFF + WT_FLOATS)
#define HBL_OFF (HBH_OFF + 4194304L)
#define HB0H_OFF (HBL_OFF + 4194304L)
#define HB0L_OFF (HB0H_OFF + 32768L)
#define KMH_OFF (HB0L_OFF + 32768L)
#define KML_OFF (KMH_OFF + 8388608L)
#define SCRATCH_FLOATS (KML_OFF + 8388608L)

__device__ float g_scratch[SCRATCH_FLOATS];
__device__ unsigned g_bar2[8 * 32];   // per-nt arrive counters (monotonic)

// bf16 weight-buffer offsets (bf16 element units inside WT)
#define W0H 0
#define W0L 81920
#define W1H 163840
#define W1L 229376
#define W2H 294912
#define W2L 360448
#define WIHH 425984
#define WIHL 622592
#define WAH 819200
#define WAL 884736

// ---------------- bf16 helpers ------------------------------------------------
__device__ __forceinline__ void cvt_split(float x0, float x1, u32& h, u32& l) {
    u32 hh;
    asm("cvt.rn.bf16x2.f32 %0, %1, %2;" : "=r"(hh) : "f"(x1), "f"(x0));
    float r0 = x0 - __uint_as_float(hh << 16);
    float r1 = x1 - __uint_as_float(hh & 0xFFFF0000u);
    u32 ll;
    asm("cvt.rn.bf16x2.f32 %0, %1, %2;" : "=r"(ll) : "f"(r1), "f"(r0));
    h = hh; l = ll;
}
__device__ __forceinline__ void ldsm_x4(u32& r0, u32& r1, u32& r2, u32& r3, u32 a) {
    asm volatile("ldmatrix.sync.aligned.m8n8.x4.shared.b16 {%0,%1,%2,%3}, [%4];"
                 : "=r"(r0), "=r"(r1), "=r"(r2), "=r"(r3) : "r"(a));
}
__device__ __forceinline__ void ldsm_x2(u32& r0, u32& r1, u32 a) {
    asm volatile("ldmatrix.sync.aligned.m8n8.x2.shared.b16 {%0,%1}, [%2];"
                 : "=r"(r0), "=r"(r1) : "r"(a));
}
__device__ __forceinline__ void mma_bf16(float* d, const u32* a, const u32* b) {
    asm volatile(
        "mma.sync.aligned.m16n8k16.row.col.f32.bf16.bf16.f32 "
        "{%0,%1,%2,%3}, {%4,%5,%6,%7}, {%8,%9}, {%0,%1,%2,%3};"
        : "+f"(d[0]), "+f"(d[1]), "+f"(d[2]), "+f"(d[3])
        : "r"(a[0]), "r"(a[1]), "r"(a[2]), "r"(a[3]), "r"(b[0]), "r"(b[1]));
}

// ---------------------------------------------------------------------------
// fused weight/h0 conversion (one launch)
__global__ __launch_bounds__(256) void convert_wall(
    const float* __restrict__ W0, const float* __restrict__ W1,
    const float* __restrict__ W2, const float* __restrict__ W_ih,
    const float* __restrict__ Wa, const float* __restrict__ h0,
    __nv_bfloat16* __restrict__ WT,
    __nv_bfloat16* __restrict__ HB0H, __nv_bfloat16* __restrict__ HB0L)
{
    int b = blockIdx.x, tid = threadIdx.x;
    const float* src; __nv_bfloat16 *dh, *dl;
    int K, Nn, tr, e;
    if (b < 320)        { src = W0;   dh = WT + W0H;  dl = WT + W0L;  K = 320; Nn = 256; tr = 1; e = b * 256 + tid; }
    else if (b < 576)   { src = W1;   dh = WT + W1H;  dl = WT + W1L;  K = 256; Nn = 256; tr = 1; e = (b - 320) * 256 + tid; }
    else if (b < 832)   { src = W2;   dh = WT + W2H;  dl = WT + W2L;  K = 256; Nn = 256; tr = 1; e = (b - 576) * 256 + tid; }
    else if (b < 1600)  { src = W_ih; dh = WT + WIHH; dl = WT + WIHL; K = 256; Nn = 768; tr = 0; e = (b - 832) * 256 + tid; }
    else if (b < 1856)  { src = Wa;   dh = WT + WAH;  dl = WT + WAL;  K = 256; Nn = 256; tr = 1; e = (b - 1600) * 256 + tid; }
    else                { src = h0;   dh = HB0H;      dl = HB0L;      K = 256; Nn = 256; tr = 0; e = (b - 1856) * 256 + tid; }
    int n = e / K, k = e % K;
    float v = tr ? src[(long)k * Nn + n] : src[e];
    __nv_bfloat16 h = __float2bfloat16(v);
    dh[e] = h;
    dl[e] = __float2bfloat16(v - __bfloat162float(h));
}

// vectorized Km split: 4.19M float4s
__global__ __launch_bounds__(256) void convert_km(
    const float* __restrict__ Km, __nv_bfloat16* __restrict__ KMH,
    __nv_bfloat16* __restrict__ KML)
{
    long i = (long)blockIdx.x * 256 + threadIdx.x;
    float4 v = ((const float4*)Km)[i];
    u32 h01, l01, h23, l23;
    cvt_split(v.x, v.y, h01, l01);
    cvt_split(v.z, v.w, h23, l23);
    ((uint2*)KMH)[i] = make_uint2(h01, h23);
    ((uint2*)KML)[i] = make_uint2(l01, l23);
}

// ---------------------------------------------------------------------------
__global__ __launch_bounds__(256) void t0_kernel(
    const float* __restrict__ p0, const float* __restrict__ M,
    const float* __restrict__ C, float* __restrict__ XIN, float* __restrict__ CC)
{
    int n = blockIdx.x;
    int tid = threadIdx.x;
    float v = p0[(long)n * L_ + tid];
    int any = __syncthreads_or(v != 0.f);
    if (!any) {
        XIN[(long)n * 320 + 64 + tid] = M[(long)n * L_ * H_ + tid];
        if (tid == 0) CC[n] = C[(long)n * L_];
        return;
    }
    __shared__ float red[256];
    __shared__ float ps[256];
    ps[tid] = v;
    __syncthreads();
    float acc = 0.f;
    const float* Mn = M + (long)n * L_ * H_;
    for (int l = 0; l < L_; l++)
        acc = fmaf(ps[l], Mn[(long)l * H_ + tid], acc);
    XIN[(long)n * 320 + 64 + tid] = acc;
    red[tid] = ps[tid] * C[(long)n * L_ + tid];
    __syncthreads();
    for (int s = 128; s > 0; s >>= 1) {
        if (tid < s) red[tid] += red[tid + s];
        __syncthreads();
    }
    if (tid == 0) CC[n] = red[0];
}

// ---------------------------------------------------------------------------
__global__ __launch_bounds__(256) void gather_kernel(
    const float* __restrict__ cond, const float* __restrict__ M,
    const float* __restrict__ C, const int* __restrict__ actions,
    float* __restrict__ XIN, float* __restrict__ CC)
{
    int r = threadIdx.x >> 5, lane = threadIdx.x & 31;
    long idx = (long)blockIdx.x * 8 + r;
    int t = (int)(idx / N_), n = (int)(idx % N_);
    float4* dst = (float4*)(XIN + idx * 320);
    const float4* csrc = (const float4*)(cond + idx * COND_);
    if (lane < 16) dst[lane] = csrc[lane];
    if (t > 0) {
        int a = actions[idx - N_];
        const float4* msrc = (const float4*)(M + ((long)n * L_ + a) * H_);
#pragma unroll
        for (int i = 0; i < 2; i++) dst[16 + lane + i * 32] = msrc[lane + i * 32];
        if (lane == 0) CC[idx] = C[(long)n * L_ + a];
    }
}

// ---------------------------------------------------------------------------
// bf16x3 tensor-core GEMM. Tile 128x128, BK=32, 8 warps.
// PRE=true: A given pre-split (Ah/Al, [m][k] bf16, lda elems). Else A fp32.
// Batched via blockIdx.z strides (elements/floats respectively).
#define BGEMM_SMEM 32768

template <bool RELU, bool PRE>
__global__ __launch_bounds__(256) void gemm_bf16(
    const float* __restrict__ A,
    const __nv_bfloat16* __restrict__ Ah, const __nv_bfloat16* __restrict__ Al,
    const __nv_bfloat16* __restrict__ Bh, const __nv_bfloat16* __restrict__ Bl,
    const float* __restrict__ bias, float* __restrict__ C,
    int K, int lda, int ldc, long batchA, long batchB, long batchC)
{
    extern __shared__ char smx[];
    u32 sb32 = (u32)__cvta_generic_to_shared(smx);

    long bz = blockIdx.z;
    if (!PRE) A += bz * batchA; else { Ah += bz * batchA; Al += bz * batchA; }
    Bh += bz * batchB; Bl += bz * batchB; C += bz * batchC;

    int m0 = blockIdx.x * 128, n0 = blockIdx.y * 128;
    int tid = threadIdx.x;
    int wid = tid >> 5, lane = tid & 31;
    int warp_m = wid & 1, warp_n = wid >> 1;
    int gid = lane >> 2, tg = lane & 3;

    int am[4], aq[4], an2[2], ac2[2], bn_[2], bc_[2];
#pragma unroll
    for (int j = 0; j < 4; j++) {
        int idx = tid + j * 256;
        am[j] = idx >> 3; aq[j] = idx & 7;
    }
#pragma unroll
    for (int j = 0; j < 2; j++) {
        int idx = tid + j * 256;
        an2[j] = idx >> 2; ac2[j] = idx & 3;          // PRE A: (m, chunk8)
        bn_[j] = idx >> 2; bc_[j] = idx & 3;
    }

    int rowa = warp_m * 64 + (lane & 15);
    int rsa = (rowa >> 1) & 3;
    int ha = lane >> 4;
    int rowb = warp_n * 32 + (lane & 7);
    int rsb = (rowb >> 1) & 3;
    int hb = (lane >> 3) & 1;

    float acc[4][4][4];
#pragma unroll
    for (int i = 0; i < 4; i++)
#pragma unroll
        for (int j = 0; j < 4; j++)
#pragma unroll
            for (int v = 0; v < 4; v++) acc[i][j][v] = 0.f;

    auto store_a_f32 = [&](int m, int q, float4 v) {
        u32 h01, l01, h23, l23;
        cvt_split(v.x, v.y, h01, l01);
        cvt_split(v.z, v.w, h23, l23);
        char* p = smx + m * 64 + (((q >> 1) ^ ((m >> 1) & 3)) * 16) + (q & 1) * 8;
        *(uint2*)p = make_uint2(h01, h23);
        *(uint2*)(p + 8192) = make_uint2(l01, l23);
    };
    auto store_a_pre = [&](int m, int c, uint4 h, uint4 l) {
        char* p = smx + m * 64 + ((c ^ ((m >> 1) & 3)) * 16);
        *(uint4*)p = h;
        *(uint4*)(p + 8192) = l;
    };
    auto store_b = [&](int n, int c, uint4 h, uint4 l) {
        char* p = smx + 16384 + n * 64 + ((c ^ ((n >> 1) & 3)) * 16);
        *(uint4*)p = h;
        *(uint4*)(p + 8192) = l;
    };

    // prologue stage
    if (!PRE) {
#pragma unroll
        for (int j = 0; j < 4; j++) {
            float4 v = *(const float4*)&A[(long)(m0 + am[j]) * lda + aq[j] * 4];
            store_a_f32(am[j], aq[j], v);
        }
    } else {
#pragma unroll
        for (int j = 0; j < 2; j++) {
            long off = (long)(m0 + an2[j]) * lda + ac2[j] * 8;
            store_a_pre(an2[j], ac2[j], *(const uint4*)(Ah + off), *(const uint4*)(Al + off));
        }
    }
#pragma unroll
    for (int j = 0; j < 2; j++) {
        long off = (long)(n0 + bn_[j]) * K + bc_[j] * 8;
        store_b(bn_[j], bc_[j], *(const uint4*)(Bh + off), *(const uint4*)(Bl + off));
    }
    __syncthreads();

    int nk = K / 32;
    for (int kt = 0; kt < nk; kt++) {
        float4 ra[4];
        uint4 rah[2], ral[2], rbh[2], rbl[2];
        bool nxt = (kt + 1 < nk);
        if (nxt) {
            int k0 = (kt + 1) * 32;
            if (!PRE) {
#pragma unroll
                for (int j = 0; j < 4; j++)
                    ra[j] = *(const float4*)&A[(long)(m0 + am[j]) * lda + k0 + aq[j] * 4];
            } else {
#pragma unroll
                for (int j = 0; j < 2; j++) {
                    long off = (long)(m0 + an2[j]) * lda + k0 + ac2[j] * 8;
                    rah[j] = *(const uint4*)(Ah + off);
                    ral[j] = *(const uint4*)(Al + off);
                }
            }
#pragma unroll
            for (int j = 0; j < 2; j++) {
                long off = (long)(n0 + bn_[j]) * K + k0 + bc_[j] * 8;
                rbh[j] = *(const uint4*)(Bh + off);
                rbl[j] = *(const uint4*)(Bl + off);
            }
        }

#pragma unroll
        for (int ks = 0; ks < 2; ks++) {
            u32 bhf[4][2], blf[4][2];
#pragma unroll
            for (int ni = 0; ni < 4; ni++) {
                int cb = (ks * 2 + hb) ^ rsb;
                u32 addr = sb32 + 16384 + (rowb + ni * 8) * 64 + cb * 16;
                ldsm_x2(bhf[ni][0], bhf[ni][1], addr);
                ldsm_x2(blf[ni][0], blf[ni][1], addr + 8192);
            }
#pragma unroll
            for (int mi = 0; mi < 4; mi++) {
                int ca = (ks * 2 + ha) ^ rsa;
                u32 addr = sb32 + (rowa + mi * 16) * 64 + ca * 16;
                u32 ah[4], al[4];
                ldsm_x4(ah[0], ah[1], ah[2], ah[3], addr);
                ldsm_x4(al[0], al[1], al[2], al[3], addr + 8192);
#pragma unroll
                for (int ni = 0; ni < 4; ni++) {
                    mma_bf16(acc[mi][ni], ah, bhf[ni]);
                    mma_bf16(acc[mi][ni], ah, blf[ni]);
                    mma_bf16(acc[mi][ni], al, bhf[ni]);
                }
            }
        }
        __syncthreads();
        if (nxt) {
            if (!PRE) {
#pragma unroll
                for (int j = 0; j < 4; j++) store_a_f32(am[j], aq[j], ra[j]);
            } else {
#pragma unroll
                for (int j = 0; j < 2; j++) store_a_pre(an2[j], ac2[j], rah[j], ral[j]);
            }
#pragma unroll
            for (int j = 0; j < 2; j++) store_b(bn_[j], bc_[j], rbh[j], rbl[j]);
        }
        __syncthreads();
    }

#pragma unroll
    for (int mi = 0; mi < 4; mi++) {
        int mbase = m0 + warp_m * 64 + mi * 16;
#pragma unroll
        for (int ni = 0; ni < 4; ni++) {
            int col = n0 + warp_n * 32 + ni * 8 + tg * 2;
            float b0 = 0.f, b1 = 0.f;
            if (bias) { b0 = bias[col]; b1 = bias[col + 1]; }
            float v0 = acc[mi][ni][0] + b0, v1 = acc[mi][ni][1] + b1;
            float v2 = acc[mi][ni][2] + b0, v3 = acc[mi][ni][3] + b1;
            if (RELU) {
                v0 = fmaxf(v0, 0.f); v1 = fmaxf(v1, 0.f);
                v2 = fmaxf(v2, 0.f); v3 = fmaxf(v3, 0.f);
            }
            *(float2*)&C[(long)(mbase + gid) * ldc + col] = make_float2(v0, v1);
            *(float2*)&C[(long)(mbase + gid + 8) * ldc + col] = make_float2(v2, v3);
        }
    }
}

// ---------------------------------------------------------------------------
// persistent GRU, tensor-core gh (bf16x3), one-hop group barrier.
#define GRU_SMEM2 43008

__device__ __forceinline__ float sigmf(float x) { return 1.f / (1.f + __expf(-x)); }
__device__ __forceinline__ float tanhfast(float x) { return 2.f / (1.f + __expf(-2.f * x)) - 1.f; }

__global__ __launch_bounds__(256) void gru_tc(
    const float* __restrict__ GI, const float* __restrict__ h0,
    const float* __restrict__ W_hh, const float* __restrict__ b_hh,
    const __nv_bfloat16* __restrict__ HB0H, const __nv_bfloat16* __restrict__ HB0L,
    __nv_bfloat16* __restrict__ HBH, __nv_bfloat16* __restrict__ HBL)
{
    extern __shared__ char sm8[];
    u32 sb = (u32)__cvta_generic_to_shared(sm8);
    float* ghs = (float*)(sm8 + 32768);      // [32][64] fp32
    float* hown = (float*)(sm8 + 40960);     // [32][16] fp32

    int tid = threadIdx.x;
    int wid = tid >> 5, lane = tid & 31;
    int jt = blockIdx.x & 15, nt = blockIdx.x >> 4;
    int j0 = jt * 16, n0 = nt * 32;

    unsigned* arr = &g_bar2[nt * 32];

    // ---- W_hh fragment preload (two-phase through A region) ----
    u32 bhf[16][2], blf[16][2];
    {
        for (int i = 0; i < 12; i++) {
            int e = tid + i * 256;
            int r = e >> 6, q = e & 63;
            float4 v = *(const float4*)&W_hh[(long)((r >> 4) * 256 + j0 + (r & 15)) * 256 + q * 4];
            u32 h01, l01, h23, l23;
            cvt_split(v.x, v.y, h01, l01);
            cvt_split(v.z, v.w, h23, l23);
            *(uint2*)(sm8 + r * 512 + (((q >> 1) ^ (r & 7)) * 16) + (q & 1) * 8) =
                make_uint2(h01, h23);
        }
        __syncthreads();
        if (wid < 6) {
            int rb = wid * 8 + (lane & 7);
            int hb2 = (lane >> 3) & 1;
#pragma unroll
            for (int s = 0; s < 16; s++) {
                u32 addr = sb + rb * 512 + (((s * 2 + hb2) ^ (rb & 7)) * 16);
                ldsm_x2(bhf[s][0], bhf[s][1], addr);
            }
        }
        __syncthreads();
        for (int i = 0; i < 12; i++) {
            int e = tid + i * 256;
            int r = e >> 6, q = e & 63;
            float4 v = *(const float4*)&W_hh[(long)((r >> 4) * 256 + j0 + (r & 15)) * 256 + q * 4];
            u32 h01, l01, h23, l23;
            cvt_split(v.x, v.y, h01, l01);
            cvt_split(v.z, v.w, h23, l23);
            *(uint2*)(sm8 + r * 512 + (((q >> 1) ^ (r & 7)) * 16) + (q & 1) * 8) =
                make_uint2(l01, l23);
        }
        __syncthreads();
        if (wid < 6) {
            int rb = wid * 8 + (lane & 7);
            int hb2 = (lane >> 3) & 1;
#pragma unroll
            for (int s = 0; s < 16; s++) {
                u32 addr = sb + rb * 512 + (((s * 2 + hb2) ^ (rb & 7)) * 16);
                ldsm_x2(blf[s][0], blf[s][1], addr);
            }
        }
        __syncthreads();
    }

    int jj = tid & 15, nb0 = tid >> 4;
    float bhr = b_hh[j0 + jj], bhz = b_hh[256 + j0 + jj], bhn = b_hh[512 + j0 + jj];
#pragma unroll
    for (int i = 0; i < 2; i++) {
        int n = nb0 + 16 * i;
        hown[n * 16 + jj] = h0[(long)(n0 + n) * H_ + j0 + jj];
    }
    float gr[2], gz[2], gn[2];
#pragma unroll
    for (int i = 0; i < 2; i++) {
        long base = ((long)(n0 + nb0 + 16 * i)) * 768 + j0 + jj;
        gr[i] = GI[base]; gz[i] = GI[base + 256]; gn[i] = GI[base + 512];
    }
    __syncthreads();

    for (int t = 0; t < T_; t++) {
        // ---- stage h(t-1) bf16 hi/lo into smem ----
        const __nv_bfloat16* srcH = t ? HBH + (long)(t - 1) * N_ * H_ : HB0H;
        const __nv_bfloat16* srcL = t ? HBL + (long)(t - 1) * N_ * H_ : HB0L;
#pragma unroll
        for (int i = 0; i < 4; i++) {
            int e = tid + i * 256;
            int r = e >> 5, c = e & 31;
            u32 soff = r * 512 + ((c ^ (r & 7)) * 16);
            *(uint4*)(sm8 + soff) = *(const uint4*)(srcH + (long)(n0 + r) * 256 + c * 8);
            *(uint4*)(sm8 + 16384 + soff) = *(const uint4*)(srcL + (long)(n0 + r) * 256 + c * 8);
        }
        __syncthreads();

        // ---- mma: gh[32n][48col] (warps 0-5) ----
        if (wid < 6) {
            float acc[2][4];
#pragma unroll
            for (int mt = 0; mt < 2; mt++)
#pragma unroll
                for (int v = 0; v < 4; v++) acc[mt][v] = 0.f;
            int rowa = lane & 15, ha2 = lane >> 4;
#pragma unroll
            for (int s = 0; s < 16; s++) {
#pragma unroll
                for (int mt = 0; mt < 2; mt++) {
                    int rr = rowa + mt * 16;
                    u32 addr = sb + rr * 512 + (((s * 2 + ha2) ^ (rr & 7)) * 16);
                    u32 ah[4], al[4];
                    ldsm_x4(ah[0], ah[1], ah[2], ah[3], addr);
                    ldsm_x4(al[0], al[1], al[2], al[3], addr + 16384);
                    mma_bf16(acc[mt], ah, bhf[s]);
                    mma_bf16(acc[mt], ah, blf[s]);
                    mma_bf16(acc[mt], al, bhf[s]);
                }
            }
            int gid = lane >> 2, tg = lane & 3;
#pragma unroll
            for (int mt = 0; mt < 2; mt++) {
                *(float2*)&ghs[(mt * 16 + gid) * 64 + wid * 8 + tg * 2] =
                    make_float2(acc[mt][0], acc[mt][1]);
                *(float2*)&ghs[(mt * 16 + gid + 8) * 64 + wid * 8 + tg * 2] =
                    make_float2(acc[mt][2], acc[mt][3]);
            }
        }
        __syncthreads();

        // ---- elementwise tail ----
        __nv_bfloat16* bhd = HBH + (long)t * N_ * H_;
        __nv_bfloat16* bld = HBL + (long)t * N_ * H_;
#pragma unroll
        for (int i = 0; i < 2; i++) {
            int n = nb0 + 16 * i;
            float ghr = ghs[n * 64 + jj];
            float ghz = ghs[n * 64 + 16 + jj];
            float ghn = ghs[n * 64 + 32 + jj];
            float rg = sigmf(gr[i] + ghr + bhr);
            float z  = sigmf(gz[i] + ghz + bhz);
            float nv = tanhfast(gn[i] + rg * (ghn + bhn));
            float hp = hown[n * 16 + jj];
            float hn = (1.f - z) * nv + z * hp;
            hown[n * 16 + jj] = hn;
            long gofs = (long)(n0 + n) * H_ + j0 + jj;
            __nv_bfloat16 hh = __float2bfloat16(hn);
            bhd[gofs] = hh;
            bld[gofs] = __float2bfloat16(hn - __bfloat162float(hh));
        }

        if (t < T_ - 1) {
            __syncthreads();
            if (tid == 0) {
                asm volatile("red.release.gpu.global.add.u32 [%0], %1;"
                             :: "l"(arr), "r"(1u) : "memory");
            }
            // prefetch gi(t+1) while waiting
#pragma unroll
            for (int i = 0; i < 2; i++) {
                long base = ((long)(t + 1) * N_ + n0 + nb0 + 16 * i) * 768 + j0 + jj;
                gr[i] = GI[base]; gz[i] = GI[base + 256]; gn[i] = GI[base + 512];
            }
            if (tid == 0) {
                unsigned target = (unsigned)(t + 1) * 16u;
                unsigned e;
                do {
                    asm volatile("ld.acquire.gpu.global.u32 %0, [%1];"
                                 : "=r"(e) : "l"(arr) : "memory");
                } while (e < target);
            }
            __syncthreads();
        }
    }
}

// ---------------------------------------------------------------------------
// warp-per-(t,n): h reconstruct (hi+lo) + copy, softmax, one-hot, value.
__global__ __launch_bounds__(256) void epilogue_kernel(
    const float* __restrict__ WB, const float* __restrict__ CC,
    const int* __restrict__ actions, const float* __restrict__ Wc,
    const float* __restrict__ bc,
    const __nv_bfloat16* __restrict__ HBH, const __nv_bfloat16* __restrict__ HBL,
    float* __restrict__ out)
{
    int wid = threadIdx.x >> 5, lane = threadIdx.x & 31;
    long idx = (long)blockIdx.x * 8 + wid;
    int t = (int)(idx / N_), n = (int)(idx % N_);
    float cc = CC[idx];
    long base = idx * OUTW_;

    // reconstruct 8 h values
    const __nv_bfloat162* hv = (const __nv_bfloat162*)(HBH + idx * 256 + lane * 8);
    const __nv_bfloat162* lv = (const __nv_bfloat162*)(HBL + idx * 256 + lane * 8);
    float h[8];
#pragma unroll
    for (int i = 0; i < 4; i++) {
        float2 fh = __bfloat1622float2(hv[i]);
        float2 fl = __bfloat1622float2(lv[i]);
        h[2 * i] = fh.x + fl.x;
        h[2 * i + 1] = fh.y + fl.y;
    }
    float2* hdst = (float2*)(out + base + 2 + lane * 8);
#pragma unroll
    for (int i = 0; i < 4; i++) hdst[i] = make_float2(h[2 * i], h[2 * i + 1]);

    const float4* wc = (const float4*)Wc;
    float4 c0 = wc[lane * 2], c1 = wc[lane * 2 + 1];
    float d = h[0] * c0.x + h[1] * c0.y + h[2] * c0.z + h[3] * c0.w
            + h[4] * c1.x + h[5] * c1.y + h[6] * c1.z + h[7] * c1.w;
#pragma unroll
    for (int o = 16; o; o >>= 1) d += __shfl_xor_sync(~0u, d, o);

    const float4* wrow = (const float4*)(WB + ((long)n * T_ + t) * L_);
    float4 w0 = wrow[lane * 2], w1 = wrow[lane * 2 + 1];
    float wv[8] = {w0.x * cc, w0.y * cc, w0.z * cc, w0.w * cc,
                   w1.x * cc, w1.y * cc, w1.z * cc, w1.w * cc};
    float mx = wv[0];
#pragma unroll
    for (int i = 1; i < 8; i++) mx = fmaxf(mx, wv[i]);
#pragma unroll
    for (int o = 16; o; o >>= 1) mx = fmaxf(mx, __shfl_xor_sync(~0u, mx, o));
    float e[8], s = 0.f;
#pragma unroll
    for (int i = 0; i < 8; i++) { e[i] = expf(wv[i] - mx); s += e[i]; }
#pragma unroll
    for (int o = 16; o; o >>= 1) s += __shfl_xor_sync(~0u, s, o);
    float inv = 1.f / s;

    int a = actions[idx];
    float2* pdst = (float2*)(out + base + 258 + lane * 8);
    float2* odst = (float2*)(out + base + 514 + lane * 8);
#pragma unroll
    for (int i = 0; i < 4; i++) {
        pdst[i] = make_float2(e[2 * i] * inv, e[2 * i + 1] * inv);
        int l0 = lane * 8 + 2 * i;
        odst[i] = make_float2(l0 == a ? 1.f : 0.f, l0 + 1 == a ? 1.f : 0.f);
    }
    if (lane == 0) {
        out[base + 0] = (float)a;
        out[base + 1] = d + bc[0];
    }
}

// ---------------------------------------------------------------------------
extern "C" void kernel_launch(void* const* d_in, const int* in_sizes, int n_in,
                              void* d_out, int out_size)
{
    const float* cond = (const float*)d_in[0];
    const float* M    = (const float*)d_in[1];
    const float* Km   = (const float*)d_in[2];
    const float* Cm   = (const float*)d_in[3];
    const float* h0   = (const float*)d_in[4];
    const float* p0   = (const float*)d_in[5];
    const float* W0   = (const float*)d_in[6];
    const float* b0   = (const float*)d_in[7];
    const float* W1   = (const float*)d_in[8];
    const float* b1   = (const float*)d_in[9];
    const float* W2   = (const float*)d_in[10];
    const float* b2   = (const float*)d_in[11];
    const float* W_ih = (const float*)d_in[12];
    const float* W_hh = (const float*)d_in[13];
    const float* b_ih = (const float*)d_in[14];
    const float* b_hh = (const float*)d_in[15];
    const float* Wa   = (const float*)d_in[16];
    const float* ba   = (const float*)d_in[17];
    const float* Wc   = (const float*)d_in[18];
    const float* bc   = (const float*)d_in[19];
    const int* actions = (const int*)d_in[20];
    float* out = (float*)d_out;

    float* base = nullptr;
    cudaGetSymbolAddress((void**)&base, g_scratch);
    float* XIN = base + XIN_OFF;
    float* XA  = base + XA_OFF;
    float* XB  = base + XB_OFF;
    float* GI  = base + GI_OFF;
    float* KB  = base + KB_OFF;
    float* WB  = base + WB_OFF;
    float* CC  = base + CC_OFF;
    __nv_bfloat16* WT = (__nv_bfloat16*)(base + WT_OFF);
    __nv_bfloat16* HBH = (__nv_bfloat16*)(base + HBH_OFF);
    __nv_bfloat16* HBL = (__nv_bfloat16*)(base + HBL_OFF);
    __nv_bfloat16* HB0H = (__nv_bfloat16*)(base + HB0H_OFF);
    __nv_bfloat16* HB0L = (__nv_bfloat16*)(base + HB0L_OFF);
    __nv_bfloat16* KMH = (__nv_bfloat16*)(base + KMH_OFF);
    __nv_bfloat16* KML = (__nv_bfloat16*)(base + KML_OFF);

    void* bar_addr = nullptr;
    cudaGetSymbolAddress(&bar_addr, g_bar2);

    cudaFuncSetAttribute(gru_tc,
                         cudaFuncAttributeMaxDynamicSharedMemorySize, GRU_SMEM2);

    // phase 0: conversions (2 launches)
    convert_wall<<<2112, 256>>>(W0, W1, W2, W_ih, Wa, h0, WT, HB0H, HB0L);
    convert_km<<<16384, 256>>>(Km, KMH, KML);

    // phase A
    t0_kernel<<<N_, 256>>>(p0, M, Cm, XIN, CC);
    gather_kernel<<<ROWS_ / 8, 256>>>(cond, M, Cm, actions, XIN, CC);
    gemm_bf16<true, false><<<dim3(ROWS_ / 128, 2), 256, BGEMM_SMEM>>>(
        XIN, nullptr, nullptr, WT + W0H, WT + W0L, b0, XA, 320, 320, 256, 0, 0, 0);
    gemm_bf16<true, false><<<dim3(ROWS_ / 128, 2), 256, BGEMM_SMEM>>>(
        XA, nullptr, nullptr, WT + W1H, WT + W1L, b1, XB, 256, 256, 256, 0, 0, 0);
    gemm_bf16<true, false><<<dim3(ROWS_ / 128, 2), 256, BGEMM_SMEM>>>(
        XB, nullptr, nullptr, WT + W2H, WT + W2L, b2, XA, 256, 256, 256, 0, 0, 0);
    gemm_bf16<false, false><<<dim3(ROWS_ / 128, 6), 256, BGEMM_SMEM>>>(
        XA, nullptr, nullptr, WT + WIHH, WT + WIHL, b_ih, GI, 256, 256, 768, 0, 0, 0);

    // phase B: persistent tensor-core GRU (one-hop group counters)
    cudaMemsetAsync(bar_addr, 0, 8 * 32 * sizeof(unsigned));
    gru_tc<<<128, 256, GRU_SMEM2>>>(GI, h0, W_hh, b_hh, HB0H, HB0L, HBH, HBL);

    // phase C
    gemm_bf16<false, true><<<dim3(ROWS_ / 128, 2), 256, BGEMM_SMEM>>>(
        nullptr, HBH, HBL, WT + WAH, WT + WAL, ba, KB, 256, 256, 256, 0, 0, 0);
    gemm_bf16<false, false><<<dim3(1, 2, 256), 256, BGEMM_SMEM>>>(
        KB, nullptr, nullptr, KMH, KML, nullptr, WB, 256, N_ * 256, 256,
        256L, (long)L_ * H_, (long)T_ * L_);
    epilogue_kernel<<<ROWS_ / 8, 256>>>(WB, CC, actions, Wc, bc, HBH, HBL, out);
}

// round 11
// speedup vs baseline: 2.4506x; 1.0117x over previous
#include <cuda_runtime.h>
#include <cuda_bf16.h>
#include <math.h>

#define T_ 128
#define N_ 256
#define L_ 256
#define H_ 256
#define COND_ 64
#define ROWS_ (T_ * N_)   // 32768
#define OUTW_ 770

typedef unsigned long long u64;
typedef unsigned u32;

// ---------------- scratch (float units) --------------------------------------
#define XIN_OFF 0L
#define XA_OFF  (XIN_OFF + (long)ROWS_ * 320)
#define XB_OFF  (XA_OFF  + (long)ROWS_ * 256)
#define GI_OFF  (XB_OFF  + (long)ROWS_ * 256)
#define KB_OFF  (GI_OFF  + (long)ROWS_ * 768)
#define WB_OFF  (KB_OFF  + (long)ROWS_ * 256)
#define CC_OFF  (WB_OFF  + (long)ROWS_ * 256)
#define WT_OFF  (CC_OFF + (long)ROWS_)
#define WT_FLOATS 475136L
#define HBH_OFF (WT_OFF + WT_FLOATS)
#define HBL_OFF (HBH_OFF + 4194304L)
#define HB0H_OFF (HBL_OFF + 4194304L)
#define HB0L_OFF (HB0H_OFF + 32768L)
#define SCRATCH_FLOATS (HB0L_OFF + 32768L)

__device__ float g_scratch[SCRATCH_FLOATS];
__device__ unsigned g_bar2[8 * 32];   // per-nt arrive counters (monotonic)

// bf16 weight-buffer offsets (bf16 element units inside WT)
#define W0H 0
#define W0L 81920
#define W1H 163840
#define W1L 229376
#define W2H 294912
#define W2L 360448
#define WIHH 425984
#define WIHL 622592
#define WAH 819200
#define WAL 884736

// ---------------- bf16 helpers ------------------------------------------------
__device__ __forceinline__ void cvt_split(float x0, float x1, u32& h, u32& l) {
    u32 hh;
    asm("cvt.rn.bf16x2.f32 %0, %1, %2;" : "=r"(hh) : "f"(x1), "f"(x0));
    float r0 = x0 - __uint_as_float(hh << 16);
    float r1 = x1 - __uint_as_float(hh & 0xFFFF0000u);
    u32 ll;
    asm("cvt.rn.bf16x2.f32 %0, %1, %2;" : "=r"(ll) : "f"(r1), "f"(r0));
    h = hh; l = ll;
}
__device__ __forceinline__ void ldsm_x4(u32& r0, u32& r1, u32& r2, u32& r3, u32 a) {
    asm volatile("ldmatrix.sync.aligned.m8n8.x4.shared.b16 {%0,%1,%2,%3}, [%4];"
                 : "=r"(r0), "=r"(r1), "=r"(r2), "=r"(r3) : "r"(a));
}
__device__ __forceinline__ void ldsm_x2(u32& r0, u32& r1, u32 a) {
    asm volatile("ldmatrix.sync.aligned.m8n8.x2.shared.b16 {%0,%1}, [%2];"
                 : "=r"(r0), "=r"(r1) : "r"(a));
}
__device__ __forceinline__ void mma_bf16(float* d, const u32* a, const u32* b) {
    asm volatile(
        "mma.sync.aligned.m16n8k16.row.col.f32.bf16.bf16.f32 "
        "{%0,%1,%2,%3}, {%4,%5,%6,%7}, {%8,%9}, {%0,%1,%2,%3};"
        : "+f"(d[0]), "+f"(d[1]), "+f"(d[2]), "+f"(d[3])
        : "r"(a[0]), "r"(a[1]), "r"(a[2]), "r"(a[3]), "r"(b[0]), "r"(b[1]));
}

// ---------------------------------------------------------------------------
// fused weight/h0 conversion (one launch)
__global__ __launch_bounds__(256) void convert_wall(
    const float* __restrict__ W0, const float* __restrict__ W1,
    const float* __restrict__ W2, const float* __restrict__ W_ih,
    const float* __restrict__ Wa, const float* __restrict__ h0,
    __nv_bfloat16* __restrict__ WT,
    __nv_bfloat16* __restrict__ HB0H, __nv_bfloat16* __restrict__ HB0L)
{
    int b = blockIdx.x, tid = threadIdx.x;
    const float* src; __nv_bfloat16 *dh, *dl;
    int K, Nn, tr, e;
    if (b < 320)        { src = W0;   dh = WT + W0H;  dl = WT + W0L;  K = 320; Nn = 256; tr = 1; e = b * 256 + tid; }
    else if (b < 576)   { src = W1;   dh = WT + W1H;  dl = WT + W1L;  K = 256; Nn = 256; tr = 1; e = (b - 320) * 256 + tid; }
    else if (b < 832)   { src = W2;   dh = WT + W2H;  dl = WT + W2L;  K = 256; Nn = 256; tr = 1; e = (b - 576) * 256 + tid; }
    else if (b < 1600)  { src = W_ih; dh = WT + WIHH; dl = WT + WIHL; K = 256; Nn = 768; tr = 0; e = (b - 832) * 256 + tid; }
    else if (b < 1856)  { src = Wa;   dh = WT + WAH;  dl = WT + WAL;  K = 256; Nn = 256; tr = 1; e = (b - 1600) * 256 + tid; }
    else                { src = h0;   dh = HB0H;      dl = HB0L;      K = 256; Nn = 256; tr = 0; e = (b - 1856) * 256 + tid; }
    int n = e / K, k = e % K;
    float v = tr ? src[(long)k * Nn + n] : src[e];
    __nv_bfloat16 h = __float2bfloat16(v);
    dh[e] = h;
    dl[e] = __float2bfloat16(v - __bfloat162float(h));
}

// ---------------------------------------------------------------------------
__global__ __launch_bounds__(256) void t0_kernel(
    const float* __restrict__ p0, const float* __restrict__ M,
    const float* __restrict__ C, float* __restrict__ XIN, float* __restrict__ CC)
{
    int n = blockIdx.x;
    int tid = threadIdx.x;
    float v = p0[(long)n * L_ + tid];
    int any = __syncthreads_or(v != 0.f);
    if (!any) {
        XIN[(long)n * 320 + 64 + tid] = M[(long)n * L_ * H_ + tid];
        if (tid == 0) CC[n] = C[(long)n * L_];
        return;
    }
    __shared__ float red[256];
    __shared__ float ps[256];
    ps[tid] = v;
    __syncthreads();
    float acc = 0.f;
    const float* Mn = M + (long)n * L_ * H_;
    for (int l = 0; l < L_; l++)
        acc = fmaf(ps[l], Mn[(long)l * H_ + tid], acc);
    XIN[(long)n * 320 + 64 + tid] = acc;
    red[tid] = ps[tid] * C[(long)n * L_ + tid];
    __syncthreads();
    for (int s = 128; s > 0; s >>= 1) {
        if (tid < s) red[tid] += red[tid + s];
        __syncthreads();
    }
    if (tid == 0) CC[n] = red[0];
}

// ---------------------------------------------------------------------------
__global__ __launch_bounds__(256) void gather_kernel(
    const float* __restrict__ cond, const float* __restrict__ M,
    const float* __restrict__ C, const int* __restrict__ actions,
    float* __restrict__ XIN, float* __restrict__ CC)
{
    int r = threadIdx.x >> 5, lane = threadIdx.x & 31;
    long idx = (long)blockIdx.x * 8 + r;
    int t = (int)(idx / N_), n = (int)(idx % N_);
    float4* dst = (float4*)(XIN + idx * 320);
    const float4* csrc = (const float4*)(cond + idx * COND_);
    if (lane < 16) dst[lane] = csrc[lane];
    if (t > 0) {
        int a = actions[idx - N_];
        const float4* msrc = (const float4*)(M + ((long)n * L_ + a) * H_);
#pragma unroll
        for (int i = 0; i < 2; i++) dst[16 + lane + i * 32] = msrc[lane + i * 32];
        if (lane == 0) CC[idx] = C[(long)n * L_ + a];
    }
}

// ---------------------------------------------------------------------------
// bf16x3 tensor-core GEMM. Tile 128x128, BK=32, 8 warps.
// APRE: A pre-split bf16 hi/lo. BPRE: B pre-split; else B fp32 [n][k] (ldb).
#define BGEMM_SMEM 32768

template <bool RELU, bool APRE, bool BPRE>
__global__ __launch_bounds__(256) void gemm_bf16(
    const float* __restrict__ A,
    const __nv_bfloat16* __restrict__ Ah, const __nv_bfloat16* __restrict__ Al,
    const float* __restrict__ Bf,
    const __nv_bfloat16* __restrict__ Bh, const __nv_bfloat16* __restrict__ Bl,
    const float* __restrict__ bias, float* __restrict__ C,
    int K, int lda, int ldb, int ldc, long batchA, long batchB, long batchC)
{
    extern __shared__ char smx[];
    u32 sb32 = (u32)__cvta_generic_to_shared(smx);

    long bz = blockIdx.z;
    if (!APRE) A += bz * batchA; else { Ah += bz * batchA; Al += bz * batchA; }
    if (!BPRE) Bf += bz * batchB; else { Bh += bz * batchB; Bl += bz * batchB; }
    C += bz * batchC;

    int m0 = blockIdx.x * 128, n0 = blockIdx.y * 128;
    int tid = threadIdx.x;
    int wid = tid >> 5, lane = tid & 31;
    int warp_m = wid & 1, warp_n = wid >> 1;
    int gid = lane >> 2, tg = lane & 3;

    int am[4], aq[4], an2[2], ac2[2], bn_[2], bc_[2];
#pragma unroll
    for (int j = 0; j < 4; j++) {
        int idx = tid + j * 256;
        am[j] = idx >> 3; aq[j] = idx & 7;       // also reused for B f32 path
    }
#pragma unroll
    for (int j = 0; j < 2; j++) {
        int idx = tid + j * 256;
        an2[j] = idx >> 2; ac2[j] = idx & 3;
        bn_[j] = idx >> 2; bc_[j] = idx & 3;
    }

    int rowa = warp_m * 64 + (lane & 15);
    int rsa = (rowa >> 1) & 3;
    int ha = lane >> 4;
    int rowb = warp_n * 32 + (lane & 7);
    int rsb = (rowb >> 1) & 3;
    int hb = (lane >> 3) & 1;

    float acc[4][4][4];
#pragma unroll
    for (int i = 0; i < 4; i++)
#pragma unroll
        for (int j = 0; j < 4; j++)
#pragma unroll
            for (int v = 0; v < 4; v++) acc[i][j][v] = 0.f;

    auto store_a_f32 = [&](int m, int q, float4 v) {
        u32 h01, l01, h23, l23;
        cvt_split(v.x, v.y, h01, l01);
        cvt_split(v.z, v.w, h23, l23);
        char* p = smx + m * 64 + (((q >> 1) ^ ((m >> 1) & 3)) * 16) + (q & 1) * 8;
        *(uint2*)p = make_uint2(h01, h23);
        *(uint2*)(p + 8192) = make_uint2(l01, l23);
    };
    auto store_b_f32 = [&](int m, int q, float4 v) {
        u32 h01, l01, h23, l23;
        cvt_split(v.x, v.y, h01, l01);
        cvt_split(v.z, v.w, h23, l23);
        char* p = smx + 16384 + m * 64 + (((q >> 1) ^ ((m >> 1) & 3)) * 16) + (q & 1) * 8;
        *(uint2*)p = make_uint2(h01, h23);
        *(uint2*)(p + 8192) = make_uint2(l01, l23);
    };
    auto store_a_pre = [&](int m, int c, uint4 h, uint4 l) {
        char* p = smx + m * 64 + ((c ^ ((m >> 1) & 3)) * 16);
        *(uint4*)p = h;
        *(uint4*)(p + 8192) = l;
    };
    auto store_b_pre = [&](int n, int c, uint4 h, uint4 l) {
        char* p = smx + 16384 + n * 64 + ((c ^ ((n >> 1) & 3)) * 16);
        *(uint4*)p = h;
        *(uint4*)(p + 8192) = l;
    };

    // prologue stage
    if (!APRE) {
#pragma unroll
        for (int j = 0; j < 4; j++) {
            float4 v = *(const float4*)&A[(long)(m0 + am[j]) * lda + aq[j] * 4];
            store_a_f32(am[j], aq[j], v);
        }
    } else {
#pragma unroll
        for (int j = 0; j < 2; j++) {
            long off = (long)(m0 + an2[j]) * lda + ac2[j] * 8;
            store_a_pre(an2[j], ac2[j], *(const uint4*)(Ah + off), *(const uint4*)(Al + off));
        }
    }
    if (!BPRE) {
#pragma unroll
        for (int j = 0; j < 4; j++) {
            float4 v = *(const float4*)&Bf[(long)(n0 + am[j]) * ldb + aq[j] * 4];
            store_b_f32(am[j], aq[j], v);
        }
    } else {
#pragma unroll
        for (int j = 0; j < 2; j++) {
            long off = (long)(n0 + bn_[j]) * K + bc_[j] * 8;
            store_b_pre(bn_[j], bc_[j], *(const uint4*)(Bh + off), *(const uint4*)(Bl + off));
        }
    }
    __syncthreads();

    int nk = K / 32;
    for (int kt = 0; kt < nk; kt++) {
        float4 ra[4], rbf[4];
        uint4 rah[2], ral[2], rbh[2], rbl[2];
        bool nxt = (kt + 1 < nk);
        if (nxt) {
            int k0 = (kt + 1) * 32;
            if (!APRE) {
#pragma unroll
                for (int j = 0; j < 4; j++)
                    ra[j] = *(const float4*)&A[(long)(m0 + am[j]) * lda + k0 + aq[j] * 4];
            } else {
#pragma unroll
                for (int j = 0; j < 2; j++) {
                    long off = (long)(m0 + an2[j]) * lda + k0 + ac2[j] * 8;
                    rah[j] = *(const uint4*)(Ah + off);
                    ral[j] = *(const uint4*)(Al + off);
                }
            }
            if (!BPRE) {
#pragma unroll
                for (int j = 0; j < 4; j++)
                    rbf[j] = *(const float4*)&Bf[(long)(n0 + am[j]) * ldb + k0 + aq[j] * 4];
            } else {
#pragma unroll
                for (int j = 0; j < 2; j++) {
                    long off = (long)(n0 + bn_[j]) * K + k0 + bc_[j] * 8;
                    rbh[j] = *(const uint4*)(Bh + off);
                    rbl[j] = *(const uint4*)(Bl + off);
                }
            }
        }

#pragma unroll
        for (int ks = 0; ks < 2; ks++) {
            u32 bhf[4][2], blf[4][2];
#pragma unroll
            for (int ni = 0; ni < 4; ni++) {
                int cb = (ks * 2 + hb) ^ rsb;
                u32 addr = sb32 + 16384 + (rowb + ni * 8) * 64 + cb * 16;
                ldsm_x2(bhf[ni][0], bhf[ni][1], addr);
                ldsm_x2(blf[ni][0], blf[ni][1], addr + 8192);
            }
#pragma unroll
            for (int mi = 0; mi < 4; mi++) {
                int ca = (ks * 2 + ha) ^ rsa;
                u32 addr = sb32 + (rowa + mi * 16) * 64 + ca * 16;
                u32 ah[4], al[4];
                ldsm_x4(ah[0], ah[1], ah[2], ah[3], addr);
                ldsm_x4(al[0], al[1], al[2], al[3], addr + 8192);
#pragma unroll
                for (int ni = 0; ni < 4; ni++) {
                    mma_bf16(acc[mi][ni], ah, bhf[ni]);
                    mma_bf16(acc[mi][ni], ah, blf[ni]);
                    mma_bf16(acc[mi][ni], al, bhf[ni]);
                }
            }
        }
        __syncthreads();
        if (nxt) {
            if (!APRE) {
#pragma unroll
                for (int j = 0; j < 4; j++) store_a_f32(am[j], aq[j], ra[j]);
            } else {
#pragma unroll
                for (int j = 0; j < 2; j++) store_a_pre(an2[j], ac2[j], rah[j], ral[j]);
            }
            if (!BPRE) {
#pragma unroll
                for (int j = 0; j < 4; j++) store_b_f32(am[j], aq[j], rbf[j]);
            } else {
#pragma unroll
                for (int j = 0; j < 2; j++) store_b_pre(bn_[j], bc_[j], rbh[j], rbl[j]);
            }
        }
        __syncthreads();
    }

#pragma unroll
    for (int mi = 0; mi < 4; mi++) {
        int mbase = m0 + warp_m * 64 + mi * 16;
#pragma unroll
        for (int ni = 0; ni < 4; ni++) {
            int col = n0 + warp_n * 32 + ni * 8 + tg * 2;
            float b0 = 0.f, b1 = 0.f;
            if (bias) { b0 = bias[col]; b1 = bias[col + 1]; }
            float v0 = acc[mi][ni][0] + b0, v1 = acc[mi][ni][1] + b1;
            float v2 = acc[mi][ni][2] + b0, v3 = acc[mi][ni][3] + b1;
            if (RELU) {
                v0 = fmaxf(v0, 0.f); v1 = fmaxf(v1, 0.f);
                v2 = fmaxf(v2, 0.f); v3 = fmaxf(v3, 0.f);
            }
            *(float2*)&C[(long)(mbase + gid) * ldc + col] = make_float2(v0, v1);
            *(float2*)&C[(long)(mbase + gid + 8) * ldc + col] = make_float2(v2, v3);
        }
    }
}

// ---------------------------------------------------------------------------
// persistent GRU, tensor-core gh, 384 threads (12 mma warps), one-hop barrier.
#define GRU_SMEM2 43008
#define GRU_THREADS 384

__device__ __forceinline__ float sigmf(float x) { return 1.f / (1.f + __expf(-x)); }
__device__ __forceinline__ float tanhfast(float x) { return 2.f / (1.f + __expf(-2.f * x)) - 1.f; }

__global__ __launch_bounds__(GRU_THREADS) void gru_tc(
    const float* __restrict__ GI, const float* __restrict__ h0,
    const float* __restrict__ W_hh, const float* __restrict__ b_hh,
    const __nv_bfloat16* __restrict__ HB0H, const __nv_bfloat16* __restrict__ HB0L,
    __nv_bfloat16* __restrict__ HBH, __nv_bfloat16* __restrict__ HBL)
{
    extern __shared__ char sm8[];
    u32 sb = (u32)__cvta_generic_to_shared(sm8);
    float* ghs = (float*)(sm8 + 32768);      // [32][64] fp32
    float* hown = (float*)(sm8 + 40960);     // [32][16] fp32

    int tid = threadIdx.x;
    int wid = tid >> 5, lane = tid & 31;
    int jt = blockIdx.x & 15, nt = blockIdx.x >> 4;
    int j0 = jt * 16, n0 = nt * 32;
    int colg = wid % 6, mt = wid / 6;        // 12 warps: 6 col-groups x 2 m-tiles

    unsigned* arr = &g_bar2[nt * 32];

    // ---- W_hh fragment preload (two-phase through A region) ----
    u32 bhf[16][2], blf[16][2];
    {
        for (int e = tid; e < 3072; e += GRU_THREADS) {
            int r = e >> 6, q = e & 63;
            float4 v = *(const float4*)&W_hh[(long)((r >> 4) * 256 + j0 + (r & 15)) * 256 + q * 4];
            u32 h01, l01, h23, l23;
            cvt_split(v.x, v.y, h01, l01);
            cvt_split(v.z, v.w, h23, l23);
            *(uint2*)(sm8 + r * 512 + (((q >> 1) ^ (r & 7)) * 16) + (q & 1) * 8) =
                make_uint2(h01, h23);
        }
        __syncthreads();
        {
            int rb = colg * 8 + (lane & 7);
            int hb2 = (lane >> 3) & 1;
#pragma unroll
            for (int s = 0; s < 16; s++) {
                u32 addr = sb + rb * 512 + (((s * 2 + hb2) ^ (rb & 7)) * 16);
                ldsm_x2(bhf[s][0], bhf[s][1], addr);
            }
        }
        __syncthreads();
        for (int e = tid; e < 3072; e += GRU_THREADS) {
            int r = e >> 6, q = e & 63;
            float4 v = *(const float4*)&W_hh[(long)((r >> 4) * 256 + j0 + (r & 15)) * 256 + q * 4];
            u32 h01, l01, h23, l23;
            cvt_split(v.x, v.y, h01, l01);
            cvt_split(v.z, v.w, h23, l23);
            *(uint2*)(sm8 + r * 512 + (((q >> 1) ^ (r & 7)) * 16) + (q & 1) * 8) =
                make_uint2(l01, l23);
        }
        __syncthreads();
        {
            int rb = colg * 8 + (lane & 7);
            int hb2 = (lane >> 3) & 1;
#pragma unroll
            for (int s = 0; s < 16; s++) {
                u32 addr = sb + rb * 512 + (((s * 2 + hb2) ^ (rb & 7)) * 16);
                ldsm_x2(blf[s][0], blf[s][1], addr);
            }
        }
        __syncthreads();
    }

    int jj = tid & 15, nb0 = (tid & 255) >> 4;
    float bhr = b_hh[j0 + jj], bhz = b_hh[256 + j0 + jj], bhn = b_hh[512 + j0 + jj];
    if (tid < 256) {
#pragma unroll
        for (int i = 0; i < 2; i++) {
            int n = nb0 + 16 * i;
            hown[n * 16 + jj] = h0[(long)(n0 + n) * H_ + j0 + jj];
        }
    }
    float gr[2], gz[2], gn[2];
    if (tid < 256) {
#pragma unroll
        for (int i = 0; i < 2; i++) {
            long base = ((long)(n0 + nb0 + 16 * i)) * 768 + j0 + jj;
            gr[i] = GI[base]; gz[i] = GI[base + 256]; gn[i] = GI[base + 512];
        }
    }
    __syncthreads();

    for (int t = 0; t < T_; t++) {
        // ---- stage h(t-1) bf16 hi/lo into smem ----
        const __nv_bfloat16* srcH = t ? HBH + (long)(t - 1) * N_ * H_ : HB0H;
        const __nv_bfloat16* srcL = t ? HBL + (long)(t - 1) * N_ * H_ : HB0L;
        for (int e = tid; e < 1024; e += GRU_THREADS) {
            int r = e >> 5, c = e & 31;
            u32 soff = r * 512 + ((c ^ (r & 7)) * 16);
            *(uint4*)(sm8 + soff) = *(const uint4*)(srcH + (long)(n0 + r) * 256 + c * 8);
            *(uint4*)(sm8 + 16384 + soff) = *(const uint4*)(srcL + (long)(n0 + r) * 256 + c * 8);
        }
        __syncthreads();

        // ---- mma: gh[32n][48col], 12 warps, each 16 rows x 8 cols ----
        {
            float acc[4];
#pragma unroll
            for (int v = 0; v < 4; v++) acc[v] = 0.f;
            int rr = mt * 16 + (lane & 15);
            int ha2 = lane >> 4;
#pragma unroll
            for (int s = 0; s < 16; s++) {
                u32 addr = sb + rr * 512 + (((s * 2 + ha2) ^ (rr & 7)) * 16);
                u32 ah[4], al[4];
                ldsm_x4(ah[0], ah[1], ah[2], ah[3], addr);
                ldsm_x4(al[0], al[1], al[2], al[3], addr + 16384);
                mma_bf16(acc, ah, bhf[s]);
                mma_bf16(acc, ah, blf[s]);
                mma_bf16(acc, al, bhf[s]);
            }
            int gid = lane >> 2, tg = lane & 3;
            *(float2*)&ghs[(mt * 16 + gid) * 64 + colg * 8 + tg * 2] =
                make_float2(acc[0], acc[1]);
            *(float2*)&ghs[(mt * 16 + gid + 8) * 64 + colg * 8 + tg * 2] =
                make_float2(acc[2], acc[3]);
        }
        __syncthreads();

        // ---- elementwise tail (threads 0..255) ----
        if (tid < 256) {
            __nv_bfloat16* bhd = HBH + (long)t * N_ * H_;
            __nv_bfloat16* bld = HBL + (long)t * N_ * H_;
#pragma unroll
            for (int i = 0; i < 2; i++) {
                int n = nb0 + 16 * i;
                float ghr = ghs[n * 64 + jj];
                float ghz = ghs[n * 64 + 16 + jj];
                float ghn = ghs[n * 64 + 32 + jj];
                float rg = sigmf(gr[i] + ghr + bhr);
                float z  = sigmf(gz[i] + ghz + bhz);
                float nv = tanhfast(gn[i] + rg * (ghn + bhn));
                float hp = hown[n * 16 + jj];
                float hn = (1.f - z) * nv + z * hp;
                hown[n * 16 + jj] = hn;
                long gofs = (long)(n0 + n) * H_ + j0 + jj;
                __nv_bfloat16 hh = __float2bfloat16(hn);
                bhd[gofs] = hh;
                bld[gofs] = __float2bfloat16(hn - __bfloat162float(hh));
            }
        }

        if (t < T_ - 1) {
            __syncthreads();
            if (tid == 0) {
                asm volatile("red.release.gpu.global.add.u32 [%0], %1;"
                             :: "l"(arr), "r"(1u) : "memory");
            }
            // prefetch gi(t+1) while waiting
            if (tid < 256) {
#pragma unroll
                for (int i = 0; i < 2; i++) {
                    long base = ((long)(t + 1) * N_ + n0 + nb0 + 16 * i) * 768 + j0 + jj;
                    gr[i] = GI[base]; gz[i] = GI[base + 256]; gn[i] = GI[base + 512];
                }
            }
            if (tid == 0) {
                unsigned target = (unsigned)(t + 1) * 16u;
                unsigned e;
                do {
                    asm volatile("ld.acquire.gpu.global.u32 %0, [%1];"
                                 : "=r"(e) : "l"(arr) : "memory");
                } while (e < target);
            }
            __syncthreads();
        }
    }
}

// ---------------------------------------------------------------------------
// warp-per-(t,n): h reconstruct (hi+lo) + copy, softmax, one-hot, value.
__global__ __launch_bounds__(256) void epilogue_kernel(
    const float* __restrict__ WB, const float* __restrict__ CC,
    const int* __restrict__ actions, const float* __restrict__ Wc,
    const float* __restrict__ bc,
    const __nv_bfloat16* __restrict__ HBH, const __nv_bfloat16* __restrict__ HBL,
    float* __restrict__ out)
{
    int wid = threadIdx.x >> 5, lane = threadIdx.x & 31;
    long idx = (long)blockIdx.x * 8 + wid;
    int t = (int)(idx / N_), n = (int)(idx % N_);
    float cc = CC[idx];
    long base = idx * OUTW_;

    const __nv_bfloat162* hv = (const __nv_bfloat162*)(HBH + idx * 256 + lane * 8);
    const __nv_bfloat162* lv = (const __nv_bfloat162*)(HBL + idx * 256 + lane * 8);
    float h[8];
#pragma unroll
    for (int i = 0; i < 4; i++) {
        float2 fh = __bfloat1622float2(hv[i]);
        float2 fl = __bfloat1622float2(lv[i]);
        h[2 * i] = fh.x + fl.x;
        h[2 * i + 1] = fh.y + fl.y;
    }
    float2* hdst = (float2*)(out + base + 2 + lane * 8);
#pragma unroll
    for (int i = 0; i < 4; i++) hdst[i] = make_float2(h[2 * i], h[2 * i + 1]);

    const float4* wc = (const float4*)Wc;
    float4 c0 = wc[lane * 2], c1 = wc[lane * 2 + 1];
    float d = h[0] * c0.x + h[1] * c0.y + h[2] * c0.z + h[3] * c0.w
            + h[4] * c1.x + h[5] * c1.y + h[6] * c1.z + h[7] * c1.w;
#pragma unroll
    for (int o = 16; o; o >>= 1) d += __shfl_xor_sync(~0u, d, o);

    const float4* wrow = (const float4*)(WB + ((long)n * T_ + t) * L_);
    float4 w0 = wrow[lane * 2], w1 = wrow[lane * 2 + 1];
    float wv[8] = {w0.x * cc, w0.y * cc, w0.z * cc, w0.w * cc,
                   w1.x * cc, w1.y * cc, w1.z * cc, w1.w * cc};
    float mx = wv[0];
#pragma unroll
    for (int i = 1; i < 8; i++) mx = fmaxf(mx, wv[i]);
#pragma unroll
    for (int o = 16; o; o >>= 1) mx = fmaxf(mx, __shfl_xor_sync(~0u, mx, o));
    float e[8], s = 0.f;
#pragma unroll
    for (int i = 0; i < 8; i++) { e[i] = expf(wv[i] - mx); s += e[i]; }
#pragma unroll
    for (int o = 16; o; o >>= 1) s += __shfl_xor_sync(~0u, s, o);
    float inv = 1.f / s;

    int a = actions[idx];
    float2* pdst = (float2*)(out + base + 258 + lane * 8);
    float2* odst = (float2*)(out + base + 514 + lane * 8);
#pragma unroll
    for (int i = 0; i < 4; i++) {
        pdst[i] = make_float2(e[2 * i] * inv, e[2 * i + 1] * inv);
        int l0 = lane * 8 + 2 * i;
        odst[i] = make_float2(l0 == a ? 1.f : 0.f, l0 + 1 == a ? 1.f : 0.f);
    }
    if (lane == 0) {
        out[base + 0] = (float)a;
        out[base + 1] = d + bc[0];
    }
}

// ---------------------------------------------------------------------------
extern "C" void kernel_launch(void* const* d_in, const int* in_sizes, int n_in,
                              void* d_out, int out_size)
{
    const float* cond = (const float*)d_in[0];
    const float* M    = (const float*)d_in[1];
    const float* Km   = (const float*)d_in[2];
    const float* Cm   = (const float*)d_in[3];
    const float* h0   = (const float*)d_in[4];
    const float* p0   = (const float*)d_in[5];
    const float* W0   = (const float*)d_in[6];
    const float* b0   = (const float*)d_in[7];
    const float* W1   = (const float*)d_in[8];
    const float* b1   = (const float*)d_in[9];
    const float* W2   = (const float*)d_in[10];
    const float* b2   = (const float*)d_in[11];
    const float* W_ih = (const float*)d_in[12];
    const float* W_hh = (const float*)d_in[13];
    const float* b_ih = (const float*)d_in[14];
    const float* b_hh = (const float*)d_in[15];
    const float* Wa   = (const float*)d_in[16];
    const float* ba   = (const float*)d_in[17];
    const float* Wc   = (const float*)d_in[18];
    const float* bc   = (const float*)d_in[19];
    const int* actions = (const int*)d_in[20];
    float* out = (float*)d_out;

    float* base = nullptr;
    cudaGetSymbolAddress((void**)&base, g_scratch);
    float* XIN = base + XIN_OFF;
    float* XA  = base + XA_OFF;
    float* XB  = base + XB_OFF;
    float* GI  = base + GI_OFF;
    float* KB  = base + KB_OFF;
    float* WB  = base + WB_OFF;
    float* CC  = base + CC_OFF;
    __nv_bfloat16* WT = (__nv_bfloat16*)(base + WT_OFF);
    __nv_bfloat16* HBH = (__nv_bfloat16*)(base + HBH_OFF);
    __nv_bfloat16* HBL = (__nv_bfloat16*)(base + HBL_OFF);
    __nv_bfloat16* HB0H = (__nv_bfloat16*)(base + HB0H_OFF);
    __nv_bfloat16* HB0L = (__nv_bfloat16*)(base + HB0L_OFF);

    void* bar_addr = nullptr;
    cudaGetSymbolAddress(&bar_addr, g_bar2);

    cudaFuncSetAttribute(gru_tc,
                         cudaFuncAttributeMaxDynamicSharedMemorySize, GRU_SMEM2);

    // phase 0: conversions (one launch)
    convert_wall<<<2112, 256>>>(W0, W1, W2, W_ih, Wa, h0, WT, HB0H, HB0L);

    // phase A
    t0_kernel<<<N_, 256>>>(p0, M, Cm, XIN, CC);
    gather_kernel<<<ROWS_ / 8, 256>>>(cond, M, Cm, actions, XIN, CC);
    gemm_bf16<true, false, true><<<dim3(ROWS_ / 128, 2), 256, BGEMM_SMEM>>>(
        XIN, nullptr, nullptr, nullptr, WT + W0H, WT + W0L, b0, XA,
        320, 320, 0, 256, 0, 0, 0);
    gemm_bf16<true, false, true><<<dim3(ROWS_ / 128, 2), 256, BGEMM_SMEM>>>(
        XA, nullptr, nullptr, nullptr, WT + W1H, WT + W1L, b1, XB,
        256, 256, 0, 256, 0, 0, 0);
    gemm_bf16<true, false, true><<<dim3(ROWS_ / 128, 2), 256, BGEMM_SMEM>>>(
        XB, nullptr, nullptr, nullptr, WT + W2H, WT + W2L, b2, XA,
        256, 256, 0, 256, 0, 0, 0);
    gemm_bf16<false, false, true><<<dim3(ROWS_ / 128, 6), 256, BGEMM_SMEM>>>(
        XA, nullptr, nullptr, nullptr, WT + WIHH, WT + WIHL, b_ih, GI,
        256, 256, 0, 768, 0, 0, 0);

    // phase B: persistent tensor-core GRU (384 threads)
    cudaMemsetAsync(bar_addr, 0, 8 * 32 * sizeof(unsigned));
    gru_tc<<<128, GRU_THREADS, GRU_SMEM2>>>(GI, h0, W_hh, b_hh, HB0H, HB0L, HBH, HBL);

    // phase C
    gemm_bf16<false, true, true><<<dim3(ROWS_ / 128, 2), 256, BGEMM_SMEM>>>(
        nullptr, HBH, HBL, nullptr, WT + WAH, WT + WAL, ba, KB,
        256, 256, 0, 256, 0, 0, 0);
    gemm_bf16<false, false, false><<<dim3(1, 2, 256), 256, BGEMM_SMEM>>>(
        KB, nullptr, nullptr, Km, nullptr, nullptr, nullptr, WB,
        256, N_ * 256, 256, 256, 256L, (long)L_ * H_, (long)T_ * L_);
    epilogue_kernel<<<ROWS_ / 8, 256>>>(WB, CC, actions, Wc, bc, HBH, HBL, out);
}

// round 12
// speedup vs baseline: 2.5660x; 1.0471x over previous
#include <cuda_runtime.h>
#include <cuda_bf16.h>
#include <math.h>

#define T_ 128
#define N_ 256
#define L_ 256
#define H_ 256
#define COND_ 64
#define ROWS_ (T_ * N_)   // 32768
#define OUTW_ 770

typedef unsigned long long u64;
typedef unsigned u32;

// ---------------- scratch (float units) --------------------------------------
#define XINH_OFF 0L                               // [ROWS][320] bf16
#define XINL_OFF (XINH_OFF + (long)ROWS_ * 160)
#define XAH_OFF  (XINL_OFF + (long)ROWS_ * 160)   // [ROWS][256] bf16
#define XAL_OFF  (XAH_OFF + (long)ROWS_ * 128)
#define XBH_OFF  (XAL_OFF + (long)ROWS_ * 128)
#define XBL_OFF  (XBH_OFF + (long)ROWS_ * 128)
#define GI_OFF   (XBL_OFF + (long)ROWS_ * 128)    // fp32 [ROWS][768]
#define KBH_OFF  (GI_OFF + (long)ROWS_ * 768)
#define KBL_OFF  (KBH_OFF + (long)ROWS_ * 128)
#define WB_OFF   (KBL_OFF + (long)ROWS_ * 128)    // fp32 [N][T][L]
#define CC_OFF   (WB_OFF + (long)ROWS_ * 256)
#define WT_OFF   (CC_OFF + (long)ROWS_)
#define WT_FLOATS 475136L
#define HBH_OFF  (WT_OFF + WT_FLOATS)
#define HBL_OFF  (HBH_OFF + 4194304L)
#define HB0H_OFF (HBL_OFF + 4194304L)
#define HB0L_OFF (HB0H_OFF + 32768L)
#define SCRATCH_FLOATS (HB0L_OFF + 32768L)

__device__ float g_scratch[SCRATCH_FLOATS];
__device__ unsigned g_bar2[8 * 32];   // per-nt arrive counters (monotonic)

// bf16 weight-buffer offsets (bf16 element units inside WT)
#define W0H 0
#define W0L 81920
#define W1H 163840
#define W1L 229376
#define W2H 294912
#define W2L 360448
#define WIHH 425984
#define WIHL 622592
#define WAH 819200
#define WAL 884736

// ---------------- bf16 helpers ------------------------------------------------
__device__ __forceinline__ void cvt_split(float x0, float x1, u32& h, u32& l) {
    u32 hh;
    asm("cvt.rn.bf16x2.f32 %0, %1, %2;" : "=r"(hh) : "f"(x1), "f"(x0));
    float r0 = x0 - __uint_as_float(hh << 16);
    float r1 = x1 - __uint_as_float(hh & 0xFFFF0000u);
    u32 ll;
    asm("cvt.rn.bf16x2.f32 %0, %1, %2;" : "=r"(ll) : "f"(r1), "f"(r0));
    h = hh; l = ll;
}
__device__ __forceinline__ void ldsm_x4(u32& r0, u32& r1, u32& r2, u32& r3, u32 a) {
    asm volatile("ldmatrix.sync.aligned.m8n8.x4.shared.b16 {%0,%1,%2,%3}, [%4];"
                 : "=r"(r0), "=r"(r1), "=r"(r2), "=r"(r3) : "r"(a));
}
__device__ __forceinline__ void ldsm_x2(u32& r0, u32& r1, u32 a) {
    asm volatile("ldmatrix.sync.aligned.m8n8.x2.shared.b16 {%0,%1}, [%2];"
                 : "=r"(r0), "=r"(r1) : "r"(a));
}
__device__ __forceinline__ void mma_bf16(float* d, const u32* a, const u32* b) {
    asm volatile(
        "mma.sync.aligned.m16n8k16.row.col.f32.bf16.bf16.f32 "
        "{%0,%1,%2,%3}, {%4,%5,%6,%7}, {%8,%9}, {%0,%1,%2,%3};"
        : "+f"(d[0]), "+f"(d[1]), "+f"(d[2]), "+f"(d[3])
        : "r"(a[0]), "r"(a[1]), "r"(a[2]), "r"(a[3]), "r"(b[0]), "r"(b[1]));
}
#define CPA16(d, s) \
    asm volatile("cp.async.ca.shared.global [%0], [%1], 16;" :: "r"(d), "l"(s))
#define CPC() asm volatile("cp.async.commit_group;" ::: "memory")

// ---------------------------------------------------------------------------
// fused weight/h0 conversion (one launch)
__global__ __launch_bounds__(256) void convert_wall(
    const float* __restrict__ W0, const float* __restrict__ W1,
    const float* __restrict__ W2, const float* __restrict__ W_ih,
    const float* __restrict__ Wa, const float* __restrict__ h0,
    __nv_bfloat16* __restrict__ WT,
    __nv_bfloat16* __restrict__ HB0H, __nv_bfloat16* __restrict__ HB0L)
{
    int b = blockIdx.x, tid = threadIdx.x;
    const float* src; __nv_bfloat16 *dh, *dl;
    int K, Nn, tr, e;
    if (b < 320)        { src = W0;   dh = WT + W0H;  dl = WT + W0L;  K = 320; Nn = 256; tr = 1; e = b * 256 + tid; }
    else if (b < 576)   { src = W1;   dh = WT + W1H;  dl = WT + W1L;  K = 256; Nn = 256; tr = 1; e = (b - 320) * 256 + tid; }
    else if (b < 832)   { src = W2;   dh = WT + W2H;  dl = WT + W2L;  K = 256; Nn = 256; tr = 1; e = (b - 576) * 256 + tid; }
    else if (b < 1600)  { src = W_ih; dh = WT + WIHH; dl = WT + WIHL; K = 256; Nn = 768; tr = 0; e = (b - 832) * 256 + tid; }
    else if (b < 1856)  { src = Wa;   dh = WT + WAH;  dl = WT + WAL;  K = 256; Nn = 256; tr = 1; e = (b - 1600) * 256 + tid; }
    else                { src = h0;   dh = HB0H;      dl = HB0L;      K = 256; Nn = 256; tr = 0; e = (b - 1856) * 256 + tid; }
    int n = e / K, k = e % K;
    float v = tr ? src[(long)k * Nn + n] : src[e];
    __nv_bfloat16 h = __float2bfloat16(v);
    dh[e] = h;
    dl[e] = __float2bfloat16(v - __bfloat162float(h));
}

// ---------------------------------------------------------------------------
__global__ __launch_bounds__(256) void t0_kernel(
    const float* __restrict__ p0, const float* __restrict__ M,
    const float* __restrict__ C, __nv_bfloat16* __restrict__ XINH,
    __nv_bfloat16* __restrict__ XINL, float* __restrict__ CC)
{
    int n = blockIdx.x;
    int tid = threadIdx.x;
    float v = p0[(long)n * L_ + tid];
    int any = __syncthreads_or(v != 0.f);
    float acc;
    if (!any) {
        acc = M[(long)n * L_ * H_ + tid];
        if (tid == 0) CC[n] = C[(long)n * L_];
    } else {
        __shared__ float red[256];
        __shared__ float ps[256];
        ps[tid] = v;
        __syncthreads();
        acc = 0.f;
        const float* Mn = M + (long)n * L_ * H_;
        for (int l = 0; l < L_; l++)
            acc = fmaf(ps[l], Mn[(long)l * H_ + tid], acc);
        red[tid] = ps[tid] * C[(long)n * L_ + tid];
        __syncthreads();
        for (int s = 128; s > 0; s >>= 1) {
            if (tid < s) red[tid] += red[tid + s];
            __syncthreads();
        }
        if (tid == 0) CC[n] = red[0];
    }
    __nv_bfloat16 h = __float2bfloat16(acc);
    XINH[(long)n * 320 + 64 + tid] = h;
    XINL[(long)n * 320 + 64 + tid] = __float2bfloat16(acc - __bfloat162float(h));
}

// ---------------------------------------------------------------------------
// builds XIN (bf16 hi/lo) rows [cond(64) | r(256)] and CC
__global__ __launch_bounds__(256) void gather_kernel(
    const float* __restrict__ cond, const float* __restrict__ M,
    const float* __restrict__ C, const int* __restrict__ actions,
    __nv_bfloat16* __restrict__ XINH, __nv_bfloat16* __restrict__ XINL,
    float* __restrict__ CC)
{
    int r = threadIdx.x >> 5, lane = threadIdx.x & 31;
    long idx = (long)blockIdx.x * 8 + r;
    int t = (int)(idx / N_), n = (int)(idx % N_);
    char* dh = (char*)(XINH + idx * 320);
    char* dl = (char*)(XINL + idx * 320);
    if (lane < 16) {
        float4 v = ((const float4*)(cond + idx * COND_))[lane];
        u32 h01, l01, h23, l23;
        cvt_split(v.x, v.y, h01, l01);
        cvt_split(v.z, v.w, h23, l23);
        *(uint2*)(dh + lane * 8) = make_uint2(h01, h23);
        *(uint2*)(dl + lane * 8) = make_uint2(l01, l23);
    }
    if (t > 0) {
        int a = actions[idx - N_];
        const float4* msrc = (const float4*)(M + ((long)n * L_ + a) * H_);
#pragma unroll
        for (int i = 0; i < 2; i++) {
            float4 v = msrc[lane + i * 32];
            u32 h01, l01, h23, l23;
            cvt_split(v.x, v.y, h01, l01);
            cvt_split(v.z, v.w, h23, l23);
            int boff = 128 + lane * 8 + i * 256;
            *(uint2*)(dh + boff) = make_uint2(h01, h23);
            *(uint2*)(dl + boff) = make_uint2(l01, l23);
        }
        if (lane == 0) CC[idx] = C[(long)n * L_ + a];
    }
}

// ---------------------------------------------------------------------------
// gemm_v2: bf16x3 tensor-core GEMM, A+B pre-split, cp.async double-buffered.
// Tile 128x128, BK=32, 8 warps. OUTSPLIT: emit bf16 hi/lo; else fp32.
#define GEMM2_SMEM 65536

template <bool RELU, bool OUTSPLIT>
__global__ __launch_bounds__(256, 2) void gemm_v2(
    const __nv_bfloat16* __restrict__ Ah, const __nv_bfloat16* __restrict__ Al,
    const __nv_bfloat16* __restrict__ Bh, const __nv_bfloat16* __restrict__ Bl,
    const float* __restrict__ bias, float* __restrict__ C,
    __nv_bfloat16* __restrict__ Ch, __nv_bfloat16* __restrict__ Cl,
    int K, int lda, int ldc)
{
    extern __shared__ char smx[];
    u32 sb32 = (u32)__cvta_generic_to_shared(smx);

    int m0 = blockIdx.x * 128, n0 = blockIdx.y * 128;
    int tid = threadIdx.x;
    int wid = tid >> 5, lane = tid & 31;
    int warp_m = wid & 1, warp_n = wid >> 1;
    int gid = lane >> 2, tg = lane & 3;

    int sm_[2], sc_[2];
#pragma unroll
    for (int j = 0; j < 2; j++) {
        int idx = tid + j * 256;
        sm_[j] = idx >> 2; sc_[j] = idx & 3;
    }

    int rowa = warp_m * 64 + (lane & 15);
    int rsa = (rowa >> 1) & 3;
    int ha = lane >> 4;
    int rowb = warp_n * 32 + (lane & 7);
    int rsb = (rowb >> 1) & 3;
    int hb = (lane >> 3) & 1;

    float acc[4][4][4];
#pragma unroll
    for (int i = 0; i < 4; i++)
#pragma unroll
        for (int j = 0; j < 4; j++)
#pragma unroll
            for (int v = 0; v < 4; v++) acc[i][j][v] = 0.f;

    auto stage = [&](int buf, int k0) {
        u32 base = sb32 + buf * 32768;
#pragma unroll
        for (int j = 0; j < 2; j++) {
            int m = sm_[j], c = sc_[j];
            u32 off = m * 64 + ((c ^ ((m >> 1) & 3)) * 16);
            long aoff = (long)(m0 + m) * lda + k0 + c * 8;
            long boff = (long)(n0 + m) * K + k0 + c * 8;
            CPA16(base + off, Ah + aoff);
            CPA16(base + off + 8192, Al + aoff);
            CPA16(base + off + 16384, Bh + boff);
            CPA16(base + off + 24576, Bl + boff);
        }
        CPC();
    };

    stage(0, 0);
    int nk = K / 32;
    for (int kt = 0; kt < nk; kt++) {
        int buf = kt & 1;
        if (kt + 1 < nk) {
            stage(buf ^ 1, (kt + 1) * 32);
            asm volatile("cp.async.wait_group 1;" ::: "memory");
        } else {
            asm volatile("cp.async.wait_group 0;" ::: "memory");
        }
        __syncthreads();

        u32 sbb = sb32 + buf * 32768;
#pragma unroll
        for (int ks = 0; ks < 2; ks++) {
            u32 bhf[4][2], blf[4][2];
#pragma unroll
            for (int ni = 0; ni < 4; ni++) {
                int cb = (ks * 2 + hb) ^ rsb;
                u32 addr = sbb + 16384 + (rowb + ni * 8) * 64 + cb * 16;
                ldsm_x2(bhf[ni][0], bhf[ni][1], addr);
                ldsm_x2(blf[ni][0], blf[ni][1], addr + 8192);
            }
#pragma unroll
            for (int mi = 0; mi < 4; mi++) {
                int ca = (ks * 2 + ha) ^ rsa;
                u32 addr = sbb + (rowa + mi * 16) * 64 + ca * 16;
                u32 ah[4], al[4];
                ldsm_x4(ah[0], ah[1], ah[2], ah[3], addr);
                ldsm_x4(al[0], al[1], al[2], al[3], addr + 8192);
#pragma unroll
                for (int ni = 0; ni < 4; ni++) {
                    mma_bf16(acc[mi][ni], ah, bhf[ni]);
                    mma_bf16(acc[mi][ni], ah, blf[ni]);
                    mma_bf16(acc[mi][ni], al, bhf[ni]);
                }
            }
        }
        __syncthreads();
    }

#pragma unroll
    for (int mi = 0; mi < 4; mi++) {
        int mbase = m0 + warp_m * 64 + mi * 16;
#pragma unroll
        for (int ni = 0; ni < 4; ni++) {
            int col = n0 + warp_n * 32 + ni * 8 + tg * 2;
            float b0 = 0.f, b1 = 0.f;
            if (bias) { b0 = bias[col]; b1 = bias[col + 1]; }
            float v0 = acc[mi][ni][0] + b0, v1 = acc[mi][ni][1] + b1;
            float v2 = acc[mi][ni][2] + b0, v3 = acc[mi][ni][3] + b1;
            if (RELU) {
                v0 = fmaxf(v0, 0.f); v1 = fmaxf(v1, 0.f);
                v2 = fmaxf(v2, 0.f); v3 = fmaxf(v3, 0.f);
            }
            if (OUTSPLIT) {
                u32 h01, l01;
                long o0 = (long)(mbase + gid) * ldc + col;
                long o1 = (long)(mbase + gid + 8) * ldc + col;
                cvt_split(v0, v1, h01, l01);
                *(u32*)(Ch + o0) = h01;
                *(u32*)(Cl + o0) = l01;
                cvt_split(v2, v3, h01, l01);
                *(u32*)(Ch + o1) = h01;
                *(u32*)(Cl + o1) = l01;
            } else {
                *(float2*)&C[(long)(mbase + gid) * ldc + col] = make_float2(v0, v1);
                *(float2*)&C[(long)(mbase + gid + 8) * ldc + col] = make_float2(v2, v3);
            }
        }
    }
}

// ---------------------------------------------------------------------------
// Km GEMM (R11-proven): A pre-split, B fp32 (cvt in staging), batched via z.
#define BGEMM_SMEM 32768

__global__ __launch_bounds__(256) void gemm_km(
    const __nv_bfloat16* __restrict__ Ah, const __nv_bfloat16* __restrict__ Al,
    const float* __restrict__ Bf, float* __restrict__ C,
    int K, int lda, int ldb, int ldc, long batchA, long batchB, long batchC)
{
    extern __shared__ char smx[];
    u32 sb32 = (u32)__cvta_generic_to_shared(smx);

    long bz = blockIdx.z;
    Ah += bz * batchA; Al += bz * batchA;
    Bf += bz * batchB; C += bz * batchC;

    int m0 = blockIdx.x * 128, n0 = blockIdx.y * 128;
    int tid = threadIdx.x;
    int wid = tid >> 5, lane = tid & 31;
    int warp_m = wid & 1, warp_n = wid >> 1;
    int gid = lane >> 2, tg = lane & 3;

    int bm[4], bq[4], an2[2], ac2[2];
#pragma unroll
    for (int j = 0; j < 4; j++) {
        int idx = tid + j * 256;
        bm[j] = idx >> 3; bq[j] = idx & 7;
    }
#pragma unroll
    for (int j = 0; j < 2; j++) {
        int idx = tid + j * 256;
        an2[j] = idx >> 2; ac2[j] = idx & 3;
    }

    int rowa = warp_m * 64 + (lane & 15);
    int rsa = (rowa >> 1) & 3;
    int ha = lane >> 4;
    int rowb = warp_n * 32 + (lane & 7);
    int rsb = (rowb >> 1) & 3;
    int hb = (lane >> 3) & 1;

    float acc[4][4][4];
#pragma unroll
    for (int i = 0; i < 4; i++)
#pragma unroll
        for (int j = 0; j < 4; j++)
#pragma unroll
            for (int v = 0; v < 4; v++) acc[i][j][v] = 0.f;

    auto store_a_pre = [&](int m, int c, uint4 h, uint4 l) {
        char* p = smx + m * 64 + ((c ^ ((m >> 1) & 3)) * 16);
        *(uint4*)p = h;
        *(uint4*)(p + 8192) = l;
    };
    auto store_b_f32 = [&](int m, int q, float4 v) {
        u32 h01, l01, h23, l23;
        cvt_split(v.x, v.y, h01, l01);
        cvt_split(v.z, v.w, h23, l23);
        char* p = smx + 16384 + m * 64 + (((q >> 1) ^ ((m >> 1) & 3)) * 16) + (q & 1) * 8;
        *(uint2*)p = make_uint2(h01, h23);
        *(uint2*)(p + 8192) = make_uint2(l01, l23);
    };

#pragma unroll
    for (int j = 0; j < 2; j++) {
        long off = (long)(m0 + an2[j]) * lda + ac2[j] * 8;
        store_a_pre(an2[j], ac2[j], *(const uint4*)(Ah + off), *(const uint4*)(Al + off));
    }
#pragma unroll
    for (int j = 0; j < 4; j++) {
        float4 v = *(const float4*)&Bf[(long)(n0 + bm[j]) * ldb + bq[j] * 4];
        store_b_f32(bm[j], bq[j], v);
    }
    __syncthreads();

    int nk = K / 32;
    for (int kt = 0; kt < nk; kt++) {
        float4 rbf[4];
        uint4 rah[2], ral[2];
        bool nxt = (kt + 1 < nk);
        if (nxt) {
            int k0 = (kt + 1) * 32;
#pragma unroll
            for (int j = 0; j < 2; j++) {
                long off = (long)(m0 + an2[j]) * lda + k0 + ac2[j] * 8;
                rah[j] = *(const uint4*)(Ah + off);
                ral[j] = *(const uint4*)(Al + off);
            }
#pragma unroll
            for (int j = 0; j < 4; j++)
                rbf[j] = *(const float4*)&Bf[(long)(n0 + bm[j]) * ldb + k0 + bq[j] * 4];
        }

#pragma unroll
        for (int ks = 0; ks < 2; ks++) {
            u32 bhf[4][2], blf[4][2];
#pragma unroll
            for (int ni = 0; ni < 4; ni++) {
                int cb = (ks * 2 + hb) ^ rsb;
                u32 addr = sb32 + 16384 + (rowb + ni * 8) * 64 + cb * 16;
                ldsm_x2(bhf[ni][0], bhf[ni][1], addr);
                ldsm_x2(blf[ni][0], blf[ni][1], addr + 8192);
            }
#pragma unroll
            for (int mi = 0; mi < 4; mi++) {
                int ca = (ks * 2 + ha) ^ rsa;
                u32 addr = sb32 + (rowa + mi * 16) * 64 + ca * 16;
                u32 ah[4], al[4];
                ldsm_x4(ah[0], ah[1], ah[2], ah[3], addr);
                ldsm_x4(al[0], al[1], al[2], al[3], addr + 8192);
#pragma unroll
                for (int ni = 0; ni < 4; ni++) {
                    mma_bf16(acc[mi][ni], ah, bhf[ni]);
                    mma_bf16(acc[mi][ni], ah, blf[ni]);
                    mma_bf16(acc[mi][ni], al, bhf[ni]);
                }
            }
        }
        __syncthreads();
        if (nxt) {
#pragma unroll
            for (int j = 0; j < 2; j++) store_a_pre(an2[j], ac2[j], rah[j], ral[j]);
#pragma unroll
            for (int j = 0; j < 4; j++) store_b_f32(bm[j], bq[j], rbf[j]);
        }
        __syncthreads();
    }

#pragma unroll
    for (int mi = 0; mi < 4; mi++) {
        int mbase = m0 + warp_m * 64 + mi * 16;
#pragma unroll
        for (int ni = 0; ni < 4; ni++) {
            int col = n0 + warp_n * 32 + ni * 8 + tg * 2;
            *(float2*)&C[(long)(mbase + gid) * ldc + col] =
                make_float2(acc[mi][ni][0], acc[mi][ni][1]);
            *(float2*)&C[(long)(mbase + gid + 8) * ldc + col] =
                make_float2(acc[mi][ni][2], acc[mi][ni][3]);
        }
    }
}

// ---------------------------------------------------------------------------
// persistent GRU (R11): tensor-core gh, 384 threads, one-hop barrier.
#define GRU_SMEM2 43008
#define GRU_THREADS 384

__device__ __forceinline__ float sigmf(float x) { return 1.f / (1.f + __expf(-x)); }
__device__ __forceinline__ float tanhfast(float x) { return 2.f / (1.f + __expf(-2.f * x)) - 1.f; }

__global__ __launch_bounds__(GRU_THREADS) void gru_tc(
    const float* __restrict__ GI, const float* __restrict__ h0,
    const float* __restrict__ W_hh, const float* __restrict__ b_hh,
    const __nv_bfloat16* __restrict__ HB0H, const __nv_bfloat16* __restrict__ HB0L,
    __nv_bfloat16* __restrict__ HBH, __nv_bfloat16* __restrict__ HBL)
{
    extern __shared__ char sm8[];
    u32 sb = (u32)__cvta_generic_to_shared(sm8);
    float* ghs = (float*)(sm8 + 32768);
    float* hown = (float*)(sm8 + 40960);

    int tid = threadIdx.x;
    int wid = tid >> 5, lane = tid & 31;
    int jt = blockIdx.x & 15, nt = blockIdx.x >> 4;
    int j0 = jt * 16, n0 = nt * 32;
    int colg = wid % 6, mt = wid / 6;

    unsigned* arr = &g_bar2[nt * 32];

    u32 bhf[16][2], blf[16][2];
    {
        for (int e = tid; e < 3072; e += GRU_THREADS) {
            int r = e >> 6, q = e & 63;
            float4 v = *(const float4*)&W_hh[(long)((r >> 4) * 256 + j0 + (r & 15)) * 256 + q * 4];
            u32 h01, l01, h23, l23;
            cvt_split(v.x, v.y, h01, l01);
            cvt_split(v.z, v.w, h23, l23);
            *(uint2*)(sm8 + r * 512 + (((q >> 1) ^ (r & 7)) * 16) + (q & 1) * 8) =
                make_uint2(h01, h23);
        }
        __syncthreads();
        {
            int rb = colg * 8 + (lane & 7);
            int hb2 = (lane >> 3) & 1;
#pragma unroll
            for (int s = 0; s < 16; s++) {
                u32 addr = sb + rb * 512 + (((s * 2 + hb2) ^ (rb & 7)) * 16);
                ldsm_x2(bhf[s][0], bhf[s][1], addr);
            }
        }
        __syncthreads();
        for (int e = tid; e < 3072; e += GRU_THREADS) {
            int r = e >> 6, q = e & 63;
            float4 v = *(const float4*)&W_hh[(long)((r >> 4) * 256 + j0 + (r & 15)) * 256 + q * 4];
            u32 h01, l01, h23, l23;
            cvt_split(v.x, v.y, h01, l01);
            cvt_split(v.z, v.w, h23, l23);
            *(uint2*)(sm8 + r * 512 + (((q >> 1) ^ (r & 7)) * 16) + (q & 1) * 8) =
                make_uint2(l01, l23);
        }
        __syncthreads();
        {
            int rb = colg * 8 + (lane & 7);
            int hb2 = (lane >> 3) & 1;
#pragma unroll
            for (int s = 0; s < 16; s++) {
                u32 addr = sb + rb * 512 + (((s * 2 + hb2) ^ (rb & 7)) * 16);
                ldsm_x2(blf[s][0], blf[s][1], addr);
            }
        }
        __syncthreads();
    }

    int jj = tid & 15, nb0 = (tid & 255) >> 4;
    float bhr = b_hh[j0 + jj], bhz = b_hh[256 + j0 + jj], bhn = b_hh[512 + j0 + jj];
    if (tid < 256) {
#pragma unroll
        for (int i = 0; i < 2; i++) {
            int n = nb0 + 16 * i;
            hown[n * 16 + jj] = h0[(long)(n0 + n) * H_ + j0 + jj];
        }
    }
    float gr[2], gz[2], gn[2];
    if (tid < 256) {
#pragma unroll
        for (int i = 0; i < 2; i++) {
            long base = ((long)(n0 + nb0 + 16 * i)) * 768 + j0 + jj;
            gr[i] = GI[base]; gz[i] = GI[base + 256]; gn[i] = GI[base + 512];
        }
    }
    __syncthreads();

    for (int t = 0; t < T_; t++) {
        const __nv_bfloat16* srcH = t ? HBH + (long)(t - 1) * N_ * H_ : HB0H;
        const __nv_bfloat16* srcL = t ? HBL + (long)(t - 1) * N_ * H_ : HB0L;
        for (int e = tid; e < 1024; e += GRU_THREADS) {
            int r = e >> 5, c = e & 31;
            u32 soff = r * 512 + ((c ^ (r & 7)) * 16);
            *(uint4*)(sm8 + soff) = *(const uint4*)(srcH + (long)(n0 + r) * 256 + c * 8);
            *(uint4*)(sm8 + 16384 + soff) = *(const uint4*)(srcL + (long)(n0 + r) * 256 + c * 8);
        }
        __syncthreads();

        {
            float acc[4];
#pragma unroll
            for (int v = 0; v < 4; v++) acc[v] = 0.f;
            int rr = mt * 16 + (lane & 15);
            int ha2 = lane >> 4;
#pragma unroll
            for (int s = 0; s < 16; s++) {
                u32 addr = sb + rr * 512 + (((s * 2 + ha2) ^ (rr & 7)) * 16);
                u32 ah[4], al[4];
                ldsm_x4(ah[0], ah[1], ah[2], ah[3], addr);
                ldsm_x4(al[0], al[1], al[2], al[3], addr + 16384);
                mma_bf16(acc, ah, bhf[s]);
                mma_bf16(acc, ah, blf[s]);
                mma_bf16(acc, al, bhf[s]);
            }
            int gid = lane >> 2, tg = lane & 3;
            *(float2*)&ghs[(mt * 16 + gid) * 64 + colg * 8 + tg * 2] =
                make_float2(acc[0], acc[1]);
            *(float2*)&ghs[(mt * 16 + gid + 8) * 64 + colg * 8 + tg * 2] =
                make_float2(acc[2], acc[3]);
        }
        __syncthreads();

        if (tid < 256) {
            __nv_bfloat16* bhd = HBH + (long)t * N_ * H_;
            __nv_bfloat16* bld = HBL + (long)t * N_ * H_;
#pragma unroll
            for (int i = 0; i < 2; i++) {
                int n = nb0 + 16 * i;
                float ghr = ghs[n * 64 + jj];
                float ghz = ghs[n * 64 + 16 + jj];
                float ghn = ghs[n * 64 + 32 + jj];
                float rg = sigmf(gr[i] + ghr + bhr);
                float z  = sigmf(gz[i] + ghz + bhz);
                float nv = tanhfast(gn[i] + rg * (ghn + bhn));
                float hp = hown[n * 16 + jj];
                float hn = (1.f - z) * nv + z * hp;
                hown[n * 16 + jj] = hn;
                long gofs = (long)(n0 + n) * H_ + j0 + jj;
                __nv_bfloat16 hh = __float2bfloat16(hn);
                bhd[gofs] = hh;
                bld[gofs] = __float2bfloat16(hn - __bfloat162float(hh));
            }
        }

        if (t < T_ - 1) {
            __syncthreads();
            if (tid == 0) {
                asm volatile("red.release.gpu.global.add.u32 [%0], %1;"
                             :: "l"(arr), "r"(1u) : "memory");
            }
            if (tid < 256) {
#pragma unroll
                for (int i = 0; i < 2; i++) {
                    long base = ((long)(t + 1) * N_ + n0 + nb0 + 16 * i) * 768 + j0 + jj;
                    gr[i] = GI[base]; gz[i] = GI[base + 256]; gn[i] = GI[base + 512];
                }
            }
            if (tid == 0) {
                unsigned target = (unsigned)(t + 1) * 16u;
                unsigned e;
                do {
                    asm volatile("ld.acquire.gpu.global.u32 %0, [%1];"
                                 : "=r"(e) : "l"(arr) : "memory");
                } while (e < target);
            }
            __syncthreads();
        }
    }
}

// ---------------------------------------------------------------------------
__global__ __launch_bounds__(256) void epilogue_kernel(
    const float* __restrict__ WB, const float* __restrict__ CC,
    const int* __restrict__ actions, const float* __restrict__ Wc,
    const float* __restrict__ bc,
    const __nv_bfloat16* __restrict__ HBH, const __nv_bfloat16* __restrict__ HBL,
    float* __restrict__ out)
{
    int wid = threadIdx.x >> 5, lane = threadIdx.x & 31;
    long idx = (long)blockIdx.x * 8 + wid;
    int t = (int)(idx / N_), n = (int)(idx % N_);
    float cc = CC[idx];
    long base = idx * OUTW_;

    const __nv_bfloat162* hv = (const __nv_bfloat162*)(HBH + idx * 256 + lane * 8);
    const __nv_bfloat162* lv = (const __nv_bfloat162*)(HBL + idx * 256 + lane * 8);
    float h[8];
#pragma unroll
    for (int i = 0; i < 4; i++) {
        float2 fh = __bfloat1622float2(hv[i]);
        float2 fl = __bfloat1622float2(lv[i]);
        h[2 * i] = fh.x + fl.x;
        h[2 * i + 1] = fh.y + fl.y;
    }
    float2* hdst = (float2*)(out + base + 2 + lane * 8);
#pragma unroll
    for (int i = 0; i < 4; i++) hdst[i] = make_float2(h[2 * i], h[2 * i + 1]);

    const float4* wc = (const float4*)Wc;
    float4 c0 = wc[lane * 2], c1 = wc[lane * 2 + 1];
    float d = h[0] * c0.x + h[1] * c0.y + h[2] * c0.z + h[3] * c0.w
            + h[4] * c1.x + h[5] * c1.y + h[6] * c1.z + h[7] * c1.w;
#pragma unroll
    for (int o = 16; o; o >>= 1) d += __shfl_xor_sync(~0u, d, o);

    const float4* wrow = (const float4*)(WB + ((long)n * T_ + t) * L_);
    float4 w0 = wrow[lane * 2], w1 = wrow[lane * 2 + 1];
    float wv[8] = {w0.x * cc, w0.y * cc, w0.z * cc, w0.w * cc,
                   w1.x * cc, w1.y * cc, w1.z * cc, w1.w * cc};
    float mx = wv[0];
#pragma unroll
    for (int i = 1; i < 8; i++) mx = fmaxf(mx, wv[i]);
#pragma unroll
    for (int o = 16; o; o >>= 1) mx = fmaxf(mx, __shfl_xor_sync(~0u, mx, o));
    float e[8], s = 0.f;
#pragma unroll
    for (int i = 0; i < 8; i++) { e[i] = expf(wv[i] - mx); s += e[i]; }
#pragma unroll
    for (int o = 16; o; o >>= 1) s += __shfl_xor_sync(~0u, s, o);
    float inv = 1.f / s;

    int a = actions[idx];
    float2* pdst = (float2*)(out + base + 258 + lane * 8);
    float2* odst = (float2*)(out + base + 514 + lane * 8);
#pragma unroll
    for (int i = 0; i < 4; i++) {
        pdst[i] = make_float2(e[2 * i] * inv, e[2 * i + 1] * inv);
        int l0 = lane * 8 + 2 * i;
        odst[i] = make_float2(l0 == a ? 1.f : 0.f, l0 + 1 == a ? 1.f : 0.f);
    }
    if (lane == 0) {
        out[base + 0] = (float)a;
        out[base + 1] = d + bc[0];
    }
}

// ---------------------------------------------------------------------------
extern "C" void kernel_launch(void* const* d_in, const int* in_sizes, int n_in,
                              void* d_out, int out_size)
{
    const float* cond = (const float*)d_in[0];
    const float* M    = (const float*)d_in[1];
    const float* Km   = (const float*)d_in[2];
    const float* Cm   = (const float*)d_in[3];
    const float* h0   = (const float*)d_in[4];
    const float* p0   = (const float*)d_in[5];
    const float* W0   = (const float*)d_in[6];
    const float* b0   = (const float*)d_in[7];
    const float* W1   = (const float*)d_in[8];
    const float* b1   = (const float*)d_in[9];
    const float* W2   = (const float*)d_in[10];
    const float* b2   = (const float*)d_in[11];
    const float* W_ih = (const float*)d_in[12];
    const float* W_hh = (const float*)d_in[13];
    const float* b_ih = (const float*)d_in[14];
    const float* b_hh = (const float*)d_in[15];
    const float* Wa   = (const float*)d_in[16];
    const float* ba   = (const float*)d_in[17];
    const float* Wc   = (const float*)d_in[18];
    const float* bc   = (const float*)d_in[19];
    const int* actions = (const int*)d_in[20];
    float* out = (float*)d_out;

    float* base = nullptr;
    cudaGetSymbolAddress((void**)&base, g_scratch);
    __nv_bfloat16* XINH = (__nv_bfloat16*)(base + XINH_OFF);
    __nv_bfloat16* XINL = (__nv_bfloat16*)(base + XINL_OFF);
    __nv_bfloat16* XAH = (__nv_bfloat16*)(base + XAH_OFF);
    __nv_bfloat16* XAL = (__nv_bfloat16*)(base + XAL_OFF);
    __nv_bfloat16* XBH = (__nv_bfloat16*)(base + XBH_OFF);
    __nv_bfloat16* XBL = (__nv_bfloat16*)(base + XBL_OFF);
    float* GI = base + GI_OFF;
    __nv_bfloat16* KBH = (__nv_bfloat16*)(base + KBH_OFF);
    __nv_bfloat16* KBL = (__nv_bfloat16*)(base + KBL_OFF);
    float* WB = base + WB_OFF;
    float* CC = base + CC_OFF;
    __nv_bfloat16* WT = (__nv_bfloat16*)(base + WT_OFF);
    __nv_bfloat16* HBH = (__nv_bfloat16*)(base + HBH_OFF);
    __nv_bfloat16* HBL = (__nv_bfloat16*)(base + HBL_OFF);
    __nv_bfloat16* HB0H = (__nv_bfloat16*)(base + HB0H_OFF);
    __nv_bfloat16* HB0L = (__nv_bfloat16*)(base + HB0L_OFF);

    void* bar_addr = nullptr;
    cudaGetSymbolAddress(&bar_addr, g_bar2);

    cudaFuncSetAttribute(gru_tc,
                         cudaFuncAttributeMaxDynamicSharedMemorySize, GRU_SMEM2);
    cudaFuncSetAttribute(gemm_v2<true, true>,
                         cudaFuncAttributeMaxDynamicSharedMemorySize, GEMM2_SMEM);
    cudaFuncSetAttribute(gemm_v2<false, false>,
                         cudaFuncAttributeMaxDynamicSharedMemorySize, GEMM2_SMEM);
    cudaFuncSetAttribute(gemm_v2<false, true>,
                         cudaFuncAttributeMaxDynamicSharedMemorySize, GEMM2_SMEM);

    // phase 0: weight/h0 conversion
    convert_wall<<<2112, 256>>>(W0, W1, W2, W_ih, Wa, h0, WT, HB0H, HB0L);

    // phase A (activations carried as bf16 hi/lo)
    t0_kernel<<<N_, 256>>>(p0, M, Cm, XINH, XINL, CC);
    gather_kernel<<<ROWS_ / 8, 256>>>(cond, M, Cm, actions, XINH, XINL, CC);
    gemm_v2<true, true><<<dim3(ROWS_ / 128, 2), 256, GEMM2_SMEM>>>(
        XINH, XINL, WT + W0H, WT + W0L, b0, nullptr, XAH, XAL, 320, 320, 256);
    gemm_v2<true, true><<<dim3(ROWS_ / 128, 2), 256, GEMM2_SMEM>>>(
        XAH, XAL, WT + W1H, WT + W1L, b1, nullptr, XBH, XBL, 256, 256, 256);
    gemm_v2<true, true><<<dim3(ROWS_ / 128, 2), 256, GEMM2_SMEM>>>(
        XBH, XBL, WT + W2H, WT + W2L, b2, nullptr, XAH, XAL, 256, 256, 256);
    gemm_v2<false, false><<<dim3(ROWS_ / 128, 6), 256, GEMM2_SMEM>>>(
        XAH, XAL, WT + WIHH, WT + WIHL, b_ih, GI, nullptr, nullptr, 256, 256, 768);

    // phase B: persistent tensor-core GRU
    cudaMemsetAsync(bar_addr, 0, 8 * 32 * sizeof(unsigned));
    gru_tc<<<128, GRU_THREADS, GRU_SMEM2>>>(GI, h0, W_hh, b_hh, HB0H, HB0L, HBH, HBL);

    // phase C
    gemm_v2<false, true><<<dim3(ROWS_ / 128, 2), 256, GEMM2_SMEM>>>(
        HBH, HBL, WT + WAH, WT + WAL, ba, nullptr, KBH, KBL, 256, 256, 256);
    gemm_km<<<dim3(1, 2, 256), 256, BGEMM_SMEM>>>(
        KBH, KBL, Km, WB, 256, 256, 256, 256,
        (long)T_ * 256, (long)L_ * H_, (long)T_ * L_);
    epilogue_kernel<<<ROWS_ / 8, 256>>>(WB, CC, actions, Wc, bc, HBH, HBL, out);
}

// round 13
// speedup vs baseline: 2.5797x; 1.0054x over previous
#include <cuda_runtime.h>
#include <cuda_bf16.h>
#include <math.h>

#define T_ 128
#define N_ 256
#define L_ 256
#define H_ 256
#define COND_ 64
#define ROWS_ (T_ * N_)   // 32768
#define OUTW_ 770

typedef unsigned long long u64;
typedef unsigned u32;

// ---------------- scratch (float units) --------------------------------------
#define XINH_OFF 0L                               // [ROWS][320] bf16
#define XINL_OFF (XINH_OFF + (long)ROWS_ * 160)
#define XAH_OFF  (XINL_OFF + (long)ROWS_ * 160)   // [ROWS][256] bf16
#define XAL_OFF  (XAH_OFF + (long)ROWS_ * 128)
#define XBH_OFF  (XAL_OFF + (long)ROWS_ * 128)
#define XBL_OFF  (XBH_OFF + (long)ROWS_ * 128)
#define GI_OFF   (XBL_OFF + (long)ROWS_ * 128)    // fp32 [ROWS][768]
#define KBH_OFF  (GI_OFF + (long)ROWS_ * 768)
#define KBL_OFF  (KBH_OFF + (long)ROWS_ * 128)
#define WB_OFF   (KBL_OFF + (long)ROWS_ * 128)    // fp32 [N][T][L]
#define CC_OFF   (WB_OFF + (long)ROWS_ * 256)
#define WT_OFF   (CC_OFF + (long)ROWS_)
#define WT_FLOATS 475136L
#define HBH_OFF  (WT_OFF + WT_FLOATS)
#define HBL_OFF  (HBH_OFF + 4194304L)
#define HB0H_OFF (HBL_OFF + 4194304L)
#define HB0L_OFF (HB0H_OFF + 32768L)
#define SCRATCH_FLOATS (HB0L_OFF + 32768L)

__device__ float g_scratch[SCRATCH_FLOATS];
__device__ unsigned g_bar2[8 * 32];   // per-nt arrive counters (monotonic)

// bf16 weight-buffer offsets (bf16 element units inside WT)
#define W0H 0
#define W0L 81920
#define W1H 163840
#define W1L 229376
#define W2H 294912
#define W2L 360448
#define WIHH 425984
#define WIHL 622592
#define WAH 819200
#define WAL 884736

// ---------------- bf16 helpers ------------------------------------------------
__device__ __forceinline__ void cvt_split(float x0, float x1, u32& h, u32& l) {
    u32 hh;
    asm("cvt.rn.bf16x2.f32 %0, %1, %2;" : "=r"(hh) : "f"(x1), "f"(x0));
    float r0 = x0 - __uint_as_float(hh << 16);
    float r1 = x1 - __uint_as_float(hh & 0xFFFF0000u);
    u32 ll;
    asm("cvt.rn.bf16x2.f32 %0, %1, %2;" : "=r"(ll) : "f"(r1), "f"(r0));
    h = hh; l = ll;
}
__device__ __forceinline__ void ldsm_x4(u32& r0, u32& r1, u32& r2, u32& r3, u32 a) {
    asm volatile("ldmatrix.sync.aligned.m8n8.x4.shared.b16 {%0,%1,%2,%3}, [%4];"
                 : "=r"(r0), "=r"(r1), "=r"(r2), "=r"(r3) : "r"(a));
}
__device__ __forceinline__ void ldsm_x2(u32& r0, u32& r1, u32 a) {
    asm volatile("ldmatrix.sync.aligned.m8n8.x2.shared.b16 {%0,%1}, [%2];"
                 : "=r"(r0), "=r"(r1) : "r"(a));
}
__device__ __forceinline__ void mma_bf16(float* d, const u32* a, const u32* b) {
    asm volatile(
        "mma.sync.aligned.m16n8k16.row.col.f32.bf16.bf16.f32 "
        "{%0,%1,%2,%3}, {%4,%5,%6,%7}, {%8,%9}, {%0,%1,%2,%3};"
        : "+f"(d[0]), "+f"(d[1]), "+f"(d[2]), "+f"(d[3])
        : "r"(a[0]), "r"(a[1]), "r"(a[2]), "r"(a[3]), "r"(b[0]), "r"(b[1]));
}
#define CPA16(d, s) \
    asm volatile("cp.async.ca.shared.global [%0], [%1], 16;" :: "r"(d), "l"(s))
#define CPC() asm volatile("cp.async.commit_group;" ::: "memory")

// ---------------------------------------------------------------------------
// fused weight/h0 conversion (one launch)
__global__ __launch_bounds__(256) void convert_wall(
    const float* __restrict__ W0, const float* __restrict__ W1,
    const float* __restrict__ W2, const float* __restrict__ W_ih,
    const float* __restrict__ Wa, const float* __restrict__ h0,
    __nv_bfloat16* __restrict__ WT,
    __nv_bfloat16* __restrict__ HB0H, __nv_bfloat16* __restrict__ HB0L)
{
    int b = blockIdx.x, tid = threadIdx.x;
    const float* src; __nv_bfloat16 *dh, *dl;
    int K, Nn, tr, e;
    if (b < 320)        { src = W0;   dh = WT + W0H;  dl = WT + W0L;  K = 320; Nn = 256; tr = 1; e = b * 256 + tid; }
    else if (b < 576)   { src = W1;   dh = WT + W1H;  dl = WT + W1L;  K = 256; Nn = 256; tr = 1; e = (b - 320) * 256 + tid; }
    else if (b < 832)   { src = W2;   dh = WT + W2H;  dl = WT + W2L;  K = 256; Nn = 256; tr = 1; e = (b - 576) * 256 + tid; }
    else if (b < 1600)  { src = W_ih; dh = WT + WIHH; dl = WT + WIHL; K = 256; Nn = 768; tr = 0; e = (b - 832) * 256 + tid; }
    else if (b < 1856)  { src = Wa;   dh = WT + WAH;  dl = WT + WAL;  K = 256; Nn = 256; tr = 1; e = (b - 1600) * 256 + tid; }
    else                { src = h0;   dh = HB0H;      dl = HB0L;      K = 256; Nn = 256; tr = 0; e = (b - 1856) * 256 + tid; }
    int n = e / K, k = e % K;
    float v = tr ? src[(long)k * Nn + n] : src[e];
    __nv_bfloat16 h = __float2bfloat16(v);
    dh[e] = h;
    dl[e] = __float2bfloat16(v - __bfloat162float(h));
}

// ---------------------------------------------------------------------------
__global__ __launch_bounds__(256) void t0_kernel(
    const float* __restrict__ p0, const float* __restrict__ M,
    const float* __restrict__ C, __nv_bfloat16* __restrict__ XINH,
    __nv_bfloat16* __restrict__ XINL, float* __restrict__ CC)
{
    int n = blockIdx.x;
    int tid = threadIdx.x;
    float v = p0[(long)n * L_ + tid];
    int any = __syncthreads_or(v != 0.f);
    float acc;
    if (!any) {
        acc = M[(long)n * L_ * H_ + tid];
        if (tid == 0) CC[n] = C[(long)n * L_];
    } else {
        __shared__ float red[256];
        __shared__ float ps[256];
        ps[tid] = v;
        __syncthreads();
        acc = 0.f;
        const float* Mn = M + (long)n * L_ * H_;
        for (int l = 0; l < L_; l++)
            acc = fmaf(ps[l], Mn[(long)l * H_ + tid], acc);
        red[tid] = ps[tid] * C[(long)n * L_ + tid];
        __syncthreads();
        for (int s = 128; s > 0; s >>= 1) {
            if (tid < s) red[tid] += red[tid + s];
            __syncthreads();
        }
        if (tid == 0) CC[n] = red[0];
    }
    __nv_bfloat16 h = __float2bfloat16(acc);
    XINH[(long)n * 320 + 64 + tid] = h;
    XINL[(long)n * 320 + 64 + tid] = __float2bfloat16(acc - __bfloat162float(h));
}

// ---------------------------------------------------------------------------
__global__ __launch_bounds__(256) void gather_kernel(
    const float* __restrict__ cond, const float* __restrict__ M,
    const float* __restrict__ C, const int* __restrict__ actions,
    __nv_bfloat16* __restrict__ XINH, __nv_bfloat16* __restrict__ XINL,
    float* __restrict__ CC)
{
    int r = threadIdx.x >> 5, lane = threadIdx.x & 31;
    long idx = (long)blockIdx.x * 8 + r;
    int t = (int)(idx / N_), n = (int)(idx % N_);
    char* dh = (char*)(XINH + idx * 320);
    char* dl = (char*)(XINL + idx * 320);
    if (lane < 16) {
        float4 v = ((const float4*)(cond + idx * COND_))[lane];
        u32 h01, l01, h23, l23;
        cvt_split(v.x, v.y, h01, l01);
        cvt_split(v.z, v.w, h23, l23);
        *(uint2*)(dh + lane * 8) = make_uint2(h01, h23);
        *(uint2*)(dl + lane * 8) = make_uint2(l01, l23);
    }
    if (t > 0) {
        int a = actions[idx - N_];
        const float4* msrc = (const float4*)(M + ((long)n * L_ + a) * H_);
#pragma unroll
        for (int i = 0; i < 2; i++) {
            float4 v = msrc[lane + i * 32];
            u32 h01, l01, h23, l23;
            cvt_split(v.x, v.y, h01, l01);
            cvt_split(v.z, v.w, h23, l23);
            int boff = 128 + lane * 8 + i * 256;
            *(uint2*)(dh + boff) = make_uint2(h01, h23);
            *(uint2*)(dl + boff) = make_uint2(l01, l23);
        }
        if (lane == 0) CC[idx] = C[(long)n * L_ + a];
    }
}

// ---------------------------------------------------------------------------
// gemm_v3: bf16x3 tensor-core GEMM, A+B pre-split, 3-stage cp.async pipeline,
// ONE __syncthreads per k-iter. Tile 128x128, BK=32, 8 warps.
#define GEMM3_SMEM 98304

template <bool RELU, bool OUTSPLIT>
__global__ __launch_bounds__(256, 2) void gemm_v3(
    const __nv_bfloat16* __restrict__ Ah, const __nv_bfloat16* __restrict__ Al,
    const __nv_bfloat16* __restrict__ Bh, const __nv_bfloat16* __restrict__ Bl,
    const float* __restrict__ bias, float* __restrict__ C,
    __nv_bfloat16* __restrict__ Ch, __nv_bfloat16* __restrict__ Cl,
    int K, int lda, int ldc)
{
    extern __shared__ char smx[];
    u32 sb32 = (u32)__cvta_generic_to_shared(smx);

    int m0 = blockIdx.x * 128, n0 = blockIdx.y * 128;
    int tid = threadIdx.x;
    int wid = tid >> 5, lane = tid & 31;
    int warp_m = wid & 1, warp_n = wid >> 1;
    int gid = lane >> 2, tg = lane & 3;

    int sm_[2], sc_[2];
#pragma unroll
    for (int j = 0; j < 2; j++) {
        int idx = tid + j * 256;
        sm_[j] = idx >> 2; sc_[j] = idx & 3;
    }

    int rowa = warp_m * 64 + (lane & 15);
    int rsa = (rowa >> 1) & 3;
    int ha = lane >> 4;
    int rowb = warp_n * 32 + (lane & 7);
    int rsb = (rowb >> 1) & 3;
    int hb = (lane >> 3) & 1;

    float acc[4][4][4];
#pragma unroll
    for (int i = 0; i < 4; i++)
#pragma unroll
        for (int j = 0; j < 4; j++)
#pragma unroll
            for (int v = 0; v < 4; v++) acc[i][j][v] = 0.f;

    auto stage = [&](int buf, int k0) {
        u32 base = sb32 + buf * 32768;
#pragma unroll
        for (int j = 0; j < 2; j++) {
            int m = sm_[j], c = sc_[j];
            u32 off = m * 64 + ((c ^ ((m >> 1) & 3)) * 16);
            long aoff = (long)(m0 + m) * lda + k0 + c * 8;
            long boff = (long)(n0 + m) * K + k0 + c * 8;
            CPA16(base + off, Ah + aoff);
            CPA16(base + off + 8192, Al + aoff);
            CPA16(base + off + 16384, Bh + boff);
            CPA16(base + off + 24576, Bl + boff);
        }
        CPC();
    };

    int nk = K / 32;
    stage(0, 0);
    if (nk > 1) stage(1, 32); else CPC();

    for (int kt = 0; kt < nk; kt++) {
        asm volatile("cp.async.wait_group 1;" ::: "memory");
        __syncthreads();                   // single barrier per k-iter

        u32 sbb = sb32 + (kt % 3) * 32768;
#pragma unroll
        for (int ks = 0; ks < 2; ks++) {
            u32 bhf[4][2], blf[4][2];
#pragma unroll
            for (int ni = 0; ni < 4; ni++) {
                int cb = (ks * 2 + hb) ^ rsb;
                u32 addr = sbb + 16384 + (rowb + ni * 8) * 64 + cb * 16;
                ldsm_x2(bhf[ni][0], bhf[ni][1], addr);
                ldsm_x2(blf[ni][0], blf[ni][1], addr + 8192);
            }
#pragma unroll
            for (int mi = 0; mi < 4; mi++) {
                int ca = (ks * 2 + ha) ^ rsa;
                u32 addr = sbb + (rowa + mi * 16) * 64 + ca * 16;
                u32 ah[4], al[4];
                ldsm_x4(ah[0], ah[1], ah[2], ah[3], addr);
                ldsm_x4(al[0], al[1], al[2], al[3], addr + 8192);
#pragma unroll
                for (int ni = 0; ni < 4; ni++) {
                    mma_bf16(acc[mi][ni], ah, bhf[ni]);
                    mma_bf16(acc[mi][ni], ah, blf[ni]);
                    mma_bf16(acc[mi][ni], al, bhf[ni]);
                }
            }
        }
        if (kt + 2 < nk) stage((kt + 2) % 3, (kt + 2) * 32);
        else CPC();                        // uniform group accounting
    }

#pragma unroll
    for (int mi = 0; mi < 4; mi++) {
        int mbase = m0 + warp_m * 64 + mi * 16;
#pragma unroll
        for (int ni = 0; ni < 4; ni++) {
            int col = n0 + warp_n * 32 + ni * 8 + tg * 2;
            float b0 = 0.f, b1 = 0.f;
            if (bias) { b0 = bias[col]; b1 = bias[col + 1]; }
            float v0 = acc[mi][ni][0] + b0, v1 = acc[mi][ni][1] + b1;
            float v2 = acc[mi][ni][2] + b0, v3 = acc[mi][ni][3] + b1;
            if (RELU) {
                v0 = fmaxf(v0, 0.f); v1 = fmaxf(v1, 0.f);
                v2 = fmaxf(v2, 0.f); v3 = fmaxf(v3, 0.f);
            }
            if (OUTSPLIT) {
                u32 h01, l01;
                long o0 = (long)(mbase + gid) * ldc + col;
                long o1 = (long)(mbase + gid + 8) * ldc + col;
                cvt_split(v0, v1, h01, l01);
                *(u32*)(Ch + o0) = h01;
                *(u32*)(Cl + o0) = l01;
                cvt_split(v2, v3, h01, l01);
                *(u32*)(Ch + o1) = h01;
                *(u32*)(Cl + o1) = l01;
            } else {
                *(float2*)&C[(long)(mbase + gid) * ldc + col] = make_float2(v0, v1);
                *(float2*)&C[(long)(mbase + gid + 8) * ldc + col] = make_float2(v2, v3);
            }
        }
    }
}

// ---------------------------------------------------------------------------
// Km GEMM (R11-proven): A pre-split, B fp32 (cvt in staging), batched via z.
#define BGEMM_SMEM 32768

__global__ __launch_bounds__(256) void gemm_km(
    const __nv_bfloat16* __restrict__ Ah, const __nv_bfloat16* __restrict__ Al,
    const float* __restrict__ Bf, float* __restrict__ C,
    int K, int lda, int ldb, int ldc, long batchA, long batchB, long batchC)
{
    extern __shared__ char smx[];
    u32 sb32 = (u32)__cvta_generic_to_shared(smx);

    long bz = blockIdx.z;
    Ah += bz * batchA; Al += bz * batchA;
    Bf += bz * batchB; C += bz * batchC;

    int m0 = blockIdx.x * 128, n0 = blockIdx.y * 128;
    int tid = threadIdx.x;
    int wid = tid >> 5, lane = tid & 31;
    int warp_m = wid & 1, warp_n = wid >> 1;
    int gid = lane >> 2, tg = lane & 3;

    int bm[4], bq[4], an2[2], ac2[2];
#pragma unroll
    for (int j = 0; j < 4; j++) {
        int idx = tid + j * 256;
        bm[j] = idx >> 3; bq[j] = idx & 7;
    }
#pragma unroll
    for (int j = 0; j < 2; j++) {
        int idx = tid + j * 256;
        an2[j] = idx >> 2; ac2[j] = idx & 3;
    }

    int rowa = warp_m * 64 + (lane & 15);
    int rsa = (rowa >> 1) & 3;
    int ha = lane >> 4;
    int rowb = warp_n * 32 + (lane & 7);
    int rsb = (rowb >> 1) & 3;
    int hb = (lane >> 3) & 1;

    float acc[4][4][4];
#pragma unroll
    for (int i = 0; i < 4; i++)
#pragma unroll
        for (int j = 0; j < 4; j++)
#pragma unroll
            for (int v = 0; v < 4; v++) acc[i][j][v] = 0.f;

    auto store_a_pre = [&](int m, int c, uint4 h, uint4 l) {
        char* p = smx + m * 64 + ((c ^ ((m >> 1) & 3)) * 16);
        *(uint4*)p = h;
        *(uint4*)(p + 8192) = l;
    };
    auto store_b_f32 = [&](int m, int q, float4 v) {
        u32 h01, l01, h23, l23;
        cvt_split(v.x, v.y, h01, l01);
        cvt_split(v.z, v.w, h23, l23);
        char* p = smx + 16384 + m * 64 + (((q >> 1) ^ ((m >> 1) & 3)) * 16) + (q & 1) * 8;
        *(uint2*)p = make_uint2(h01, h23);
        *(uint2*)(p + 8192) = make_uint2(l01, l23);
    };

#pragma unroll
    for (int j = 0; j < 2; j++) {
        long off = (long)(m0 + an2[j]) * lda + ac2[j] * 8;
        store_a_pre(an2[j], ac2[j], *(const uint4*)(Ah + off), *(const uint4*)(Al + off));
    }
#pragma unroll
    for (int j = 0; j < 4; j++) {
        float4 v = *(const float4*)&Bf[(long)(n0 + bm[j]) * ldb + bq[j] * 4];
        store_b_f32(bm[j], bq[j], v);
    }
    __syncthreads();

    int nk = K / 32;
    for (int kt = 0; kt < nk; kt++) {
        float4 rbf[4];
        uint4 rah[2], ral[2];
        bool nxt = (kt + 1 < nk);
        if (nxt) {
            int k0 = (kt + 1) * 32;
#pragma unroll
            for (int j = 0; j < 2; j++) {
                long off = (long)(m0 + an2[j]) * lda + k0 + ac2[j] * 8;
                rah[j] = *(const uint4*)(Ah + off);
                ral[j] = *(const uint4*)(Al + off);
            }
#pragma unroll
            for (int j = 0; j < 4; j++)
                rbf[j] = *(const float4*)&Bf[(long)(n0 + bm[j]) * ldb + k0 + bq[j] * 4];
        }

#pragma unroll
        for (int ks = 0; ks < 2; ks++) {
            u32 bhf[4][2], blf[4][2];
#pragma unroll
            for (int ni = 0; ni < 4; ni++) {
                int cb = (ks * 2 + hb) ^ rsb;
                u32 addr = sb32 + 16384 + (rowb + ni * 8) * 64 + cb * 16;
                ldsm_x2(bhf[ni][0], bhf[ni][1], addr);
                ldsm_x2(blf[ni][0], blf[ni][1], addr + 8192);
            }
#pragma unroll
            for (int mi = 0; mi < 4; mi++) {
                int ca = (ks * 2 + ha) ^ rsa;
                u32 addr = sb32 + (rowa + mi * 16) * 64 + ca * 16;
                u32 ah[4], al[4];
                ldsm_x4(ah[0], ah[1], ah[2], ah[3], addr);
                ldsm_x4(al[0], al[1], al[2], al[3], addr + 8192);
#pragma unroll
                for (int ni = 0; ni < 4; ni++) {
                    mma_bf16(acc[mi][ni], ah, bhf[ni]);
                    mma_bf16(acc[mi][ni], ah, blf[ni]);
                    mma_bf16(acc[mi][ni], al, bhf[ni]);
                }
            }
        }
        __syncthreads();
        if (nxt) {
#pragma unroll
            for (int j = 0; j < 2; j++) store_a_pre(an2[j], ac2[j], rah[j], ral[j]);
#pragma unroll
            for (int j = 0; j < 4; j++) store_b_f32(bm[j], bq[j], rbf[j]);
        }
        __syncthreads();
    }

#pragma unroll
    for (int mi = 0; mi < 4; mi++) {
        int mbase = m0 + warp_m * 64 + mi * 16;
#pragma unroll
        for (int ni = 0; ni < 4; ni++) {
            int col = n0 + warp_n * 32 + ni * 8 + tg * 2;
            *(float2*)&C[(long)(mbase + gid) * ldc + col] =
                make_float2(acc[mi][ni][0], acc[mi][ni][1]);
            *(float2*)&C[(long)(mbase + gid + 8) * ldc + col] =
                make_float2(acc[mi][ni][2], acc[mi][ni][3]);
        }
    }
}

// ---------------------------------------------------------------------------
// persistent GRU (R11): tensor-core gh, 384 threads, one-hop barrier.
#define GRU_SMEM2 43008
#define GRU_THREADS 384

__device__ __forceinline__ float sigmf(float x) { return 1.f / (1.f + __expf(-x)); }
__device__ __forceinline__ float tanhfast(float x) { return 2.f / (1.f + __expf(-2.f * x)) - 1.f; }

__global__ __launch_bounds__(GRU_THREADS) void gru_tc(
    const float* __restrict__ GI, const float* __restrict__ h0,
    const float* __restrict__ W_hh, const float* __restrict__ b_hh,
    const __nv_bfloat16* __restrict__ HB0H, const __nv_bfloat16* __restrict__ HB0L,
    __nv_bfloat16* __restrict__ HBH, __nv_bfloat16* __restrict__ HBL)
{
    extern __shared__ char sm8[];
    u32 sb = (u32)__cvta_generic_to_shared(sm8);
    float* ghs = (float*)(sm8 + 32768);
    float* hown = (float*)(sm8 + 40960);

    int tid = threadIdx.x;
    int wid = tid >> 5, lane = tid & 31;
    int jt = blockIdx.x & 15, nt = blockIdx.x >> 4;
    int j0 = jt * 16, n0 = nt * 32;
    int colg = wid % 6, mt = wid / 6;

    unsigned* arr = &g_bar2[nt * 32];

    u32 bhf[16][2], blf[16][2];
    {
        for (int e = tid; e < 3072; e += GRU_THREADS) {
            int r = e >> 6, q = e & 63;
            float4 v = *(const float4*)&W_hh[(long)((r >> 4) * 256 + j0 + (r & 15)) * 256 + q * 4];
            u32 h01, l01, h23, l23;
            cvt_split(v.x, v.y, h01, l01);
            cvt_split(v.z, v.w, h23, l23);
            *(uint2*)(sm8 + r * 512 + (((q >> 1) ^ (r & 7)) * 16) + (q & 1) * 8) =
                make_uint2(h01, h23);
        }
        __syncthreads();
        {
            int rb = colg * 8 + (lane & 7);
            int hb2 = (lane >> 3) & 1;
#pragma unroll
            for (int s = 0; s < 16; s++) {
                u32 addr = sb + rb * 512 + (((s * 2 + hb2) ^ (rb & 7)) * 16);
                ldsm_x2(bhf[s][0], bhf[s][1], addr);
            }
        }
        __syncthreads();
        for (int e = tid; e < 3072; e += GRU_THREADS) {
            int r = e >> 6, q = e & 63;
            float4 v = *(const float4*)&W_hh[(long)((r >> 4) * 256 + j0 + (r & 15)) * 256 + q * 4];
            u32 h01, l01, h23, l23;
            cvt_split(v.x, v.y, h01, l01);
            cvt_split(v.z, v.w, h23, l23);
            *(uint2*)(sm8 + r * 512 + (((q >> 1) ^ (r & 7)) * 16) + (q & 1) * 8) =
                make_uint2(l01, l23);
        }
        __syncthreads();
        {
            int rb = colg * 8 + (lane & 7);
            int hb2 = (lane >> 3) & 1;
#pragma unroll
            for (int s = 0; s < 16; s++) {
                u32 addr = sb + rb * 512 + (((s * 2 + hb2) ^ (rb & 7)) * 16);
                ldsm_x2(blf[s][0], blf[s][1], addr);
            }
        }
        __syncthreads();
    }

    int jj = tid & 15, nb0 = (tid & 255) >> 4;
    float bhr = b_hh[j0 + jj], bhz = b_hh[256 + j0 + jj], bhn = b_hh[512 + j0 + jj];
    if (tid < 256) {
#pragma unroll
        for (int i = 0; i < 2; i++) {
            int n = nb0 + 16 * i;
            hown[n * 16 + jj] = h0[(long)(n0 + n) * H_ + j0 + jj];
        }
    }
    float gr[2], gz[2], gn[2];
    if (tid < 256) {
#pragma unroll
        for (int i = 0; i < 2; i++) {
            long base = ((long)(n0 + nb0 + 16 * i)) * 768 + j0 + jj;
            gr[i] = GI[base]; gz[i] = GI[base + 256]; gn[i] = GI[base + 512];
        }
    }
    __syncthreads();

    for (int t = 0; t < T_; t++) {
        const __nv_bfloat16* srcH = t ? HBH + (long)(t - 1) * N_ * H_ : HB0H;
        const __nv_bfloat16* srcL = t ? HBL + (long)(t - 1) * N_ * H_ : HB0L;
        for (int e = tid; e < 1024; e += GRU_THREADS) {
            int r = e >> 5, c = e & 31;
            u32 soff = r * 512 + ((c ^ (r & 7)) * 16);
            *(uint4*)(sm8 + soff) = *(const uint4*)(srcH + (long)(n0 + r) * 256 + c * 8);
            *(uint4*)(sm8 + 16384 + soff) = *(const uint4*)(srcL + (long)(n0 + r) * 256 + c * 8);
        }
        __syncthreads();

        {
            float acc[4];
#pragma unroll
            for (int v = 0; v < 4; v++) acc[v] = 0.f;
            int rr = mt * 16 + (lane & 15);
            int ha2 = lane >> 4;
#pragma unroll
            for (int s = 0; s < 16; s++) {
                u32 addr = sb + rr * 512 + (((s * 2 + ha2) ^ (rr & 7)) * 16);
                u32 ah[4], al[4];
                ldsm_x4(ah[0], ah[1], ah[2], ah[3], addr);
                ldsm_x4(al[0], al[1], al[2], al[3], addr + 16384);
                mma_bf16(acc, ah, bhf[s]);
                mma_bf16(acc, ah, blf[s]);
                mma_bf16(acc, al, bhf[s]);
            }
            int gid = lane >> 2, tg = lane & 3;
            *(float2*)&ghs[(mt * 16 + gid) * 64 + colg * 8 + tg * 2] =
                make_float2(acc[0], acc[1]);
            *(float2*)&ghs[(mt * 16 + gid + 8) * 64 + colg * 8 + tg * 2] =
                make_float2(acc[2], acc[3]);
        }
        __syncthreads();

        if (tid < 256) {
            __nv_bfloat16* bhd = HBH + (long)t * N_ * H_;
            __nv_bfloat16* bld = HBL + (long)t * N_ * H_;
#pragma unroll
            for (int i = 0; i < 2; i++) {
                int n = nb0 + 16 * i;
                float ghr = ghs[n * 64 + jj];
                float ghz = ghs[n * 64 + 16 + jj];
                float ghn = ghs[n * 64 + 32 + jj];
                float rg = sigmf(gr[i] + ghr + bhr);
                float z  = sigmf(gz[i] + ghz + bhz);
                float nv = tanhfast(gn[i] + rg * (ghn + bhn));
                float hp = hown[n * 16 + jj];
                float hn = (1.f - z) * nv + z * hp;
                hown[n * 16 + jj] = hn;
                long gofs = (long)(n0 + n) * H_ + j0 + jj;
                __nv_bfloat16 hh = __float2bfloat16(hn);
                bhd[gofs] = hh;
                bld[gofs] = __float2bfloat16(hn - __bfloat162float(hh));
            }
        }

        if (t < T_ - 1) {
            __syncthreads();
            if (tid == 0) {
                asm volatile("red.release.gpu.global.add.u32 [%0], %1;"
                             :: "l"(arr), "r"(1u) : "memory");
            }
            if (tid < 256) {
#pragma unroll
                for (int i = 0; i < 2; i++) {
                    long base = ((long)(t + 1) * N_ + n0 + nb0 + 16 * i) * 768 + j0 + jj;
                    gr[i] = GI[base]; gz[i] = GI[base + 256]; gn[i] = GI[base + 512];
                }
            }
            if (tid == 0) {
                unsigned target = (unsigned)(t + 1) * 16u;
                unsigned e;
                do {
                    asm volatile("ld.acquire.gpu.global.u32 %0, [%1];"
                                 : "=r"(e) : "l"(arr) : "memory");
                } while (e < target);
            }
            __syncthreads();
        }
    }
}

// ---------------------------------------------------------------------------
__global__ __launch_bounds__(256) void epilogue_kernel(
    const float* __restrict__ WB, const float* __restrict__ CC,
    const int* __restrict__ actions, const float* __restrict__ Wc,
    const float* __restrict__ bc,
    const __nv_bfloat16* __restrict__ HBH, const __nv_bfloat16* __restrict__ HBL,
    float* __restrict__ out)
{
    int wid = threadIdx.x >> 5, lane = threadIdx.x & 31;
    long idx = (long)blockIdx.x * 8 + wid;
    int t = (int)(idx / N_), n = (int)(idx % N_);
    float cc = CC[idx];
    long base = idx * OUTW_;

    const __nv_bfloat162* hv = (const __nv_bfloat162*)(HBH + idx * 256 + lane * 8);
    const __nv_bfloat162* lv = (const __nv_bfloat162*)(HBL + idx * 256 + lane * 8);
    float h[8];
#pragma unroll
    for (int i = 0; i < 4; i++) {
        float2 fh = __bfloat1622float2(hv[i]);
        float2 fl = __bfloat1622float2(lv[i]);
        h[2 * i] = fh.x + fl.x;
        h[2 * i + 1] = fh.y + fl.y;
    }
    float2* hdst = (float2*)(out + base + 2 + lane * 8);
#pragma unroll
    for (int i = 0; i < 4; i++) hdst[i] = make_float2(h[2 * i], h[2 * i + 1]);

    const float4* wc = (const float4*)Wc;
    float4 c0 = wc[lane * 2], c1 = wc[lane * 2 + 1];
    float d = h[0] * c0.x + h[1] * c0.y + h[2] * c0.z + h[3] * c0.w
            + h[4] * c1.x + h[5] * c1.y + h[6] * c1.z + h[7] * c1.w;
#pragma unroll
    for (int o = 16; o; o >>= 1) d += __shfl_xor_sync(~0u, d, o);

    const float4* wrow = (const float4*)(WB + ((long)n * T_ + t) * L_);
    float4 w0 = wrow[lane * 2], w1 = wrow[lane * 2 + 1];
    float wv[8] = {w0.x * cc, w0.y * cc, w0.z * cc, w0.w * cc,
                   w1.x * cc, w1.y * cc, w1.z * cc, w1.w * cc};
    float mx = wv[0];
#pragma unroll
    for (int i = 1; i < 8; i++) mx = fmaxf(mx, wv[i]);
#pragma unroll
    for (int o = 16; o; o >>= 1) mx = fmaxf(mx, __shfl_xor_sync(~0u, mx, o));
    float e[8], s = 0.f;
#pragma unroll
    for (int i = 0; i < 8; i++) { e[i] = expf(wv[i] - mx); s += e[i]; }
#pragma unroll
    for (int o = 16; o; o >>= 1) s += __shfl_xor_sync(~0u, s, o);
    float inv = 1.f / s;

    int a = actions[idx];
    float2* pdst = (float2*)(out + base + 258 + lane * 8);
    float2* odst = (float2*)(out + base + 514 + lane * 8);
#pragma unroll
    for (int i = 0; i < 4; i++) {
        pdst[i] = make_float2(e[2 * i] * inv, e[2 * i + 1] * inv);
        int l0 = lane * 8 + 2 * i;
        odst[i] = make_float2(l0 == a ? 1.f : 0.f, l0 + 1 == a ? 1.f : 0.f);
    }
    if (lane == 0) {
        out[base + 0] = (float)a;
        out[base + 1] = d + bc[0];
    }
}

// ---------------------------------------------------------------------------
extern "C" void kernel_launch(void* const* d_in, const int* in_sizes, int n_in,
                              void* d_out, int out_size)
{
    const float* cond = (const float*)d_in[0];
    const float* M    = (const float*)d_in[1];
    const float* Km   = (const float*)d_in[2];
    const float* Cm   = (const float*)d_in[3];
    const float* h0   = (const float*)d_in[4];
    const float* p0   = (const float*)d_in[5];
    const float* W0   = (const float*)d_in[6];
    const float* b0   = (const float*)d_in[7];
    const float* W1   = (const float*)d_in[8];
    const float* b1   = (const float*)d_in[9];
    const float* W2   = (const float*)d_in[10];
    const float* b2   = (const float*)d_in[11];
    const float* W_ih = (const float*)d_in[12];
    const float* W_hh = (const float*)d_in[13];
    const float* b_ih = (const float*)d_in[14];
    const float* b_hh = (const float*)d_in[15];
    const float* Wa   = (const float*)d_in[16];
    const float* ba   = (const float*)d_in[17];
    const float* Wc   = (const float*)d_in[18];
    const float* bc   = (const float*)d_in[19];
    const int* actions = (const int*)d_in[20];
    float* out = (float*)d_out;

    float* base = nullptr;
    cudaGetSymbolAddress((void**)&base, g_scratch);
    __nv_bfloat16* XINH = (__nv_bfloat16*)(base + XINH_OFF);
    __nv_bfloat16* XINL = (__nv_bfloat16*)(base + XINL_OFF);
    __nv_bfloat16* XAH = (__nv_bfloat16*)(base + XAH_OFF);
    __nv_bfloat16* XAL = (__nv_bfloat16*)(base + XAL_OFF);
    __nv_bfloat16* XBH = (__nv_bfloat16*)(base + XBH_OFF);
    __nv_bfloat16* XBL = (__nv_bfloat16*)(base + XBL_OFF);
    float* GI = base + GI_OFF;
    __nv_bfloat16* KBH = (__nv_bfloat16*)(base + KBH_OFF);
    __nv_bfloat16* KBL = (__nv_bfloat16*)(base + KBL_OFF);
    float* WB = base + WB_OFF;
    float* CC = base + CC_OFF;
    __nv_bfloat16* WT = (__nv_bfloat16*)(base + WT_OFF);
    __nv_bfloat16* HBH = (__nv_bfloat16*)(base + HBH_OFF);
    __nv_bfloat16* HBL = (__nv_bfloat16*)(base + HBL_OFF);
    __nv_bfloat16* HB0H = (__nv_bfloat16*)(base + HB0H_OFF);
    __nv_bfloat16* HB0L = (__nv_bfloat16*)(base + HB0L_OFF);

    void* bar_addr = nullptr;
    cudaGetSymbolAddress(&bar_addr, g_bar2);

    cudaFuncSetAttribute(gru_tc,
                         cudaFuncAttributeMaxDynamicSharedMemorySize, GRU_SMEM2);
    cudaFuncSetAttribute(gemm_v3<true, true>,
                         cudaFuncAttributeMaxDynamicSharedMemorySize, GEMM3_SMEM);
    cudaFuncSetAttribute(gemm_v3<false, false>,
                         cudaFuncAttributeMaxDynamicSharedMemorySize, GEMM3_SMEM);
    cudaFuncSetAttribute(gemm_v3<false, true>,
                         cudaFuncAttributeMaxDynamicSharedMemorySize, GEMM3_SMEM);

    // phase 0: weight/h0 conversion
    convert_wall<<<2112, 256>>>(W0, W1, W2, W_ih, Wa, h0, WT, HB0H, HB0L);

    // phase A (activations carried as bf16 hi/lo)
    t0_kernel<<<N_, 256>>>(p0, M, Cm, XINH, XINL, CC);
    gather_kernel<<<ROWS_ / 8, 256>>>(cond, M, Cm, actions, XINH, XINL, CC);
    gemm_v3<true, true><<<dim3(ROWS_ / 128, 2), 256, GEMM3_SMEM>>>(
        XINH, XINL, WT + W0H, WT + W0L, b0, nullptr, XAH, XAL, 320, 320, 256);
    gemm_v3<true, true><<<dim3(ROWS_ / 128, 2), 256, GEMM3_SMEM>>>(
        XAH, XAL, WT + W1H, WT + W1L, b1, nullptr, XBH, XBL, 256, 256, 256);
    gemm_v3<true, true><<<dim3(ROWS_ / 128, 2), 256, GEMM3_SMEM>>>(
        XBH, XBL, WT + W2H, WT + W2L, b2, nullptr, XAH, XAL, 256, 256, 256);
    gemm_v3<false, false><<<dim3(ROWS_ / 128, 6), 256, GEMM3_SMEM>>>(
        XAH, XAL, WT + WIHH, WT + WIHL, b_ih, GI, nullptr, nullptr, 256, 256, 768);

    // phase B: persistent tensor-core GRU
    cudaMemsetAsync(bar_addr, 0, 8 * 32 * sizeof(unsigned));
    gru_tc<<<128, GRU_THREADS, GRU_SMEM2>>>(GI, h0, W_hh, b_hh, HB0H, HB0L, HBH, HBL);

    // phase C
    gemm_v3<false, true><<<dim3(ROWS_ / 128, 2), 256, GEMM3_SMEM>>>(
        HBH, HBL, WT + WAH, WT + WAL, ba, nullptr, KBH, KBL, 256, 256, 256);
    gemm_km<<<dim3(1, 2, 256), 256, BGEMM_SMEM>>>(
        KBH, KBL, Km, WB, 256, 256, 256, 256,
        (long)T_ * 256, (long)L_ * H_, (long)T_ * L_);
    epilogue_kernel<<<ROWS_ / 8, 256>>>(WB, CC, actions, Wc, bc, HBH, HBL, out);
}

// round 15
// speedup vs baseline: 2.6615x; 1.0317x over previous
#include <cuda_runtime.h>
#include <cuda_bf16.h>
#include <math.h>

#define T_ 128
#define N_ 256
#define L_ 256
#define H_ 256
#define COND_ 64
#define ROWS_ (T_ * N_)   // 32768
#define OUTW_ 770

typedef unsigned long long u64;
typedef unsigned u32;

// ---------------- scratch (float units) --------------------------------------
#define XINH_OFF 0L                               // [ROWS][320] bf16
#define XINL_OFF (XINH_OFF + (long)ROWS_ * 160)
#define XAH_OFF  (XINL_OFF + (long)ROWS_ * 160)   // [ROWS][256] bf16
#define XAL_OFF  (XAH_OFF + (long)ROWS_ * 128)
#define XBH_OFF  (XAL_OFF + (long)ROWS_ * 128)
#define XBL_OFF  (XBH_OFF + (long)ROWS_ * 128)
#define GI_OFF   (XBL_OFF + (long)ROWS_ * 128)    // fp32 [ROWS][768]
#define KBH_OFF  (GI_OFF + (long)ROWS_ * 768)
#define KBL_OFF  (KBH_OFF + (long)ROWS_ * 128)
#define WB_OFF   (KBL_OFF + (long)ROWS_ * 128)    // fp32 [N][T][L]
#define CC_OFF   (WB_OFF + (long)ROWS_ * 256)
#define WT_OFF   (CC_OFF + (long)ROWS_)
#define WT_FLOATS 475136L
#define HBH_OFF  (WT_OFF + WT_FLOATS)
#define HBL_OFF  (HBH_OFF + 4194304L)
#define HB0H_OFF (HBL_OFF + 4194304L)
#define HB0L_OFF (HB0H_OFF + 32768L)
#define SCRATCH_FLOATS (HB0L_OFF + 32768L)

__device__ float g_scratch[SCRATCH_FLOATS];
__device__ unsigned g_bar2[8 * 32];   // per-nt arrive counters (monotonic)

// bf16 weight-buffer offsets (bf16 element units inside WT)
#define W0H 0
#define W0L 81920
#define W1H 163840
#define W1L 229376
#define W2H 294912
#define W2L 360448
#define WIHH 425984
#define WIHL 622592
#define WAH 819200
#define WAL 884736

// ---------------- bf16 helpers ------------------------------------------------
__device__ __forceinline__ void cvt_split(float x0, float x1, u32& h, u32& l) {
    u32 hh;
    asm("cvt.rn.bf16x2.f32 %0, %1, %2;" : "=r"(hh) : "f"(x1), "f"(x0));
    float r0 = x0 - __uint_as_float(hh << 16);
    float r1 = x1 - __uint_as_float(hh & 0xFFFF0000u);
    u32 ll;
    asm("cvt.rn.bf16x2.f32 %0, %1, %2;" : "=r"(ll) : "f"(r1), "f"(r0));
    h = hh; l = ll;
}
__device__ __forceinline__ void ldsm_x4(u32& r0, u32& r1, u32& r2, u32& r3, u32 a) {
    asm volatile("ldmatrix.sync.aligned.m8n8.x4.shared.b16 {%0,%1,%2,%3}, [%4];"
                 : "=r"(r0), "=r"(r1), "=r"(r2), "=r"(r3) : "r"(a));
}
__device__ __forceinline__ void ldsm_x2(u32& r0, u32& r1, u32 a) {
    asm volatile("ldmatrix.sync.aligned.m8n8.x2.shared.b16 {%0,%1}, [%2];"
                 : "=r"(r0), "=r"(r1) : "r"(a));
}
__device__ __forceinline__ void mma_bf16(float* d, const u32* a, const u32* b) {
    asm volatile(
        "mma.sync.aligned.m16n8k16.row.col.f32.bf16.bf16.f32 "
        "{%0,%1,%2,%3}, {%4,%5,%6,%7}, {%8,%9}, {%0,%1,%2,%3};"
        : "+f"(d[0]), "+f"(d[1]), "+f"(d[2]), "+f"(d[3])
        : "r"(a[0]), "r"(a[1]), "r"(a[2]), "r"(a[3]), "r"(b[0]), "r"(b[1]));
}
#define CPA16(d, s) \
    asm volatile("cp.async.cg.shared.global [%0], [%1], 16;" :: "r"(d), "l"(s))
#define CPC() asm volatile("cp.async.commit_group;" ::: "memory")

// ---------------------------------------------------------------------------
// fused weight/h0 conversion (one launch)
__global__ __launch_bounds__(256) void convert_wall(
    const float* __restrict__ W0, const float* __restrict__ W1,
    const float* __restrict__ W2, const float* __restrict__ W_ih,
    const float* __restrict__ Wa, const float* __restrict__ h0,
    __nv_bfloat16* __restrict__ WT,
    __nv_bfloat16* __restrict__ HB0H, __nv_bfloat16* __restrict__ HB0L)
{
    int b = blockIdx.x, tid = threadIdx.x;
    const float* src; __nv_bfloat16 *dh, *dl;
    int K, Nn, tr, e;
    if (b < 320)        { src = W0;   dh = WT + W0H;  dl = WT + W0L;  K = 320; Nn = 256; tr = 1; e = b * 256 + tid; }
    else if (b < 576)   { src = W1;   dh = WT + W1H;  dl = WT + W1L;  K = 256; Nn = 256; tr = 1; e = (b - 320) * 256 + tid; }
    else if (b < 832)   { src = W2;   dh = WT + W2H;  dl = WT + W2L;  K = 256; Nn = 256; tr = 1; e = (b - 576) * 256 + tid; }
    else if (b < 1600)  { src = W_ih; dh = WT + WIHH; dl = WT + WIHL; K = 256; Nn = 768; tr = 0; e = (b - 832) * 256 + tid; }
    else if (b < 1856)  { src = Wa;   dh = WT + WAH;  dl = WT + WAL;  K = 256; Nn = 256; tr = 1; e = (b - 1600) * 256 + tid; }
    else                { src = h0;   dh = HB0H;      dl = HB0L;      K = 256; Nn = 256; tr = 0; e = (b - 1856) * 256 + tid; }
    int n = e / K, k = e % K;
    float v = tr ? src[(long)k * Nn + n] : src[e];
    __nv_bfloat16 h = __float2bfloat16(v);
    dh[e] = h;
    dl[e] = __float2bfloat16(v - __bfloat162float(h));
}

// ---------------------------------------------------------------------------
__global__ __launch_bounds__(256) void t0_kernel(
    const float* __restrict__ p0, const float* __restrict__ M,
    const float* __restrict__ C, __nv_bfloat16* __restrict__ XINH,
    __nv_bfloat16* __restrict__ XINL, float* __restrict__ CC)
{
    int n = blockIdx.x;
    int tid = threadIdx.x;
    float v = p0[(long)n * L_ + tid];
    int any = __syncthreads_or(v != 0.f);
    float acc;
    if (!any) {
        acc = M[(long)n * L_ * H_ + tid];
        if (tid == 0) CC[n] = C[(long)n * L_];
    } else {
        __shared__ float red[256];
        __shared__ float ps[256];
        ps[tid] = v;
        __syncthreads();
        acc = 0.f;
        const float* Mn = M + (long)n * L_ * H_;
        for (int l = 0; l < L_; l++)
            acc = fmaf(ps[l], Mn[(long)l * H_ + tid], acc);
        red[tid] = ps[tid] * C[(long)n * L_ + tid];
        __syncthreads();
        for (int s = 128; s > 0; s >>= 1) {
            if (tid < s) red[tid] += red[tid + s];
            __syncthreads();
        }
        if (tid == 0) CC[n] = red[0];
    }
    __nv_bfloat16 h = __float2bfloat16(acc);
    XINH[(long)n * 320 + 64 + tid] = h;
    XINL[(long)n * 320 + 64 + tid] = __float2bfloat16(acc - __bfloat162float(h));
}

// ---------------------------------------------------------------------------
__global__ __launch_bounds__(256) void gather_kernel(
    const float* __restrict__ cond, const float* __restrict__ M,
    const float* __restrict__ C, const int* __restrict__ actions,
    __nv_bfloat16* __restrict__ XINH, __nv_bfloat16* __restrict__ XINL,
    float* __restrict__ CC)
{
    int r = threadIdx.x >> 5, lane = threadIdx.x & 31;
    long idx = (long)blockIdx.x * 8 + r;
    int t = (int)(idx / N_), n = (int)(idx % N_);
    char* dh = (char*)(XINH + idx * 320);
    char* dl = (char*)(XINL + idx * 320);
    if (lane < 16) {
        float4 v = ((const float4*)(cond + idx * COND_))[lane];
        u32 h01, l01, h23, l23;
        cvt_split(v.x, v.y, h01, l01);
        cvt_split(v.z, v.w, h23, l23);
        *(uint2*)(dh + lane * 8) = make_uint2(h01, h23);
        *(uint2*)(dl + lane * 8) = make_uint2(l01, l23);
    }
    if (t > 0) {
        int a = actions[idx - N_];
        const float4* msrc = (const float4*)(M + ((long)n * L_ + a) * H_);
#pragma unroll
        for (int i = 0; i < 2; i++) {
            float4 v = msrc[lane + i * 32];
            u32 h01, l01, h23, l23;
            cvt_split(v.x, v.y, h01, l01);
            cvt_split(v.z, v.w, h23, l23);
            int boff = 128 + lane * 8 + i * 256;
            *(uint2*)(dh + boff) = make_uint2(h01, h23);
            *(uint2*)(dl + boff) = make_uint2(l01, l23);
        }
        if (lane == 0) CC[idx] = C[(long)n * L_ + a];
    }
}

// ---------------------------------------------------------------------------
// gemm_v4: bf16x3 mma.sync GEMM, A+B pre-split, 3-stage cp.async pipeline with
// EARLY stage issue (prefetch gets a full compute window). One sync per k-iter.
#define GEMM3_SMEM 98304

template <bool RELU, bool OUTSPLIT>
__global__ __launch_bounds__(256, 2) void gemm_v4(
    const __nv_bfloat16* __restrict__ Ah, const __nv_bfloat16* __restrict__ Al,
    const __nv_bfloat16* __restrict__ Bh, const __nv_bfloat16* __restrict__ Bl,
    const float* __restrict__ bias, float* __restrict__ C,
    __nv_bfloat16* __restrict__ Ch, __nv_bfloat16* __restrict__ Cl,
    int K, int lda, int ldc)
{
    extern __shared__ char smx[];
    u32 sb32 = (u32)__cvta_generic_to_shared(smx);

    int m0 = blockIdx.x * 128, n0 = blockIdx.y * 128;
    int tid = threadIdx.x;
    int wid = tid >> 5, lane = tid & 31;
    int warp_m = wid & 1, warp_n = wid >> 1;
    int gid = lane >> 2, tg = lane & 3;

    int sm_[2], sc_[2];
#pragma unroll
    for (int j = 0; j < 2; j++) {
        int idx = tid + j * 256;
        sm_[j] = idx >> 2; sc_[j] = idx & 3;
    }

    int rowa = warp_m * 64 + (lane & 15);
    int rsa = (rowa >> 1) & 3;
    int ha = lane >> 4;
    int rowb = warp_n * 32 + (lane & 7);
    int rsb = (rowb >> 1) & 3;
    int hb = (lane >> 3) & 1;

    float acc[4][4][4];
#pragma unroll
    for (int i = 0; i < 4; i++)
#pragma unroll
        for (int j = 0; j < 4; j++)
#pragma unroll
            for (int v = 0; v < 4; v++) acc[i][j][v] = 0.f;

    auto stage = [&](int buf, int k0) {
        u32 base = sb32 + buf * 32768;
#pragma unroll
        for (int j = 0; j < 2; j++) {
            int m = sm_[j], c = sc_[j];
            u32 off = m * 64 + ((c ^ ((m >> 1) & 3)) * 16);
            long aoff = (long)(m0 + m) * lda + k0 + c * 8;
            long boff = (long)(n0 + m) * K + k0 + c * 8;
            CPA16(base + off, Ah + aoff);
            CPA16(base + off + 8192, Al + aoff);
            CPA16(base + off + 16384, Bh + boff);
            CPA16(base + off + 24576, Bl + boff);
        }
        CPC();
    };

    int nk = K / 32;
    stage(0, 0);
    if (nk > 1) stage(1, 32); else CPC();

    for (int kt = 0; kt < nk; kt++) {
        asm volatile("cp.async.wait_group 1;" ::: "memory");
        __syncthreads();                   // stage(kt) landed; buf (kt+2)%3 free

        // issue next stage BEFORE compute so it overlaps the whole iteration
        if (kt + 2 < nk) stage((kt + 2) % 3, (kt + 2) * 32);
        else CPC();                        // uniform group accounting

        u32 sbb = sb32 + (kt % 3) * 32768;
#pragma unroll
        for (int ks = 0; ks < 2; ks++) {
            u32 bhf[4][2], blf[4][2];
#pragma unroll
            for (int ni = 0; ni < 4; ni++) {
                int cb = (ks * 2 + hb) ^ rsb;
                u32 addr = sbb + 16384 + (rowb + ni * 8) * 64 + cb * 16;
                ldsm_x2(bhf[ni][0], bhf[ni][1], addr);
                ldsm_x2(blf[ni][0], blf[ni][1], addr + 8192);
            }
#pragma unroll
            for (int mi = 0; mi < 4; mi++) {
                int ca = (ks * 2 + ha) ^ rsa;
                u32 addr = sbb + (rowa + mi * 16) * 64 + ca * 16;
                u32 ah[4], al[4];
                ldsm_x4(ah[0], ah[1], ah[2], ah[3], addr);
                ldsm_x4(al[0], al[1], al[2], al[3], addr + 8192);
#pragma unroll
                for (int ni = 0; ni < 4; ni++) {
                    mma_bf16(acc[mi][ni], ah, bhf[ni]);
                    mma_bf16(acc[mi][ni], ah, blf[ni]);
                    mma_bf16(acc[mi][ni], al, bhf[ni]);
                }
            }
        }
    }

#pragma unroll
    for (int mi = 0; mi < 4; mi++) {
        int mbase = m0 + warp_m * 64 + mi * 16;
#pragma unroll
        for (int ni = 0; ni < 4; ni++) {
            int col = n0 + warp_n * 32 + ni * 8 + tg * 2;
            float b0 = 0.f, b1 = 0.f;
            if (bias) { b0 = bias[col]; b1 = bias[col + 1]; }
            float v0 = acc[mi][ni][0] + b0, v1 = acc[mi][ni][1] + b1;
            float v2 = acc[mi][ni][2] + b0, v3 = acc[mi][ni][3] + b1;
            if (RELU) {
                v0 = fmaxf(v0, 0.f); v1 = fmaxf(v1, 0.f);
                v2 = fmaxf(v2, 0.f); v3 = fmaxf(v3, 0.f);
            }
            if (OUTSPLIT) {
                u32 h01, l01;
                long o0 = (long)(mbase + gid) * ldc + col;
                long o1 = (long)(mbase + gid + 8) * ldc + col;
                cvt_split(v0, v1, h01, l01);
                *(u32*)(Ch + o0) = h01;
                *(u32*)(Cl + o0) = l01;
                cvt_split(v2, v3, h01, l01);
                *(u32*)(Ch + o1) = h01;
                *(u32*)(Cl + o1) = l01;
            } else {
                *(float2*)&C[(long)(mbase + gid) * ldc + col] = make_float2(v0, v1);
                *(float2*)&C[(long)(mbase + gid + 8) * ldc + col] = make_float2(v2, v3);
            }
        }
    }
}

// ---------------------------------------------------------------------------
// Km GEMM (R11-proven): A pre-split, B fp32 (cvt in staging), batched via z.
#define BGEMM_SMEM 32768

__global__ __launch_bounds__(256) void gemm_km(
    const __nv_bfloat16* __restrict__ Ah, const __nv_bfloat16* __restrict__ Al,
    const float* __restrict__ Bf, float* __restrict__ C,
    int K, int lda, int ldb, int ldc, long batchA, long batchB, long batchC)
{
    extern __shared__ char smx[];
    u32 sb32 = (u32)__cvta_generic_to_shared(smx);

    long bz = blockIdx.z;
    Ah += bz * batchA; Al += bz * batchA;
    Bf += bz * batchB; C += bz * batchC;

    int m0 = blockIdx.x * 128, n0 = blockIdx.y * 128;
    int tid = threadIdx.x;
    int wid = tid >> 5, lane = tid & 31;
    int warp_m = wid & 1, warp_n = wid >> 1;
    int gid = lane >> 2, tg = lane & 3;

    int bm[4], bq[4], an2[2], ac2[2];
#pragma unroll
    for (int j = 0; j < 4; j++) {
        int idx = tid + j * 256;
        bm[j] = idx >> 3; bq[j] = idx & 7;
    }
#pragma unroll
    for (int j = 0; j < 2; j++) {
        int idx = tid + j * 256;
        an2[j] = idx >> 2; ac2[j] = idx & 3;
    }

    int rowa = warp_m * 64 + (lane & 15);
    int rsa = (rowa >> 1) & 3;
    int ha = lane >> 4;
    int rowb = warp_n * 32 + (lane & 7);
    int rsb = (rowb >> 1) & 3;
    int hb = (lane >> 3) & 1;

    float acc[4][4][4];
#pragma unroll
    for (int i = 0; i < 4; i++)
#pragma unroll
        for (int j = 0; j < 4; j++)
#pragma unroll
            for (int v = 0; v < 4; v++) acc[i][j][v] = 0.f;

    auto store_a_pre = [&](int m, int c, uint4 h, uint4 l) {
        char* p = smx + m * 64 + ((c ^ ((m >> 1) & 3)) * 16);
        *(uint4*)p = h;
        *(uint4*)(p + 8192) = l;
    };
    auto store_b_f32 = [&](int m, int q, float4 v) {
        u32 h01, l01, h23, l23;
        cvt_split(v.x, v.y, h01, l01);
        cvt_split(v.z, v.w, h23, l23);
        char* p = smx + 16384 + m * 64 + (((q >> 1) ^ ((m >> 1) & 3)) * 16) + (q & 1) * 8;
        *(uint2*)p = make_uint2(h01, h23);
        *(uint2*)(p + 8192) = make_uint2(l01, l23);
    };

#pragma unroll
    for (int j = 0; j < 2; j++) {
        long off = (long)(m0 + an2[j]) * lda + ac2[j] * 8;
        store_a_pre(an2[j], ac2[j], *(const uint4*)(Ah + off), *(const uint4*)(Al + off));
    }
#pragma unroll
    for (int j = 0; j < 4; j++) {
        float4 v = *(const float4*)&Bf[(long)(n0 + bm[j]) * ldb + bq[j] * 4];
        store_b_f32(bm[j], bq[j], v);
    }
    __syncthreads();

    int nk = K / 32;
    for (int kt = 0; kt < nk; kt++) {
        float4 rbf[4];
        uint4 rah[2], ral[2];
        bool nxt = (kt + 1 < nk);
        if (nxt) {
            int k0 = (kt + 1) * 32;
#pragma unroll
            for (int j = 0; j < 2; j++) {
                long off = (long)(m0 + an2[j]) * lda + k0 + ac2[j] * 8;
                rah[j] = *(const uint4*)(Ah + off);
                ral[j] = *(const uint4*)(Al + off);
            }
#pragma unroll
            for (int j = 0; j < 4; j++)
                rbf[j] = *(const float4*)&Bf[(long)(n0 + bm[j]) * ldb + k0 + bq[j] * 4];
        }

#pragma unroll
        for (int ks = 0; ks < 2; ks++) {
            u32 bhf[4][2], blf[4][2];
#pragma unroll
            for (int ni = 0; ni < 4; ni++) {
                int cb = (ks * 2 + hb) ^ rsb;
                u32 addr = sb32 + 16384 + (rowb + ni * 8) * 64 + cb * 16;
                ldsm_x2(bhf[ni][0], bhf[ni][1], addr);
                ldsm_x2(blf[ni][0], blf[ni][1], addr + 8192);
            }
#pragma unroll
            for (int mi = 0; mi < 4; mi++) {
                int ca = (ks * 2 + ha) ^ rsa;
                u32 addr = sb32 + (rowa + mi * 16) * 64 + ca * 16;
                u32 ah[4], al[4];
                ldsm_x4(ah[0], ah[1], ah[2], ah[3], addr);
                ldsm_x4(al[0], al[1], al[2], al[3], addr + 8192);
#pragma unroll
                for (int ni = 0; ni < 4; ni++) {
                    mma_bf16(acc[mi][ni], ah, bhf[ni]);
                    mma_bf16(acc[mi][ni], ah, blf[ni]);
                    mma_bf16(acc[mi][ni], al, bhf[ni]);
                }
            }
        }
        __syncthreads();
        if (nxt) {
#pragma unroll
            for (int j = 0; j < 2; j++) store_a_pre(an2[j], ac2[j], rah[j], ral[j]);
#pragma unroll
            for (int j = 0; j < 4; j++) store_b_f32(bm[j], bq[j], rbf[j]);
        }
        __syncthreads();
    }

#pragma unroll
    for (int mi = 0; mi < 4; mi++) {
        int mbase = m0 + warp_m * 64 + mi * 16;
#pragma unroll
        for (int ni = 0; ni < 4; ni++) {
            int col = n0 + warp_n * 32 + ni * 8 + tg * 2;
            *(float2*)&C[(long)(mbase + gid) * ldc + col] =
                make_float2(acc[mi][ni][0], acc[mi][ni][1]);
            *(float2*)&C[(long)(mbase + gid + 8) * ldc + col] =
                make_float2(acc[mi][ni][2], acc[mi][ni][3]);
        }
    }
}

// ---------------------------------------------------------------------------
// persistent GRU (R11): tensor-core gh, 384 threads, one-hop barrier.
#define GRU_SMEM2 43008
#define GRU_THREADS 384

__device__ __forceinline__ float sigmf(float x) { return 1.f / (1.f + __expf(-x)); }
__device__ __forceinline__ float tanhfast(float x) { return 2.f / (1.f + __expf(-2.f * x)) - 1.f; }

__global__ __launch_bounds__(GRU_THREADS) void gru_tc(
    const float* __restrict__ GI, const float* __restrict__ h0,
    const float* __restrict__ W_hh, const float* __restrict__ b_hh,
    const __nv_bfloat16* __restrict__ HB0H, const __nv_bfloat16* __restrict__ HB0L,
    __nv_bfloat16* __restrict__ HBH, __nv_bfloat16* __restrict__ HBL)
{
    extern __shared__ char sm8[];
    u32 sb = (u32)__cvta_generic_to_shared(sm8);
    float* ghs = (float*)(sm8 + 32768);
    float* hown = (float*)(sm8 + 40960);

    int tid = threadIdx.x;
    int wid = tid >> 5, lane = tid & 31;
    int jt = blockIdx.x & 15, nt = blockIdx.x >> 4;
    int j0 = jt * 16, n0 = nt * 32;
    int colg = wid % 6, mt = wid / 6;

    unsigned* arr = &g_bar2[nt * 32];

    u32 bhf[16][2], blf[16][2];
    {
        for (int e = tid; e < 3072; e += GRU_THREADS) {
            int r = e >> 6, q = e & 63;
            float4 v = *(const float4*)&W_hh[(long)((r >> 4) * 256 + j0 + (r & 15)) * 256 + q * 4];
            u32 h01, l01, h23, l23;
            cvt_split(v.x, v.y, h01, l01);
            cvt_split(v.z, v.w, h23, l23);
            *(uint2*)(sm8 + r * 512 + (((q >> 1) ^ (r & 7)) * 16) + (q & 1) * 8) =
                make_uint2(h01, h23);
        }
        __syncthreads();
        {
            int rb = colg * 8 + (lane & 7);
            int hb2 = (lane >> 3) & 1;
#pragma unroll
            for (int s = 0; s < 16; s++) {
                u32 addr = sb + rb * 512 + (((s * 2 + hb2) ^ (rb & 7)) * 16);
                ldsm_x2(bhf[s][0], bhf[s][1], addr);
            }
        }
        __syncthreads();
        for (int e = tid; e < 3072; e += GRU_THREADS) {
            int r = e >> 6, q = e & 63;
            float4 v = *(const float4*)&W_hh[(long)((r >> 4) * 256 + j0 + (r & 15)) * 256 + q * 4];
            u32 h01, l01, h23, l23;
            cvt_split(v.x, v.y, h01, l01);
            cvt_split(v.z, v.w, h23, l23);
            *(uint2*)(sm8 + r * 512 + (((q >> 1) ^ (r & 7)) * 16) + (q & 1) * 8) =
                make_uint2(l01, l23);
        }
        __syncthreads();
        {
            int rb = colg * 8 + (lane & 7);
            int hb2 = (lane >> 3) & 1;
#pragma unroll
            for (int s = 0; s < 16; s++) {
                u32 addr = sb + rb * 512 + (((s * 2 + hb2) ^ (rb & 7)) * 16);
                ldsm_x2(blf[s][0], blf[s][1], addr);
            }
        }
        __syncthreads();
    }

    int jj = tid & 15, nb0 = (tid & 255) >> 4;
    float bhr = b_hh[j0 + jj], bhz = b_hh[256 + j0 + jj], bhn = b_hh[512 + j0 + jj];
    if (tid < 256) {
#pragma unroll
        for (int i = 0; i < 2; i++) {
            int n = nb0 + 16 * i;
            hown[n * 16 + jj] = h0[(long)(n0 + n) * H_ + j0 + jj];
        }
    }
    float gr[2], gz[2], gn[2];
    if (tid < 256) {
#pragma unroll
        for (int i = 0; i < 2; i++) {
            long base = ((long)(n0 + nb0 + 16 * i)) * 768 + j0 + jj;
            gr[i] = GI[base]; gz[i] = GI[base + 256]; gn[i] = GI[base + 512];
        }
    }
    __syncthreads();

    for (int t = 0; t < T_; t++) {
        const __nv_bfloat16* srcH = t ? HBH + (long)(t - 1) * N_ * H_ : HB0H;
        const __nv_bfloat16* srcL = t ? HBL + (long)(t - 1) * N_ * H_ : HB0L;
        for (int e = tid; e < 1024; e += GRU_THREADS) {
            int r = e >> 5, c = e & 31;
            u32 soff = r * 512 + ((c ^ (r & 7)) * 16);
            *(uint4*)(sm8 + soff) = *(const uint4*)(srcH + (long)(n0 + r) * 256 + c * 8);
            *(uint4*)(sm8 + 16384 + soff) = *(const uint4*)(srcL + (long)(n0 + r) * 256 + c * 8);
        }
        __syncthreads();

        {
            float acc[4];
#pragma unroll
            for (int v = 0; v < 4; v++) acc[v] = 0.f;
            int rr = mt * 16 + (lane & 15);
            int ha2 = lane >> 4;
#pragma unroll
            for (int s = 0; s < 16; s++) {
                u32 addr = sb + rr * 512 + (((s * 2 + ha2) ^ (rr & 7)) * 16);
                u32 ah[4], al[4];
                ldsm_x4(ah[0], ah[1], ah[2], ah[3], addr);
                ldsm_x4(al[0], al[1], al[2], al[3], addr + 16384);
                mma_bf16(acc, ah, bhf[s]);
                mma_bf16(acc, ah, blf[s]);
                mma_bf16(acc, al, bhf[s]);
            }
            int gid = lane >> 2, tg = lane & 3;
            *(float2*)&ghs[(mt * 16 + gid) * 64 + colg * 8 + tg * 2] =
                make_float2(acc[0], acc[1]);
            *(float2*)&ghs[(mt * 16 + gid + 8) * 64 + colg * 8 + tg * 2] =
                make_float2(acc[2], acc[3]);
        }
        __syncthreads();

        if (tid < 256) {
            __nv_bfloat16* bhd = HBH + (long)t * N_ * H_;
            __nv_bfloat16* bld = HBL + (long)t * N_ * H_;
#pragma unroll
            for (int i = 0; i < 2; i++) {
                int n = nb0 + 16 * i;
                float ghr = ghs[n * 64 + jj];
                float ghz = ghs[n * 64 + 16 + jj];
                float ghn = ghs[n * 64 + 32 + jj];
                float rg = sigmf(gr[i] + ghr + bhr);
                float z  = sigmf(gz[i] + ghz + bhz);
                float nv = tanhfast(gn[i] + rg * (ghn + bhn));
                float hp = hown[n * 16 + jj];
                float hn = (1.f - z) * nv + z * hp;
                hown[n * 16 + jj] = hn;
                long gofs = (long)(n0 + n) * H_ + j0 + jj;
                __nv_bfloat16 hh = __float2bfloat16(hn);
                bhd[gofs] = hh;
                bld[gofs] = __float2bfloat16(hn - __bfloat162float(hh));
            }
        }

        if (t < T_ - 1) {
            __syncthreads();
            if (tid == 0) {
                asm volatile("red.release.gpu.global.add.u32 [%0], %1;"
                             :: "l"(arr), "r"(1u) : "memory");
            }
            if (tid < 256) {
#pragma unroll
                for (int i = 0; i < 2; i++) {
                    long base = ((long)(t + 1) * N_ + n0 + nb0 + 16 * i) * 768 + j0 + jj;
                    gr[i] = GI[base]; gz[i] = GI[base + 256]; gn[i] = GI[base + 512];
                }
            }
            if (tid == 0) {
                unsigned target = (unsigned)(t + 1) * 16u;
                unsigned e;
                do {
                    asm volatile("ld.acquire.gpu.global.u32 %0, [%1];"
                                 : "=r"(e) : "l"(arr) : "memory");
                } while (e < target);
            }
            __syncthreads();
        }
    }
}

// ---------------------------------------------------------------------------
__global__ __launch_bounds__(256) void epilogue_kernel(
    const float* __restrict__ WB, const float* __restrict__ CC,
    const int* __restrict__ actions, const float* __restrict__ Wc,
    const float* __restrict__ bc,
    const __nv_bfloat16* __restrict__ HBH, const __nv_bfloat16* __restrict__ HBL,
    float* __restrict__ out)
{
    int wid = threadIdx.x >> 5, lane = threadIdx.x & 31;
    long idx = (long)blockIdx.x * 8 + wid;
    int t = (int)(idx / N_), n = (int)(idx % N_);
    float cc = CC[idx];
    long base = idx * OUTW_;

    const __nv_bfloat162* hv = (const __nv_bfloat162*)(HBH + idx * 256 + lane * 8);
    const __nv_bfloat162* lv = (const __nv_bfloat162*)(HBL + idx * 256 + lane * 8);
    float h[8];
#pragma unroll
    for (int i = 0; i < 4; i++) {
        float2 fh = __bfloat1622float2(hv[i]);
        float2 fl = __bfloat1622float2(lv[i]);
        h[2 * i] = fh.x + fl.x;
        h[2 * i + 1] = fh.y + fl.y;
    }
    float2* hdst = (float2*)(out + base + 2 + lane * 8);
#pragma unroll
    for (int i = 0; i < 4; i++) hdst[i] = make_float2(h[2 * i], h[2 * i + 1]);

    const float4* wc = (const float4*)Wc;
    float4 c0 = wc[lane * 2], c1 = wc[lane * 2 + 1];
    float d = h[0] * c0.x + h[1] * c0.y + h[2] * c0.z + h[3] * c0.w
            + h[4] * c1.x + h[5] * c1.y + h[6] * c1.z + h[7] * c1.w;
#pragma unroll
    for (int o = 16; o; o >>= 1) d += __shfl_xor_sync(~0u, d, o);

    const float4* wrow = (const float4*)(WB + ((long)n * T_ + t) * L_);
    float4 w0 = wrow[lane * 2], w1 = wrow[lane * 2 + 1];
    float wv[8] = {w0.x * cc, w0.y * cc, w0.z * cc, w0.w * cc,
                   w1.x * cc, w1.y * cc, w1.z * cc, w1.w * cc};
    float mx = wv[0];
#pragma unroll
    for (int i = 1; i < 8; i++) mx = fmaxf(mx, wv[i]);
#pragma unroll
    for (int o = 16; o; o >>= 1) mx = fmaxf(mx, __shfl_xor_sync(~0u, mx, o));
    float e[8], s = 0.f;
#pragma unroll
    for (int i = 0; i < 8; i++) { e[i] = expf(wv[i] - mx); s += e[i]; }
#pragma unroll
    for (int o = 16; o; o >>= 1) s += __shfl_xor_sync(~0u, s, o);
    float inv = 1.f / s;

    int a = actions[idx];
    float2* pdst = (float2*)(out + base + 258 + lane * 8);
    float2* odst = (float2*)(out + base + 514 + lane * 8);
#pragma unroll
    for (int i = 0; i < 4; i++) {
        pdst[i] = make_float2(e[2 * i] * inv, e[2 * i + 1] * inv);
        int l0 = lane * 8 + 2 * i;
        odst[i] = make_float2(l0 == a ? 1.f : 0.f, l0 + 1 == a ? 1.f : 0.f);
    }
    if (lane == 0) {
        out[base + 0] = (float)a;
        out[base + 1] = d + bc[0];
    }
}

// ---------------------------------------------------------------------------
extern "C" void kernel_launch(void* const* d_in, const int* in_sizes, int n_in,
                              void* d_out, int out_size)
{
    const float* cond = (const float*)d_in[0];
    const float* M    = (const float*)d_in[1];
    const float* Km   = (const float*)d_in[2];
    const float* Cm   = (const float*)d_in[3];
    const float* h0   = (const float*)d_in[4];
    const float* p0   = (const float*)d_in[5];
    const float* W0   = (const float*)d_in[6];
    const float* b0   = (const float*)d_in[7];
    const float* W1   = (const float*)d_in[8];
    const float* b1   = (const float*)d_in[9];
    const float* W2   = (const float*)d_in[10];
    const float* b2   = (const float*)d_in[11];
    const float* W_ih = (const float*)d_in[12];
    const float* W_hh = (const float*)d_in[13];
    const float* b_ih = (const float*)d_in[14];
    const float* b_hh = (const float*)d_in[15];
    const float* Wa   = (const float*)d_in[16];
    const float* ba   = (const float*)d_in[17];
    const float* Wc   = (const float*)d_in[18];
    const float* bc   = (const float*)d_in[19];
    const int* actions = (const int*)d_in[20];
    float* out = (float*)d_out;

    float* base = nullptr;
    cudaGetSymbolAddress((void**)&base, g_scratch);
    __nv_bfloat16* XINH = (__nv_bfloat16*)(base + XINH_OFF);
    __nv_bfloat16* XINL = (__nv_bfloat16*)(base + XINL_OFF);
    __nv_bfloat16* XAH = (__nv_bfloat16*)(base + XAH_OFF);
    __nv_bfloat16* XAL = (__nv_bfloat16*)(base + XAL_OFF);
    __nv_bfloat16* XBH = (__nv_bfloat16*)(base + XBH_OFF);
    __nv_bfloat16* XBL = (__nv_bfloat16*)(base + XBL_OFF);
    float* GI = base + GI_OFF;
    __nv_bfloat16* KBH = (__nv_bfloat16*)(base + KBH_OFF);
    __nv_bfloat16* KBL = (__nv_bfloat16*)(base + KBL_OFF);
    float* WB = base + WB_OFF;
    float* CC = base + CC_OFF;
    __nv_bfloat16* WT = (__nv_bfloat16*)(base + WT_OFF);
    __nv_bfloat16* HBH = (__nv_bfloat16*)(base + HBH_OFF);
    __nv_bfloat16* HBL = (__nv_bfloat16*)(base + HBL_OFF);
    __nv_bfloat16* HB0H = (__nv_bfloat16*)(base + HB0H_OFF);
    __nv_bfloat16* HB0L = (__nv_bfloat16*)(base + HB0L_OFF);

    void* bar_addr = nullptr;
    cudaGetSymbolAddress(&bar_addr, g_bar2);

    cudaFuncSetAttribute(gru_tc,
                         cudaFuncAttributeMaxDynamicSharedMemorySize, GRU_SMEM2);
    cudaFuncSetAttribute(gemm_v4<true, true>,
                         cudaFuncAttributeMaxDynamicSharedMemorySize, GEMM3_SMEM);
    cudaFuncSetAttribute(gemm_v4<false, false>,
                         cudaFuncAttributeMaxDynamicSharedMemorySize, GEMM3_SMEM);
    cudaFuncSetAttribute(gemm_v4<false, true>,
                         cudaFuncAttributeMaxDynamicSharedMemorySize, GEMM3_SMEM);

    // phase 0: weight/h0 conversion
    convert_wall<<<2112, 256>>>(W0, W1, W2, W_ih, Wa, h0, WT, HB0H, HB0L);

    // phase A (activations carried as bf16 hi/lo)
    t0_kernel<<<N_, 256>>>(p0, M, Cm, XINH, XINL, CC);
    gather_kernel<<<ROWS_ / 8, 256>>>(cond, M, Cm, actions, XINH, XINL, CC);
    gemm_v4<true, true><<<dim3(ROWS_ / 128, 2), 256, GEMM3_SMEM>>>(
        XINH, XINL, WT + W0H, WT + W0L, b0, nullptr, XAH, XAL, 320, 320, 256);
    gemm_v4<true, true><<<dim3(ROWS_ / 128, 2), 256, GEMM3_SMEM>>>(
        XAH, XAL, WT + W1H, WT + W1L, b1, nullptr, XBH, XBL, 256, 256, 256);
    gemm_v4<true, true><<<dim3(ROWS_ / 128, 2), 256, GEMM3_SMEM>>>(
        XBH, XBL, WT + W2H, WT + W2L, b2, nullptr, XAH, XAL, 256, 256, 256);
    gemm_v4<false, false><<<dim3(ROWS_ / 128, 6), 256, GEMM3_SMEM>>>(
        XAH, XAL, WT + WIHH, WT + WIHL, b_ih, GI, nullptr, nullptr, 256, 256, 768);

    // phase B: persistent tensor-core GRU
    cudaMemsetAsync(bar_addr, 0, 8 * 32 * sizeof(unsigned));
    gru_tc<<<128, GRU_THREADS, GRU_SMEM2>>>(GI, h0, W_hh, b_hh, HB0H, HB0L, HBH, HBL);

    // phase C
    gemm_v4<false, true><<<dim3(ROWS_ / 128, 2), 256, GEMM3_SMEM>>>(
        HBH, HBL, WT + WAH, WT + WAL, ba, nullptr, KBH, KBL, 256, 256, 256);
    gemm_km<<<dim3(1, 2, 256), 256, BGEMM_SMEM>>>(
        KBH, KBL, Km, WB, 256, 256, 256, 256,
        (long)T_ * 256, (long)L_ * H_, (long)T_ * L_);
    epilogue_kernel<<<ROWS_ / 8, 256>>>(WB, CC, actions, Wc, bc, HBH, HBL, out);
}